// round 6
// baseline (speedup 1.0000x reference)
#include <cuda_runtime.h>
#include <cstdint>

#define Bq   4
#define Sq   2048
#define Dq   1024
#define Hq   16
#define HDq  64
#define Mq   (Bq*Sq)

__device__ float g_xn[(size_t)Mq*Dq];
__device__ float g_q[(size_t)Mq*Dq];
__device__ float g_k[(size_t)Mq*Dq];
__device__ float g_v[(size_t)Mq*Dq];
__device__ float g_ctx[(size_t)Mq*Dq];
__device__ float g_wt[4][(size_t)Dq*Dq];   // tf32-rounded weights

// ---------------------------------------------------------------------------
// helpers
// ---------------------------------------------------------------------------
__device__ __forceinline__ uint32_t f2tf(float f) {
    uint32_t u;
    asm("cvt.rna.tf32.f32 %0, %1;" : "=r"(u) : "f"(f));
    return u;
}
__device__ __forceinline__ float f2tff(float f) {
    return __uint_as_float(f2tf(f));
}

__device__ __forceinline__ void mma8(float* c, const uint32_t* a, const uint32_t* b) {
    asm volatile(
        "mma.sync.aligned.m16n8k8.row.col.f32.tf32.tf32.f32 "
        "{%0,%1,%2,%3},{%4,%5,%6,%7},{%8,%9},{%0,%1,%2,%3};"
        : "+f"(c[0]), "+f"(c[1]), "+f"(c[2]), "+f"(c[3])
        : "r"(a[0]), "r"(a[1]), "r"(a[2]), "r"(a[3]), "r"(b[0]), "r"(b[1]));
}

__device__ __forceinline__ void cp16(uint32_t dst, const void* src) {
    asm volatile("cp.async.cg.shared.global [%0], [%1], 16;"
                 :: "r"(dst), "l"(src));
}
__device__ __forceinline__ void cp_commit() { asm volatile("cp.async.commit_group;"); }
__device__ __forceinline__ void cp_wait1()  { asm volatile("cp.async.wait_group 1;"); }
__device__ __forceinline__ void cp_wait0()  { asm volatile("cp.async.wait_group 0;"); }

__device__ __forceinline__ int rp_bucket(int rp) {
    if (rp < 0) rp = 0;
    if (rp < 16) return rp;
    int bk = 16 + (int)(__logf((float)rp * 0.0625f) * 7.6944086f);
    return bk > 31 ? 31 : bk;
}

// ---------------------------------------------------------------------------
// Kernel 0: round weights to tf32 (values exactly representable in tf32)
// ---------------------------------------------------------------------------
__global__ __launch_bounds__(256) void cvtw_kernel(
    const float* __restrict__ w0, const float* __restrict__ w1,
    const float* __restrict__ w2, const float* __restrict__ w3)
{
    const float* w = (blockIdx.y == 0) ? w0 : (blockIdx.y == 1) ? w1
                   : (blockIdx.y == 2) ? w2 : w3;
    float* o = g_wt[blockIdx.y];
    size_t i = ((size_t)blockIdx.x * 256 + threadIdx.x) * 4;
    float4 v = *(const float4*)&w[i];
    float4 r = { f2tff(v.x), f2tff(v.y), f2tff(v.z), f2tff(v.w) };
    *(float4*)&o[i] = r;
}

// ---------------------------------------------------------------------------
// Kernel 1: RMS norm, tf32-rounded output
// ---------------------------------------------------------------------------
__global__ __launch_bounds__(256) void norm_kernel(
    const float* __restrict__ x, const float* __restrict__ lnw,
    float* __restrict__ xn)
{
    int row = blockIdx.x;
    const float4* xr = (const float4*)(x + (size_t)row * Dq);
    float4 v = xr[threadIdx.x];
    float s = v.x * v.x + v.y * v.y + v.z * v.z + v.w * v.w;
    __shared__ float red[8];
    #pragma unroll
    for (int o = 16; o > 0; o >>= 1) s += __shfl_xor_sync(0xffffffffu, s, o);
    if ((threadIdx.x & 31) == 0) red[threadIdx.x >> 5] = s;
    __syncthreads();
    float t = 0.f;
    #pragma unroll
    for (int i = 0; i < 8; i++) t += red[i];
    float rs = rsqrtf(t * (1.0f / (float)Dq) + 1e-6f);
    float4 lw = ((const float4*)lnw)[threadIdx.x];
    float4 o4 = { f2tff(v.x * rs * lw.x), f2tff(v.y * rs * lw.y),
                  f2tff(v.z * rs * lw.z), f2tff(v.w * rs * lw.w) };
    ((float4*)(xn + (size_t)row * Dq))[threadIdx.x] = o4;
}

// ---------------------------------------------------------------------------
// Kernel 2: tf32 GEMM (inputs pre-rounded -> no cvt in loop), 3-stage cp.async.
// BM=BN=128, BK=32, 256 thr, 2 CTAs/SM. ROUND: round output to tf32.
// RES: C = A@W + res (fp32 out).
// ---------------------------------------------------------------------------
#define GA_ST    36
#define GB_ST    136
#define GA_WORDS (128 * GA_ST)
#define GB_WORDS (32 * GB_ST)
#define GB_BASE  (3 * GA_WORDS)
#define GEMM_SMEM_BYTES ((3 * GA_WORDS + 3 * GB_WORDS) * 4)  // 107520
#define NKT (Dq / 32)

template<bool RES, bool ROUND>
__global__ __launch_bounds__(256, 2) void gemm_tc2(
    const float* __restrict__ A, const float* __restrict__ W,
    float* __restrict__ C, const float* __restrict__ res)
{
    extern __shared__ uint32_t smu[];
    uint32_t smb = (uint32_t)__cvta_generic_to_shared(smu);

    const int col0 = blockIdx.x << 7;
    const int row0 = blockIdx.y << 7;

    const int tid = threadIdx.x;
    const int wid = tid >> 5, lane = tid & 31;
    const int lq = lane >> 2, lr = lane & 3;
    const int warpM = (wid & 1) * 64;
    const int warpN = (wid >> 1) * 32;

    const int ar = tid >> 3, ac = (tid & 7) << 2;
    const int br = tid >> 5, bc = (tid & 31) << 2;

    auto copyTile = [&](int t, int st) {
        int k0 = t * 32;
        #pragma unroll
        for (int u = 0; u < 4; u++) {
            int r = ar + u * 32;
            cp16(smb + (st * GA_WORDS + r * GA_ST + ac) * 4,
                 A + (size_t)(row0 + r) * Dq + k0 + ac);
        }
        #pragma unroll
        for (int u = 0; u < 4; u++) {
            int r = br + u * 8;
            cp16(smb + (GB_BASE + st * GB_WORDS + r * GB_ST + bc) * 4,
                 W + (size_t)(k0 + r) * Dq + col0 + bc);
        }
        cp_commit();
    };

    float acc[4][4][4] = {};

    copyTile(0, 0);
    copyTile(1, 1);

    #pragma unroll 1
    for (int t = 0; t < NKT; t++) {
        int stage = t % 3;
        if (t + 1 < NKT) cp_wait1(); else cp_wait0();
        __syncthreads();
        if (t + 2 < NKT) copyTile(t + 2, (t + 2) % 3);

        const uint32_t* As = smu + stage * GA_WORDS;
        const uint32_t* Bs = smu + GB_BASE + stage * GB_WORDS;

        #pragma unroll
        for (int ks = 0; ks < 4; ks++) {
            uint32_t a[4][4], b[4][2];
            #pragma unroll
            for (int mt = 0; mt < 4; mt++) {
                int rb = warpM + mt * 16 + lq;
                int cb = ks * 8 + lr;
                a[mt][0] = As[rb * GA_ST + cb];
                a[mt][1] = As[(rb + 8) * GA_ST + cb];
                a[mt][2] = As[rb * GA_ST + cb + 4];
                a[mt][3] = As[(rb + 8) * GA_ST + cb + 4];
            }
            #pragma unroll
            for (int nt = 0; nt < 4; nt++) {
                int nb = warpN + nt * 8 + lq;
                b[nt][0] = Bs[(ks * 8 + lr) * GB_ST + nb];
                b[nt][1] = Bs[(ks * 8 + lr + 4) * GB_ST + nb];
            }
            #pragma unroll
            for (int mt = 0; mt < 4; mt++)
                #pragma unroll
                for (int nt = 0; nt < 4; nt++)
                    mma8(acc[mt][nt], a[mt], b[nt]);
        }
    }

    #pragma unroll
    for (int mt = 0; mt < 4; mt++)
        #pragma unroll
        for (int nt = 0; nt < 4; nt++) {
            int row = row0 + warpM + mt * 16 + lq;
            int col = col0 + warpN + nt * 8 + lr * 2;
            float2 v0 = { acc[mt][nt][0], acc[mt][nt][1] };
            float2 v1 = { acc[mt][nt][2], acc[mt][nt][3] };
            if (ROUND) {
                v0.x = f2tff(v0.x); v0.y = f2tff(v0.y);
                v1.x = f2tff(v1.x); v1.y = f2tff(v1.y);
            }
            if (RES) {
                float2 r0 = *(const float2*)&res[(size_t)row * Dq + col];
                float2 r1 = *(const float2*)&res[(size_t)(row + 8) * Dq + col];
                v0.x += r0.x; v0.y += r0.y; v1.x += r1.x; v1.y += r1.y;
            }
            *(float2*)&C[(size_t)row * Dq + col] = v0;
            *(float2*)&C[(size_t)(row + 8) * Dq + col] = v1;
        }
}

// ---------------------------------------------------------------------------
// Kernel 3: flash attention, tf32, cp.async 2-stage K/V, hoisted Q fragments.
// Inputs (g_q/g_k/g_v) pre-rounded to tf32 -> no cvt at tile load.
// smem words: Q 128x68, K 2x64x68, V 2x64x72, P 128x68 = 35328 (141312 B).
// ---------------------------------------------------------------------------
#define QS(r, c)      sm[(r) * 68 + (c)]
#define KS(st, r, c)  sm[8704 + (st) * 4352 + (r) * 68 + (c)]
#define VS(st, r, c)  sm[17408 + (st) * 4608 + (r) * 72 + (c)]
#define PS(r, c)      sm[26624 + (r) * 68 + (c)]
#define FLASH_SMEM_WORDS 35328
#define NTILES (Sq / 64)

__global__ __launch_bounds__(256) void flash_tc(const float* __restrict__ rel_emb)
{
    extern __shared__ uint32_t sm[];
    __shared__ float bias_tab[32];

    const int tid = threadIdx.x;
    const int wid = tid >> 5, lane = tid & 31;
    const int lq = lane >> 2, lr = lane & 3;
    const int warpRow = wid * 16;

    const int q0 = blockIdx.x << 7;
    const int bh = blockIdx.y;
    const int b = bh >> 4, h = bh & 15;
    const size_t base = ((size_t)b * Sq) * Dq + (size_t)h * HDq;

    uint32_t smb = (uint32_t)__cvta_generic_to_shared(sm);

    if (tid < 32) bias_tab[tid] = rel_emb[tid * Hq + h];

    // load Q tile (raw tf32 bits)
    #pragma unroll
    for (int u = 0; u < 8; u++) {
        int lin = tid + u * 256;
        int r = lin >> 4, c4 = (lin & 15) << 2;
        *(uint4*)&QS(r, c4) =
            *(const uint4*)&g_q[base + (size_t)(q0 + r) * Dq + c4];
    }

    auto copyKV = [&](int t, int st) {
        int k0 = t * 64;
        #pragma unroll
        for (int u = 0; u < 4; u++) {
            int lin = tid + u * 256;
            int r = lin >> 4, c4 = (lin & 15) << 2;
            cp16(smb + (8704 + st * 4352 + r * 68 + c4) * 4,
                 &g_k[base + (size_t)(k0 + r) * Dq + c4]);
            cp16(smb + (17408 + st * 4608 + r * 72 + c4) * 4,
                 &g_v[base + (size_t)(k0 + r) * Dq + c4]);
        }
        cp_commit();
    };

    copyKV(0, 0);
    copyKV(1, 1);

    __syncthreads();   // Q visible
    // hoist Q fragments (loop-invariant)
    uint32_t aq[8][4];
    #pragma unroll
    for (int ks = 0; ks < 8; ks++) {
        int rb = warpRow + lq, cb = ks * 8 + lr;
        aq[ks][0] = QS(rb, cb);     aq[ks][1] = QS(rb + 8, cb);
        aq[ks][2] = QS(rb, cb + 4); aq[ks][3] = QS(rb + 8, cb + 4);
    }

    const float NEG_INF = __int_as_float(0xff800000u);
    float mA = NEG_INF, mB = NEG_INF, lA = 0.f, lB = 0.f;
    float o[8][4] = {};
    const int rowA = q0 + warpRow + lq;

    #pragma unroll 1
    for (int t = 0; t < NTILES; t++) {
        int st = t & 1;
        if (t + 1 < NTILES) cp_wait1(); else cp_wait0();
        __syncthreads();

        int k0 = t * 64;

        // S = Q K^T
        float s[8][4] = {};
        #pragma unroll
        for (int nt = 0; nt < 8; nt++) {
            #pragma unroll
            for (int ks = 0; ks < 8; ks++) {
                uint32_t bb[2];
                bb[0] = KS(st, nt * 8 + lq, ks * 8 + lr);
                bb[1] = KS(st, nt * 8 + lq, ks * 8 + lr + 4);
                mma8(s[nt], aq[ks], bb);
            }
        }

        // + relative position bias
        #pragma unroll
        for (int nt = 0; nt < 8; nt++) {
            int kc = k0 + nt * 8 + lr * 2;
            s[nt][0] += bias_tab[rp_bucket(rowA - kc)];
            s[nt][1] += bias_tab[rp_bucket(rowA - kc - 1)];
            s[nt][2] += bias_tab[rp_bucket(rowA + 8 - kc)];
            s[nt][3] += bias_tab[rp_bucket(rowA + 8 - kc - 1)];
        }

        // online softmax
        float mxA = NEG_INF, mxB = NEG_INF;
        #pragma unroll
        for (int nt = 0; nt < 8; nt++) {
            mxA = fmaxf(mxA, fmaxf(s[nt][0], s[nt][1]));
            mxB = fmaxf(mxB, fmaxf(s[nt][2], s[nt][3]));
        }
        mxA = fmaxf(mxA, __shfl_xor_sync(0xffffffffu, mxA, 1));
        mxA = fmaxf(mxA, __shfl_xor_sync(0xffffffffu, mxA, 2));
        mxB = fmaxf(mxB, __shfl_xor_sync(0xffffffffu, mxB, 1));
        mxB = fmaxf(mxB, __shfl_xor_sync(0xffffffffu, mxB, 2));
        float nmA = fmaxf(mA, mxA), nmB = fmaxf(mB, mxB);
        float alA = __expf(mA - nmA), alB = __expf(mB - nmB);
        float sumA = 0.f, sumB = 0.f;
        #pragma unroll
        for (int nt = 0; nt < 8; nt++) {
            s[nt][0] = __expf(s[nt][0] - nmA); sumA += s[nt][0];
            s[nt][1] = __expf(s[nt][1] - nmA); sumA += s[nt][1];
            s[nt][2] = __expf(s[nt][2] - nmB); sumB += s[nt][2];
            s[nt][3] = __expf(s[nt][3] - nmB); sumB += s[nt][3];
        }
        sumA += __shfl_xor_sync(0xffffffffu, sumA, 1);
        sumA += __shfl_xor_sync(0xffffffffu, sumA, 2);
        sumB += __shfl_xor_sync(0xffffffffu, sumB, 1);
        sumB += __shfl_xor_sync(0xffffffffu, sumB, 2);
        lA = lA * alA + sumA; mA = nmA;
        lB = lB * alB + sumB; mB = nmB;
        #pragma unroll
        for (int nt = 0; nt < 8; nt++) {
            o[nt][0] *= alA; o[nt][1] *= alA;
            o[nt][2] *= alB; o[nt][3] *= alB;
        }

        // stage P (tf32) in warp-private smem
        #pragma unroll
        for (int nt = 0; nt < 8; nt++) {
            int c = nt * 8 + lr * 2;
            PS(warpRow + lq, c)         = f2tf(s[nt][0]);
            PS(warpRow + lq, c + 1)     = f2tf(s[nt][1]);
            PS(warpRow + 8 + lq, c)     = f2tf(s[nt][2]);
            PS(warpRow + 8 + lq, c + 1) = f2tf(s[nt][3]);
        }
        __syncwarp();

        // O += P V
        #pragma unroll
        for (int ks = 0; ks < 8; ks++) {
            uint32_t ap[4];
            int cb = ks * 8 + lr;
            ap[0] = PS(warpRow + lq, cb);     ap[1] = PS(warpRow + 8 + lq, cb);
            ap[2] = PS(warpRow + lq, cb + 4); ap[3] = PS(warpRow + 8 + lq, cb + 4);
            #pragma unroll
            for (int nt = 0; nt < 8; nt++) {
                uint32_t bb[2];
                bb[0] = VS(st, ks * 8 + lr, nt * 8 + lq);
                bb[1] = VS(st, ks * 8 + lr + 4, nt * 8 + lq);
                mma8(o[nt], ap, bb);
            }
        }

        __syncthreads();   // stage fully consumed before refill
        if (t + 2 < NTILES) copyKV(t + 2, st);
    }

    float invA = 1.0f / lA, invB = 1.0f / lB;
    #pragma unroll
    for (int nt = 0; nt < 8; nt++) {
        int col = nt * 8 + lr * 2;
        float2 vA = { f2tff(o[nt][0] * invA), f2tff(o[nt][1] * invA) };
        float2 vB = { f2tff(o[nt][2] * invB), f2tff(o[nt][3] * invB) };
        *(float2*)&g_ctx[base + (size_t)rowA * Dq + col] = vA;
        *(float2*)&g_ctx[base + (size_t)(rowA + 8) * Dq + col] = vB;
    }
}

// ---------------------------------------------------------------------------
// Launch
// ---------------------------------------------------------------------------
extern "C" void kernel_launch(void* const* d_in, const int* in_sizes, int n_in,
                              void* d_out, int out_size)
{
    const float* input = (const float*)d_in[0];
    const float* wq    = (const float*)d_in[2];
    const float* wk    = (const float*)d_in[3];
    const float* wv    = (const float*)d_in[4];
    const float* wo    = (const float*)d_in[5];
    const float* rel   = (const float*)d_in[6];
    const float* lnw   = (const float*)d_in[7];
    float* out         = (float*)d_out;

    static const int FLASH_SMEM = FLASH_SMEM_WORDS * 4;   // 141312
    cudaFuncSetAttribute(flash_tc,
                         cudaFuncAttributeMaxDynamicSharedMemorySize, FLASH_SMEM);
    cudaFuncSetAttribute(gemm_tc2<false, true>,
                         cudaFuncAttributeMaxDynamicSharedMemorySize, GEMM_SMEM_BYTES);
    cudaFuncSetAttribute(gemm_tc2<true, false>,
                         cudaFuncAttributeMaxDynamicSharedMemorySize, GEMM_SMEM_BYTES);

    float *g_xn_p, *g_q_p, *g_k_p, *g_v_p, *g_ctx_p, *g_wt_p;
    cudaGetSymbolAddress((void**)&g_xn_p, g_xn);
    cudaGetSymbolAddress((void**)&g_q_p,  g_q);
    cudaGetSymbolAddress((void**)&g_k_p,  g_k);
    cudaGetSymbolAddress((void**)&g_v_p,  g_v);
    cudaGetSymbolAddress((void**)&g_ctx_p, g_ctx);
    cudaGetSymbolAddress((void**)&g_wt_p, g_wt);

    dim3 gw(Dq * Dq / 1024, 4);
    cvtw_kernel<<<gw, 256>>>(wq, wk, wv, wo);

    norm_kernel<<<Mq, 256>>>(input, lnw, g_xn_p);

    const float* wq_t = g_wt_p;
    const float* wk_t = g_wt_p + (size_t)Dq * Dq;
    const float* wv_t = g_wt_p + 2 * (size_t)Dq * Dq;
    const float* wo_t = g_wt_p + 3 * (size_t)Dq * Dq;

    dim3 gg(Dq / 128, Mq / 128);
    gemm_tc2<false, true><<<gg, 256, GEMM_SMEM_BYTES>>>(g_xn_p, wq_t, g_q_p, nullptr);
    gemm_tc2<false, true><<<gg, 256, GEMM_SMEM_BYTES>>>(g_xn_p, wk_t, g_k_p, nullptr);
    gemm_tc2<false, true><<<gg, 256, GEMM_SMEM_BYTES>>>(g_xn_p, wv_t, g_v_p, nullptr);

    dim3 gf(Sq / 128, Bq * Hq);
    flash_tc<<<gf, 256, FLASH_SMEM>>>(rel);

    gemm_tc2<true, false><<<gg, 256, GEMM_SMEM_BYTES>>>(g_ctx_p, wo_t, out, input);
}

// round 7
// speedup vs baseline: 1.1492x; 1.1492x over previous
#include <cuda_runtime.h>
#include <cstdint>

#define Bq   4
#define Sq   2048
#define Dq   1024
#define Hq   16
#define HDq  64
#define Mq   (Bq*Sq)

__device__ float g_xn[(size_t)Mq*Dq];
__device__ float g_q[(size_t)Mq*Dq];
__device__ float g_k[(size_t)Mq*Dq];
__device__ float g_v[(size_t)Mq*Dq];
__device__ float g_ctx[(size_t)Mq*Dq];
__device__ float g_wt[4][(size_t)Dq*Dq];   // tf32-rounded weights

// ---------------------------------------------------------------------------
// helpers
// ---------------------------------------------------------------------------
__device__ __forceinline__ uint32_t f2tf(float f) {
    uint32_t u;
    asm("cvt.rna.tf32.f32 %0, %1;" : "=r"(u) : "f"(f));
    return u;
}
__device__ __forceinline__ float f2tff(float f) {
    return __uint_as_float(f2tf(f));
}

__device__ __forceinline__ void mma8(float* c, const uint32_t* a, const uint32_t* b) {
    asm volatile(
        "mma.sync.aligned.m16n8k8.row.col.f32.tf32.tf32.f32 "
        "{%0,%1,%2,%3},{%4,%5,%6,%7},{%8,%9},{%0,%1,%2,%3};"
        : "+f"(c[0]), "+f"(c[1]), "+f"(c[2]), "+f"(c[3])
        : "r"(a[0]), "r"(a[1]), "r"(a[2]), "r"(a[3]), "r"(b[0]), "r"(b[1]));
}

__device__ __forceinline__ void cp16(uint32_t dst, const void* src) {
    asm volatile("cp.async.cg.shared.global [%0], [%1], 16;"
                 :: "r"(dst), "l"(src));
}
__device__ __forceinline__ void cp_commit() { asm volatile("cp.async.commit_group;"); }
__device__ __forceinline__ void cp_wait1()  { asm volatile("cp.async.wait_group 1;"); }
__device__ __forceinline__ void cp_wait0()  { asm volatile("cp.async.wait_group 0;"); }

__device__ __forceinline__ int rp_bucket(int rp) {
    if (rp < 0) rp = 0;
    if (rp < 16) return rp;
    int bk = 16 + (int)(__logf((float)rp * 0.0625f) * 7.6944086f);
    return bk > 31 ? 31 : bk;
}

// ---------------------------------------------------------------------------
// Kernel 0: round weights to tf32
// ---------------------------------------------------------------------------
__global__ __launch_bounds__(256) void cvtw_kernel(
    const float* __restrict__ w0, const float* __restrict__ w1,
    const float* __restrict__ w2, const float* __restrict__ w3)
{
    const float* w = (blockIdx.y == 0) ? w0 : (blockIdx.y == 1) ? w1
                   : (blockIdx.y == 2) ? w2 : w3;
    float* o = g_wt[blockIdx.y];
    size_t i = ((size_t)blockIdx.x * 256 + threadIdx.x) * 4;
    float4 v = *(const float4*)&w[i];
    float4 r = { f2tff(v.x), f2tff(v.y), f2tff(v.z), f2tff(v.w) };
    *(float4*)&o[i] = r;
}

// ---------------------------------------------------------------------------
// Kernel 1: RMS norm, tf32-rounded output
// ---------------------------------------------------------------------------
__global__ __launch_bounds__(256) void norm_kernel(
    const float* __restrict__ x, const float* __restrict__ lnw,
    float* __restrict__ xn)
{
    int row = blockIdx.x;
    const float4* xr = (const float4*)(x + (size_t)row * Dq);
    float4 v = xr[threadIdx.x];
    float s = v.x * v.x + v.y * v.y + v.z * v.z + v.w * v.w;
    __shared__ float red[8];
    #pragma unroll
    for (int o = 16; o > 0; o >>= 1) s += __shfl_xor_sync(0xffffffffu, s, o);
    if ((threadIdx.x & 31) == 0) red[threadIdx.x >> 5] = s;
    __syncthreads();
    float t = 0.f;
    #pragma unroll
    for (int i = 0; i < 8; i++) t += red[i];
    float rs = rsqrtf(t * (1.0f / (float)Dq) + 1e-6f);
    float4 lw = ((const float4*)lnw)[threadIdx.x];
    float4 o4 = { f2tff(v.x * rs * lw.x), f2tff(v.y * rs * lw.y),
                  f2tff(v.z * rs * lw.z), f2tff(v.w * rs * lw.w) };
    ((float4*)(xn + (size_t)row * Dq))[threadIdx.x] = o4;
}

// ---------------------------------------------------------------------------
// Kernel 2: tf32 GEMM (inputs pre-rounded), 3-stage cp.async. (R6 version)
// ---------------------------------------------------------------------------
#define GA_ST    36
#define GB_ST    136
#define GA_WORDS (128 * GA_ST)
#define GB_WORDS (32 * GB_ST)
#define GB_BASE  (3 * GA_WORDS)
#define GEMM_SMEM_BYTES ((3 * GA_WORDS + 3 * GB_WORDS) * 4)  // 107520
#define NKT (Dq / 32)

template<bool RES, bool ROUND>
__global__ __launch_bounds__(256, 2) void gemm_tc2(
    const float* __restrict__ A, const float* __restrict__ W,
    float* __restrict__ C, const float* __restrict__ res)
{
    extern __shared__ uint32_t smu[];
    uint32_t smb = (uint32_t)__cvta_generic_to_shared(smu);

    const int col0 = blockIdx.x << 7;
    const int row0 = blockIdx.y << 7;

    const int tid = threadIdx.x;
    const int wid = tid >> 5, lane = tid & 31;
    const int lq = lane >> 2, lr = lane & 3;
    const int warpM = (wid & 1) * 64;
    const int warpN = (wid >> 1) * 32;

    const int ar = tid >> 3, ac = (tid & 7) << 2;
    const int br = tid >> 5, bc = (tid & 31) << 2;

    auto copyTile = [&](int t, int st) {
        int k0 = t * 32;
        #pragma unroll
        for (int u = 0; u < 4; u++) {
            int r = ar + u * 32;
            cp16(smb + (st * GA_WORDS + r * GA_ST + ac) * 4,
                 A + (size_t)(row0 + r) * Dq + k0 + ac);
        }
        #pragma unroll
        for (int u = 0; u < 4; u++) {
            int r = br + u * 8;
            cp16(smb + (GB_BASE + st * GB_WORDS + r * GB_ST + bc) * 4,
                 W + (size_t)(k0 + r) * Dq + col0 + bc);
        }
        cp_commit();
    };

    float acc[4][4][4] = {};

    copyTile(0, 0);
    copyTile(1, 1);

    #pragma unroll 1
    for (int t = 0; t < NKT; t++) {
        int stage = t % 3;
        if (t + 1 < NKT) cp_wait1(); else cp_wait0();
        __syncthreads();
        if (t + 2 < NKT) copyTile(t + 2, (t + 2) % 3);

        const uint32_t* As = smu + stage * GA_WORDS;
        const uint32_t* Bs = smu + GB_BASE + stage * GB_WORDS;

        #pragma unroll
        for (int ks = 0; ks < 4; ks++) {
            uint32_t a[4][4], b[4][2];
            #pragma unroll
            for (int mt = 0; mt < 4; mt++) {
                int rb = warpM + mt * 16 + lq;
                int cb = ks * 8 + lr;
                a[mt][0] = As[rb * GA_ST + cb];
                a[mt][1] = As[(rb + 8) * GA_ST + cb];
                a[mt][2] = As[rb * GA_ST + cb + 4];
                a[mt][3] = As[(rb + 8) * GA_ST + cb + 4];
            }
            #pragma unroll
            for (int nt = 0; nt < 4; nt++) {
                int nb = warpN + nt * 8 + lq;
                b[nt][0] = Bs[(ks * 8 + lr) * GB_ST + nb];
                b[nt][1] = Bs[(ks * 8 + lr + 4) * GB_ST + nb];
            }
            #pragma unroll
            for (int mt = 0; mt < 4; mt++)
                #pragma unroll
                for (int nt = 0; nt < 4; nt++)
                    mma8(acc[mt][nt], a[mt], b[nt]);
        }
    }

    #pragma unroll
    for (int mt = 0; mt < 4; mt++)
        #pragma unroll
        for (int nt = 0; nt < 4; nt++) {
            int row = row0 + warpM + mt * 16 + lq;
            int col = col0 + warpN + nt * 8 + lr * 2;
            float2 v0 = { acc[mt][nt][0], acc[mt][nt][1] };
            float2 v1 = { acc[mt][nt][2], acc[mt][nt][3] };
            if (ROUND) {
                v0.x = f2tff(v0.x); v0.y = f2tff(v0.y);
                v1.x = f2tff(v1.x); v1.y = f2tff(v1.y);
            }
            if (RES) {
                float2 r0 = *(const float2*)&res[(size_t)row * Dq + col];
                float2 r1 = *(const float2*)&res[(size_t)(row + 8) * Dq + col];
                v0.x += r0.x; v0.y += r0.y; v1.x += r1.x; v1.y += r1.y;
            }
            *(float2*)&C[(size_t)row * Dq + col] = v0;
            *(float2*)&C[(size_t)(row + 8) * Dq + col] = v1;
        }
}

// ---------------------------------------------------------------------------
// Kernel 3: flash attention — EXACT R3 structure (empirically fastest, ~274us).
// No launch-bounds cap, plain LDG->STS loads, Q frags re-read from smem.
// Inputs pre-rounded tf32 -> raw bit copies (no cvt). ctx rounded at write.
// ---------------------------------------------------------------------------
#define QS(r, c) sm[(r) * 68 + (c)]
#define KS(r, c) sm[8704 + (r) * 68 + (c)]
#define VS(r, c) sm[13056 + (r) * 72 + (c)]
#define PS(r, c) sm[17664 + (r) * 68 + (c)]
#define FLASH_SMEM_WORDS (17664 + 128 * 68)

__global__ __launch_bounds__(256) void flash_tc(const float* __restrict__ rel_emb)
{
    extern __shared__ uint32_t sm[];
    __shared__ float bias_tab[32];

    const int tid = threadIdx.x;
    const int wid = tid >> 5, lane = tid & 31;
    const int lq = lane >> 2, lr = lane & 3;
    const int warpRow = wid * 16;

    const int q0 = blockIdx.x << 7;
    const int bh = blockIdx.y;
    const int b = bh >> 4, h = bh & 15;
    const size_t base = ((size_t)b * Sq) * Dq + (size_t)h * HDq;

    if (tid < 32) bias_tab[tid] = rel_emb[tid * Hq + h];

    #pragma unroll
    for (int u = 0; u < 8; u++) {
        int lin = tid + u * 256;
        int r = lin >> 4, c4 = (lin & 15) << 2;
        *(uint4*)&QS(r, c4) =
            *(const uint4*)&g_q[base + (size_t)(q0 + r) * Dq + c4];
    }

    const float NEG_INF = __int_as_float(0xff800000u);
    float mA = NEG_INF, mB = NEG_INF, lA = 0.f, lB = 0.f;
    float o[8][4] = {};
    const int rowA = q0 + warpRow + lq;

    for (int k0 = 0; k0 < Sq; k0 += 64) {
        __syncthreads();
        #pragma unroll
        for (int u = 0; u < 4; u++) {
            int lin = tid + u * 256;
            int r = lin >> 4, c4 = (lin & 15) << 2;
            *(uint4*)&KS(r, c4) =
                *(const uint4*)&g_k[base + (size_t)(k0 + r) * Dq + c4];
            *(uint4*)&VS(r, c4) =
                *(const uint4*)&g_v[base + (size_t)(k0 + r) * Dq + c4];
        }
        __syncthreads();

        float s[8][4] = {};
        uint32_t aq[8][4];
        #pragma unroll
        for (int ks = 0; ks < 8; ks++) {
            int rb = warpRow + lq, cb = ks * 8 + lr;
            aq[ks][0] = QS(rb, cb);     aq[ks][1] = QS(rb + 8, cb);
            aq[ks][2] = QS(rb, cb + 4); aq[ks][3] = QS(rb + 8, cb + 4);
        }
        #pragma unroll
        for (int nt = 0; nt < 8; nt++) {
            #pragma unroll
            for (int ks = 0; ks < 8; ks++) {
                uint32_t bb[2];
                bb[0] = KS(nt * 8 + lq, ks * 8 + lr);
                bb[1] = KS(nt * 8 + lq, ks * 8 + lr + 4);
                mma8(s[nt], aq[ks], bb);
            }
        }

        #pragma unroll
        for (int nt = 0; nt < 8; nt++) {
            int kc = k0 + nt * 8 + lr * 2;
            s[nt][0] += bias_tab[rp_bucket(rowA - kc)];
            s[nt][1] += bias_tab[rp_bucket(rowA - kc - 1)];
            s[nt][2] += bias_tab[rp_bucket(rowA + 8 - kc)];
            s[nt][3] += bias_tab[rp_bucket(rowA + 8 - kc - 1)];
        }

        float mxA = NEG_INF, mxB = NEG_INF;
        #pragma unroll
        for (int nt = 0; nt < 8; nt++) {
            mxA = fmaxf(mxA, fmaxf(s[nt][0], s[nt][1]));
            mxB = fmaxf(mxB, fmaxf(s[nt][2], s[nt][3]));
        }
        mxA = fmaxf(mxA, __shfl_xor_sync(0xffffffffu, mxA, 1));
        mxA = fmaxf(mxA, __shfl_xor_sync(0xffffffffu, mxA, 2));
        mxB = fmaxf(mxB, __shfl_xor_sync(0xffffffffu, mxB, 1));
        mxB = fmaxf(mxB, __shfl_xor_sync(0xffffffffu, mxB, 2));
        float nmA = fmaxf(mA, mxA), nmB = fmaxf(mB, mxB);
        float alA = __expf(mA - nmA), alB = __expf(mB - nmB);
        float sumA = 0.f, sumB = 0.f;
        #pragma unroll
        for (int nt = 0; nt < 8; nt++) {
            s[nt][0] = __expf(s[nt][0] - nmA); sumA += s[nt][0];
            s[nt][1] = __expf(s[nt][1] - nmA); sumA += s[nt][1];
            s[nt][2] = __expf(s[nt][2] - nmB); sumB += s[nt][2];
            s[nt][3] = __expf(s[nt][3] - nmB); sumB += s[nt][3];
        }
        sumA += __shfl_xor_sync(0xffffffffu, sumA, 1);
        sumA += __shfl_xor_sync(0xffffffffu, sumA, 2);
        sumB += __shfl_xor_sync(0xffffffffu, sumB, 1);
        sumB += __shfl_xor_sync(0xffffffffu, sumB, 2);
        lA = lA * alA + sumA; mA = nmA;
        lB = lB * alB + sumB; mB = nmB;
        #pragma unroll
        for (int nt = 0; nt < 8; nt++) {
            o[nt][0] *= alA; o[nt][1] *= alA;
            o[nt][2] *= alB; o[nt][3] *= alB;
        }

        #pragma unroll
        for (int nt = 0; nt < 8; nt++) {
            int c = nt * 8 + lr * 2;
            PS(warpRow + lq, c)         = f2tf(s[nt][0]);
            PS(warpRow + lq, c + 1)     = f2tf(s[nt][1]);
            PS(warpRow + 8 + lq, c)     = f2tf(s[nt][2]);
            PS(warpRow + 8 + lq, c + 1) = f2tf(s[nt][3]);
        }
        __syncwarp();

        #pragma unroll
        for (int ks = 0; ks < 8; ks++) {
            uint32_t ap[4];
            int cb = ks * 8 + lr;
            ap[0] = PS(warpRow + lq, cb);     ap[1] = PS(warpRow + 8 + lq, cb);
            ap[2] = PS(warpRow + lq, cb + 4); ap[3] = PS(warpRow + 8 + lq, cb + 4);
            #pragma unroll
            for (int nt = 0; nt < 8; nt++) {
                uint32_t bb[2];
                bb[0] = VS(ks * 8 + lr, nt * 8 + lq);
                bb[1] = VS(ks * 8 + lr + 4, nt * 8 + lq);
                mma8(o[nt], ap, bb);
            }
        }
    }

    float invA = 1.0f / lA, invB = 1.0f / lB;
    #pragma unroll
    for (int nt = 0; nt < 8; nt++) {
        int col = nt * 8 + lr * 2;
        float2 vA = { f2tff(o[nt][0] * invA), f2tff(o[nt][1] * invA) };
        float2 vB = { f2tff(o[nt][2] * invB), f2tff(o[nt][3] * invB) };
        *(float2*)&g_ctx[base + (size_t)rowA * Dq + col] = vA;
        *(float2*)&g_ctx[base + (size_t)(rowA + 8) * Dq + col] = vB;
    }
}

// ---------------------------------------------------------------------------
// Launch
// ---------------------------------------------------------------------------
extern "C" void kernel_launch(void* const* d_in, const int* in_sizes, int n_in,
                              void* d_out, int out_size)
{
    const float* input = (const float*)d_in[0];
    const float* wq    = (const float*)d_in[2];
    const float* wk    = (const float*)d_in[3];
    const float* wv    = (const float*)d_in[4];
    const float* wo    = (const float*)d_in[5];
    const float* rel   = (const float*)d_in[6];
    const float* lnw   = (const float*)d_in[7];
    float* out         = (float*)d_out;

    static const int FLASH_SMEM = FLASH_SMEM_WORDS * 4;   // 105472
    cudaFuncSetAttribute(flash_tc,
                         cudaFuncAttributeMaxDynamicSharedMemorySize, FLASH_SMEM);
    cudaFuncSetAttribute(gemm_tc2<false, true>,
                         cudaFuncAttributeMaxDynamicSharedMemorySize, GEMM_SMEM_BYTES);
    cudaFuncSetAttribute(gemm_tc2<true, false>,
                         cudaFuncAttributeMaxDynamicSharedMemorySize, GEMM_SMEM_BYTES);

    float *g_xn_p, *g_q_p, *g_k_p, *g_v_p, *g_ctx_p, *g_wt_p;
    cudaGetSymbolAddress((void**)&g_xn_p, g_xn);
    cudaGetSymbolAddress((void**)&g_q_p,  g_q);
    cudaGetSymbolAddress((void**)&g_k_p,  g_k);
    cudaGetSymbolAddress((void**)&g_v_p,  g_v);
    cudaGetSymbolAddress((void**)&g_ctx_p, g_ctx);
    cudaGetSymbolAddress((void**)&g_wt_p, g_wt);

    dim3 gw(Dq * Dq / 1024, 4);
    cvtw_kernel<<<gw, 256>>>(wq, wk, wv, wo);

    norm_kernel<<<Mq, 256>>>(input, lnw, g_xn_p);

    const float* wq_t = g_wt_p;
    const float* wk_t = g_wt_p + (size_t)Dq * Dq;
    const float* wv_t = g_wt_p + 2 * (size_t)Dq * Dq;
    const float* wo_t = g_wt_p + 3 * (size_t)Dq * Dq;

    dim3 gg(Dq / 128, Mq / 128);
    gemm_tc2<false, true><<<gg, 256, GEMM_SMEM_BYTES>>>(g_xn_p, wq_t, g_q_p, nullptr);
    gemm_tc2<false, true><<<gg, 256, GEMM_SMEM_BYTES>>>(g_xn_p, wk_t, g_k_p, nullptr);
    gemm_tc2<false, true><<<gg, 256, GEMM_SMEM_BYTES>>>(g_xn_p, wv_t, g_v_p, nullptr);

    dim3 gf(Sq / 128, Bq * Hq);
    flash_tc<<<gf, 256, FLASH_SMEM>>>(rel);

    gemm_tc2<true, false><<<gg, 256, GEMM_SMEM_BYTES>>>(g_ctx_p, wo_t, out, input);
}

// round 9
// speedup vs baseline: 1.2092x; 1.0522x over previous
#include <cuda_runtime.h>
#include <cstdint>

#define Bq   4
#define Sq   2048
#define Dq   1024
#define Hq   16
#define HDq  64
#define Mq   (Bq*Sq)

__device__ float g_xn[(size_t)Mq*Dq];
__device__ float g_q[(size_t)Mq*Dq];
__device__ float g_k[(size_t)Mq*Dq];
__device__ float g_v[(size_t)Mq*Dq];
__device__ float g_ctx[(size_t)Mq*Dq];
__device__ float g_wt[4][(size_t)Dq*Dq];   // tf32-rounded weights

// ---------------------------------------------------------------------------
// helpers
// ---------------------------------------------------------------------------
__device__ __forceinline__ uint32_t f2tf(float f) {
    uint32_t u;
    asm("cvt.rna.tf32.f32 %0, %1;" : "=r"(u) : "f"(f));
    return u;
}
__device__ __forceinline__ float f2tff(float f) {
    return __uint_as_float(f2tf(f));
}

__device__ __forceinline__ void mma8(float* c, const uint32_t* a, const uint32_t* b) {
    asm volatile(
        "mma.sync.aligned.m16n8k8.row.col.f32.tf32.tf32.f32 "
        "{%0,%1,%2,%3},{%4,%5,%6,%7},{%8,%9},{%0,%1,%2,%3};"
        : "+f"(c[0]), "+f"(c[1]), "+f"(c[2]), "+f"(c[3])
        : "r"(a[0]), "r"(a[1]), "r"(a[2]), "r"(a[3]), "r"(b[0]), "r"(b[1]));
}

__device__ __forceinline__ void cp16(uint32_t dst, const void* src) {
    asm volatile("cp.async.cg.shared.global [%0], [%1], 16;"
                 :: "r"(dst), "l"(src));
}
__device__ __forceinline__ void cp_commit() { asm volatile("cp.async.commit_group;"); }
__device__ __forceinline__ void cp_wait1()  { asm volatile("cp.async.wait_group 1;"); }
__device__ __forceinline__ void cp_wait0()  { asm volatile("cp.async.wait_group 0;"); }

__device__ __forceinline__ int rp_bucket(int rp) {
    if (rp < 0) rp = 0;
    if (rp < 16) return rp;
    int bk = 16 + (int)(__logf((float)rp * 0.0625f) * 7.6944086f);
    return bk > 31 ? 31 : bk;
}

// ---------------------------------------------------------------------------
// Kernel 0: round weights to tf32
// ---------------------------------------------------------------------------
__global__ __launch_bounds__(256) void cvtw_kernel(
    const float* __restrict__ w0, const float* __restrict__ w1,
    const float* __restrict__ w2, const float* __restrict__ w3)
{
    const float* w = (blockIdx.y == 0) ? w0 : (blockIdx.y == 1) ? w1
                   : (blockIdx.y == 2) ? w2 : w3;
    float* o = g_wt[blockIdx.y];
    size_t i = ((size_t)blockIdx.x * 256 + threadIdx.x) * 4;
    float4 v = *(const float4*)&w[i];
    float4 r = { f2tff(v.x), f2tff(v.y), f2tff(v.z), f2tff(v.w) };
    *(float4*)&o[i] = r;
}

// ---------------------------------------------------------------------------
// Kernel 1: RMS norm, tf32-rounded output
// ---------------------------------------------------------------------------
__global__ __launch_bounds__(256) void norm_kernel(
    const float* __restrict__ x, const float* __restrict__ lnw,
    float* __restrict__ xn)
{
    int row = blockIdx.x;
    const float4* xr = (const float4*)(x + (size_t)row * Dq);
    float4 v = xr[threadIdx.x];
    float s = v.x * v.x + v.y * v.y + v.z * v.z + v.w * v.w;
    __shared__ float red[8];
    #pragma unroll
    for (int o = 16; o > 0; o >>= 1) s += __shfl_xor_sync(0xffffffffu, s, o);
    if ((threadIdx.x & 31) == 0) red[threadIdx.x >> 5] = s;
    __syncthreads();
    float t = 0.f;
    #pragma unroll
    for (int i = 0; i < 8; i++) t += red[i];
    float rs = rsqrtf(t * (1.0f / (float)Dq) + 1e-6f);
    float4 lw = ((const float4*)lnw)[threadIdx.x];
    float4 o4 = { f2tff(v.x * rs * lw.x), f2tff(v.y * rs * lw.y),
                  f2tff(v.z * rs * lw.z), f2tff(v.w * rs * lw.w) };
    ((float4*)(xn + (size_t)row * Dq))[threadIdx.x] = o4;
}

// ---------------------------------------------------------------------------
// Kernel 2: tf32 GEMM (inputs pre-rounded), 3-stage cp.async. (unchanged)
// ---------------------------------------------------------------------------
#define GA_ST    36
#define GB_ST    136
#define GA_WORDS (128 * GA_ST)
#define GB_WORDS (32 * GB_ST)
#define GB_BASE  (3 * GA_WORDS)
#define GEMM_SMEM_BYTES ((3 * GA_WORDS + 3 * GB_WORDS) * 4)  // 107520
#define NKT (Dq / 32)

template<bool RES, bool ROUND>
__global__ __launch_bounds__(256, 2) void gemm_tc2(
    const float* __restrict__ A, const float* __restrict__ W,
    float* __restrict__ C, const float* __restrict__ res)
{
    extern __shared__ uint32_t smu[];
    uint32_t smb = (uint32_t)__cvta_generic_to_shared(smu);

    const int col0 = blockIdx.x << 7;
    const int row0 = blockIdx.y << 7;

    const int tid = threadIdx.x;
    const int wid = tid >> 5, lane = tid & 31;
    const int lq = lane >> 2, lr = lane & 3;
    const int warpM = (wid & 1) * 64;
    const int warpN = (wid >> 1) * 32;

    const int ar = tid >> 3, ac = (tid & 7) << 2;
    const int br = tid >> 5, bc = (tid & 31) << 2;

    auto copyTile = [&](int t, int st) {
        int k0 = t * 32;
        #pragma unroll
        for (int u = 0; u < 4; u++) {
            int r = ar + u * 32;
            cp16(smb + (st * GA_WORDS + r * GA_ST + ac) * 4,
                 A + (size_t)(row0 + r) * Dq + k0 + ac);
        }
        #pragma unroll
        for (int u = 0; u < 4; u++) {
            int r = br + u * 8;
            cp16(smb + (GB_BASE + st * GB_WORDS + r * GB_ST + bc) * 4,
                 W + (size_t)(k0 + r) * Dq + col0 + bc);
        }
        cp_commit();
    };

    float acc[4][4][4] = {};

    copyTile(0, 0);
    copyTile(1, 1);

    #pragma unroll 1
    for (int t = 0; t < NKT; t++) {
        int stage = t % 3;
        if (t + 1 < NKT) cp_wait1(); else cp_wait0();
        __syncthreads();
        if (t + 2 < NKT) copyTile(t + 2, (t + 2) % 3);

        const uint32_t* As = smu + stage * GA_WORDS;
        const uint32_t* Bs = smu + GB_BASE + stage * GB_WORDS;

        #pragma unroll
        for (int ks = 0; ks < 4; ks++) {
            uint32_t a[4][4], b[4][2];
            #pragma unroll
            for (int mt = 0; mt < 4; mt++) {
                int rb = warpM + mt * 16 + lq;
                int cb = ks * 8 + lr;
                a[mt][0] = As[rb * GA_ST + cb];
                a[mt][1] = As[(rb + 8) * GA_ST + cb];
                a[mt][2] = As[rb * GA_ST + cb + 4];
                a[mt][3] = As[(rb + 8) * GA_ST + cb + 4];
            }
            #pragma unroll
            for (int nt = 0; nt < 4; nt++) {
                int nb = warpN + nt * 8 + lq;
                b[nt][0] = Bs[(ks * 8 + lr) * GB_ST + nb];
                b[nt][1] = Bs[(ks * 8 + lr + 4) * GB_ST + nb];
            }
            #pragma unroll
            for (int mt = 0; mt < 4; mt++)
                #pragma unroll
                for (int nt = 0; nt < 4; nt++)
                    mma8(acc[mt][nt], a[mt], b[nt]);
        }
    }

    #pragma unroll
    for (int mt = 0; mt < 4; mt++)
        #pragma unroll
        for (int nt = 0; nt < 4; nt++) {
            int row = row0 + warpM + mt * 16 + lq;
            int col = col0 + warpN + nt * 8 + lr * 2;
            float2 v0 = { acc[mt][nt][0], acc[mt][nt][1] };
            float2 v1 = { acc[mt][nt][2], acc[mt][nt][3] };
            if (ROUND) {
                v0.x = f2tff(v0.x); v0.y = f2tff(v0.y);
                v1.x = f2tff(v1.x); v1.y = f2tff(v1.y);
            }
            if (RES) {
                float2 r0 = *(const float2*)&res[(size_t)row * Dq + col];
                float2 r1 = *(const float2*)&res[(size_t)(row + 8) * Dq + col];
                v0.x += r0.x; v0.y += r0.y; v1.x += r1.x; v1.y += r1.y;
            }
            *(float2*)&C[(size_t)row * Dq + col] = v0;
            *(float2*)&C[(size_t)(row + 8) * Dq + col] = v1;
        }
}

// ---------------------------------------------------------------------------
// Kernel 3: flash attention — 64-query CTAs, 128 threads, 3 CTAs/SM.
// FIX vs R8: K/V copy loop now u<8 (full 64 rows with 128 threads).
// ---------------------------------------------------------------------------
#define QS(r, c) sm[(r) * 68 + (c)]
#define KS(r, c) sm[4352 + (r) * 68 + (c)]
#define VS(r, c) sm[8704 + (r) * 72 + (c)]
#define PS(r, c) sm[13312 + (r) * 68 + (c)]
#define FLASH_SMEM_WORDS 17664

__global__ __launch_bounds__(128, 3) void flash_tc(const float* __restrict__ rel_emb)
{
    extern __shared__ uint32_t sm[];
    __shared__ float bias_tab[32];

    const int tid = threadIdx.x;
    const int wid = tid >> 5, lane = tid & 31;
    const int lq = lane >> 2, lr = lane & 3;
    const int warpRow = wid * 16;

    const int q0 = blockIdx.x << 6;
    const int bh = blockIdx.y;
    const int b = bh >> 4, h = bh & 15;
    const size_t base = ((size_t)b * Sq) * Dq + (size_t)h * HDq;

    if (tid < 32) bias_tab[tid] = rel_emb[tid * Hq + h];

    // load Q tile (64 x 64, raw tf32 bits)
    #pragma unroll
    for (int u = 0; u < 8; u++) {
        int lin = tid + u * 128;
        int r = lin >> 4, c4 = (lin & 15) << 2;
        *(uint4*)&QS(r, c4) =
            *(const uint4*)&g_q[base + (size_t)(q0 + r) * Dq + c4];
    }
    __syncthreads();   // bias_tab + Q visible

    const float NEG_INF = __int_as_float(0xff800000u);
    float mA = NEG_INF, mB = NEG_INF, lA = 0.f, lB = 0.f;
    float o[8][4] = {};
    const int rowA = q0 + warpRow + lq;
    const float b31 = bias_tab[31];
    const float b0  = bias_tab[0];

    for (int k0 = 0; k0 < Sq; k0 += 64) {
        __syncthreads();
        #pragma unroll
        for (int u = 0; u < 8; u++) {        // FIX: was u < 4 (half-loaded K/V)
            int lin = tid + u * 128;
            int r = lin >> 4, c4 = (lin & 15) << 2;
            *(uint4*)&KS(r, c4) =
                *(const uint4*)&g_k[base + (size_t)(k0 + r) * Dq + c4];
            *(uint4*)&VS(r, c4) =
                *(const uint4*)&g_v[base + (size_t)(k0 + r) * Dq + c4];
        }
        __syncthreads();

        // S = Q K^T
        float s[8][4] = {};
        uint32_t aq[8][4];
        #pragma unroll
        for (int ks = 0; ks < 8; ks++) {
            int rb = warpRow + lq, cb = ks * 8 + lr;
            aq[ks][0] = QS(rb, cb);     aq[ks][1] = QS(rb + 8, cb);
            aq[ks][2] = QS(rb, cb + 4); aq[ks][3] = QS(rb + 8, cb + 4);
        }
        #pragma unroll
        for (int nt = 0; nt < 8; nt++) {
            #pragma unroll
            for (int ks = 0; ks < 8; ks++) {
                uint32_t bb[2];
                bb[0] = KS(nt * 8 + lq, ks * 8 + lr);
                bb[1] = KS(nt * 8 + lq, ks * 8 + lr + 4);
                mma8(s[nt], aq[ks], bb);
            }
        }

        // + relative position bias (fast path when bucket constant over tile)
        if (rowA - (k0 + 63) >= 128) {
            #pragma unroll
            for (int nt = 0; nt < 8; nt++) {
                s[nt][0] += b31; s[nt][1] += b31;
                s[nt][2] += b31; s[nt][3] += b31;
            }
        } else if (k0 > rowA + 8) {
            #pragma unroll
            for (int nt = 0; nt < 8; nt++) {
                s[nt][0] += b0; s[nt][1] += b0;
                s[nt][2] += b0; s[nt][3] += b0;
            }
        } else {
            #pragma unroll
            for (int nt = 0; nt < 8; nt++) {
                int kc = k0 + nt * 8 + lr * 2;
                s[nt][0] += bias_tab[rp_bucket(rowA - kc)];
                s[nt][1] += bias_tab[rp_bucket(rowA - kc - 1)];
                s[nt][2] += bias_tab[rp_bucket(rowA + 8 - kc)];
                s[nt][3] += bias_tab[rp_bucket(rowA + 8 - kc - 1)];
            }
        }

        // online softmax
        float mxA = NEG_INF, mxB = NEG_INF;
        #pragma unroll
        for (int nt = 0; nt < 8; nt++) {
            mxA = fmaxf(mxA, fmaxf(s[nt][0], s[nt][1]));
            mxB = fmaxf(mxB, fmaxf(s[nt][2], s[nt][3]));
        }
        mxA = fmaxf(mxA, __shfl_xor_sync(0xffffffffu, mxA, 1));
        mxA = fmaxf(mxA, __shfl_xor_sync(0xffffffffu, mxA, 2));
        mxB = fmaxf(mxB, __shfl_xor_sync(0xffffffffu, mxB, 1));
        mxB = fmaxf(mxB, __shfl_xor_sync(0xffffffffu, mxB, 2));
        float nmA = fmaxf(mA, mxA), nmB = fmaxf(mB, mxB);
        float alA = __expf(mA - nmA), alB = __expf(mB - nmB);
        float sumA = 0.f, sumB = 0.f;
        #pragma unroll
        for (int nt = 0; nt < 8; nt++) {
            s[nt][0] = __expf(s[nt][0] - nmA); sumA += s[nt][0];
            s[nt][1] = __expf(s[nt][1] - nmA); sumA += s[nt][1];
            s[nt][2] = __expf(s[nt][2] - nmB); sumB += s[nt][2];
            s[nt][3] = __expf(s[nt][3] - nmB); sumB += s[nt][3];
        }
        sumA += __shfl_xor_sync(0xffffffffu, sumA, 1);
        sumA += __shfl_xor_sync(0xffffffffu, sumA, 2);
        sumB += __shfl_xor_sync(0xffffffffu, sumB, 1);
        sumB += __shfl_xor_sync(0xffffffffu, sumB, 2);
        lA = lA * alA + sumA; mA = nmA;
        lB = lB * alB + sumB; mB = nmB;
        #pragma unroll
        for (int nt = 0; nt < 8; nt++) {
            o[nt][0] *= alA; o[nt][1] *= alA;
            o[nt][2] *= alB; o[nt][3] *= alB;
        }

        // stage P (tf32) in warp-private smem
        #pragma unroll
        for (int nt = 0; nt < 8; nt++) {
            int c = nt * 8 + lr * 2;
            PS(warpRow + lq, c)         = f2tf(s[nt][0]);
            PS(warpRow + lq, c + 1)     = f2tf(s[nt][1]);
            PS(warpRow + 8 + lq, c)     = f2tf(s[nt][2]);
            PS(warpRow + 8 + lq, c + 1) = f2tf(s[nt][3]);
        }
        __syncwarp();

        // O += P V
        #pragma unroll
        for (int ks = 0; ks < 8; ks++) {
            uint32_t ap[4];
            int cb = ks * 8 + lr;
            ap[0] = PS(warpRow + lq, cb);     ap[1] = PS(warpRow + 8 + lq, cb);
            ap[2] = PS(warpRow + lq, cb + 4); ap[3] = PS(warpRow + 8 + lq, cb + 4);
            #pragma unroll
            for (int nt = 0; nt < 8; nt++) {
                uint32_t bb[2];
                bb[0] = VS(ks * 8 + lr, nt * 8 + lq);
                bb[1] = VS(ks * 8 + lr + 4, nt * 8 + lq);
                mma8(o[nt], ap, bb);
            }
        }
    }

    float invA = 1.0f / lA, invB = 1.0f / lB;
    #pragma unroll
    for (int nt = 0; nt < 8; nt++) {
        int col = nt * 8 + lr * 2;
        float2 vA = { f2tff(o[nt][0] * invA), f2tff(o[nt][1] * invA) };
        float2 vB = { f2tff(o[nt][2] * invB), f2tff(o[nt][3] * invB) };
        *(float2*)&g_ctx[base + (size_t)rowA * Dq + col] = vA;
        *(float2*)&g_ctx[base + (size_t)(rowA + 8) * Dq + col] = vB;
    }
}

// ---------------------------------------------------------------------------
// Launch
// ---------------------------------------------------------------------------
extern "C" void kernel_launch(void* const* d_in, const int* in_sizes, int n_in,
                              void* d_out, int out_size)
{
    const float* input = (const float*)d_in[0];
    const float* wq    = (const float*)d_in[2];
    const float* wk    = (const float*)d_in[3];
    const float* wv    = (const float*)d_in[4];
    const float* wo    = (const float*)d_in[5];
    const float* rel   = (const float*)d_in[6];
    const float* lnw   = (const float*)d_in[7];
    float* out         = (float*)d_out;

    static const int FLASH_SMEM = FLASH_SMEM_WORDS * 4;   // 70656
    cudaFuncSetAttribute(flash_tc,
                         cudaFuncAttributeMaxDynamicSharedMemorySize, FLASH_SMEM);
    cudaFuncSetAttribute(gemm_tc2<false, true>,
                         cudaFuncAttributeMaxDynamicSharedMemorySize, GEMM_SMEM_BYTES);
    cudaFuncSetAttribute(gemm_tc2<true, false>,
                         cudaFuncAttributeMaxDynamicSharedMemorySize, GEMM_SMEM_BYTES);

    float *g_xn_p, *g_q_p, *g_k_p, *g_v_p, *g_ctx_p, *g_wt_p;
    cudaGetSymbolAddress((void**)&g_xn_p, g_xn);
    cudaGetSymbolAddress((void**)&g_q_p,  g_q);
    cudaGetSymbolAddress((void**)&g_k_p,  g_k);
    cudaGetSymbolAddress((void**)&g_v_p,  g_v);
    cudaGetSymbolAddress((void**)&g_ctx_p, g_ctx);
    cudaGetSymbolAddress((void**)&g_wt_p, g_wt);

    dim3 gw(Dq * Dq / 1024, 4);
    cvtw_kernel<<<gw, 256>>>(wq, wk, wv, wo);

    norm_kernel<<<Mq, 256>>>(input, lnw, g_xn_p);

    const float* wq_t = g_wt_p;
    const float* wk_t = g_wt_p + (size_t)Dq * Dq;
    const float* wv_t = g_wt_p + 2 * (size_t)Dq * Dq;
    const float* wo_t = g_wt_p + 3 * (size_t)Dq * Dq;

    dim3 gg(Dq / 128, Mq / 128);
    gemm_tc2<false, true><<<gg, 256, GEMM_SMEM_BYTES>>>(g_xn_p, wq_t, g_q_p, nullptr);
    gemm_tc2<false, true><<<gg, 256, GEMM_SMEM_BYTES>>>(g_xn_p, wk_t, g_k_p, nullptr);
    gemm_tc2<false, true><<<gg, 256, GEMM_SMEM_BYTES>>>(g_xn_p, wv_t, g_v_p, nullptr);

    dim3 gf(Sq / 64, Bq * Hq);
    flash_tc<<<gf, 128, FLASH_SMEM>>>(rel);

    gemm_tc2<true, false><<<gg, 256, GEMM_SMEM_BYTES>>>(g_ctx_p, wo_t, out, input);
}

// round 10
// speedup vs baseline: 1.2486x; 1.0326x over previous
#include <cuda_runtime.h>
#include <cstdint>

#define Bq   4
#define Sq   2048
#define Dq   1024
#define Hq   16
#define HDq  64
#define Mq   (Bq*Sq)

__device__ float g_xn[(size_t)Mq*Dq];
__device__ float g_q[(size_t)Mq*Dq];
__device__ float g_k[(size_t)Mq*Dq];
__device__ float g_v[(size_t)Mq*Dq];
__device__ float g_ctx[(size_t)Mq*Dq];
__device__ float g_wt[4][(size_t)Dq*Dq];   // tf32-rounded weights

// ---------------------------------------------------------------------------
// helpers
// ---------------------------------------------------------------------------
__device__ __forceinline__ uint32_t f2tf(float f) {
    uint32_t u;
    asm("cvt.rna.tf32.f32 %0, %1;" : "=r"(u) : "f"(f));
    return u;
}
__device__ __forceinline__ float f2tff(float f) {
    return __uint_as_float(f2tf(f));
}

__device__ __forceinline__ void mma8(float* c, const uint32_t* a, const uint32_t* b) {
    asm volatile(
        "mma.sync.aligned.m16n8k8.row.col.f32.tf32.tf32.f32 "
        "{%0,%1,%2,%3},{%4,%5,%6,%7},{%8,%9},{%0,%1,%2,%3};"
        : "+f"(c[0]), "+f"(c[1]), "+f"(c[2]), "+f"(c[3])
        : "r"(a[0]), "r"(a[1]), "r"(a[2]), "r"(a[3]), "r"(b[0]), "r"(b[1]));
}

__device__ __forceinline__ void ldsm4(uint32_t& r0, uint32_t& r1,
                                      uint32_t& r2, uint32_t& r3, uint32_t addr) {
    asm volatile("ldmatrix.sync.aligned.m8n8.x4.shared.b16 {%0,%1,%2,%3}, [%4];"
                 : "=r"(r0), "=r"(r1), "=r"(r2), "=r"(r3) : "r"(addr));
}

__device__ __forceinline__ void cp16(uint32_t dst, const void* src) {
    asm volatile("cp.async.cg.shared.global [%0], [%1], 16;"
                 :: "r"(dst), "l"(src));
}
__device__ __forceinline__ void cp_commit() { asm volatile("cp.async.commit_group;"); }
__device__ __forceinline__ void cp_wait1()  { asm volatile("cp.async.wait_group 1;"); }
__device__ __forceinline__ void cp_wait0()  { asm volatile("cp.async.wait_group 0;"); }

__device__ __forceinline__ int rp_bucket(int rp) {
    if (rp < 0) rp = 0;
    if (rp < 16) return rp;
    int bk = 16 + (int)(__logf((float)rp * 0.0625f) * 7.6944086f);
    return bk > 31 ? 31 : bk;
}

// ---------------------------------------------------------------------------
// Kernel 0: round weights to tf32
// ---------------------------------------------------------------------------
__global__ __launch_bounds__(256) void cvtw_kernel(
    const float* __restrict__ w0, const float* __restrict__ w1,
    const float* __restrict__ w2, const float* __restrict__ w3)
{
    const float* w = (blockIdx.y == 0) ? w0 : (blockIdx.y == 1) ? w1
                   : (blockIdx.y == 2) ? w2 : w3;
    float* o = g_wt[blockIdx.y];
    size_t i = ((size_t)blockIdx.x * 256 + threadIdx.x) * 4;
    float4 v = *(const float4*)&w[i];
    float4 r = { f2tff(v.x), f2tff(v.y), f2tff(v.z), f2tff(v.w) };
    *(float4*)&o[i] = r;
}

// ---------------------------------------------------------------------------
// Kernel 1: RMS norm, tf32-rounded output
// ---------------------------------------------------------------------------
__global__ __launch_bounds__(256) void norm_kernel(
    const float* __restrict__ x, const float* __restrict__ lnw,
    float* __restrict__ xn)
{
    int row = blockIdx.x;
    const float4* xr = (const float4*)(x + (size_t)row * Dq);
    float4 v = xr[threadIdx.x];
    float s = v.x * v.x + v.y * v.y + v.z * v.z + v.w * v.w;
    __shared__ float red[8];
    #pragma unroll
    for (int o = 16; o > 0; o >>= 1) s += __shfl_xor_sync(0xffffffffu, s, o);
    if ((threadIdx.x & 31) == 0) red[threadIdx.x >> 5] = s;
    __syncthreads();
    float t = 0.f;
    #pragma unroll
    for (int i = 0; i < 8; i++) t += red[i];
    float rs = rsqrtf(t * (1.0f / (float)Dq) + 1e-6f);
    float4 lw = ((const float4*)lnw)[threadIdx.x];
    float4 o4 = { f2tff(v.x * rs * lw.x), f2tff(v.y * rs * lw.y),
                  f2tff(v.z * rs * lw.z), f2tff(v.w * rs * lw.w) };
    ((float4*)(xn + (size_t)row * Dq))[threadIdx.x] = o4;
}

// ---------------------------------------------------------------------------
// Kernel 2: tf32 GEMM (inputs pre-rounded), 3-stage cp.async. (unchanged)
// ---------------------------------------------------------------------------
#define GA_ST    36
#define GB_ST    136
#define GA_WORDS (128 * GA_ST)
#define GB_WORDS (32 * GB_ST)
#define GB_BASE  (3 * GA_WORDS)
#define GEMM_SMEM_BYTES ((3 * GA_WORDS + 3 * GB_WORDS) * 4)  // 107520
#define NKT (Dq / 32)

template<bool RES, bool ROUND>
__global__ __launch_bounds__(256, 2) void gemm_tc2(
    const float* __restrict__ A, const float* __restrict__ W,
    float* __restrict__ C, const float* __restrict__ res)
{
    extern __shared__ uint32_t smu[];
    uint32_t smb = (uint32_t)__cvta_generic_to_shared(smu);

    const int col0 = blockIdx.x << 7;
    const int row0 = blockIdx.y << 7;

    const int tid = threadIdx.x;
    const int wid = tid >> 5, lane = tid & 31;
    const int lq = lane >> 2, lr = lane & 3;
    const int warpM = (wid & 1) * 64;
    const int warpN = (wid >> 1) * 32;

    const int ar = tid >> 3, ac = (tid & 7) << 2;
    const int br = tid >> 5, bc = (tid & 31) << 2;

    auto copyTile = [&](int t, int st) {
        int k0 = t * 32;
        #pragma unroll
        for (int u = 0; u < 4; u++) {
            int r = ar + u * 32;
            cp16(smb + (st * GA_WORDS + r * GA_ST + ac) * 4,
                 A + (size_t)(row0 + r) * Dq + k0 + ac);
        }
        #pragma unroll
        for (int u = 0; u < 4; u++) {
            int r = br + u * 8;
            cp16(smb + (GB_BASE + st * GB_WORDS + r * GB_ST + bc) * 4,
                 W + (size_t)(k0 + r) * Dq + col0 + bc);
        }
        cp_commit();
    };

    float acc[4][4][4] = {};

    copyTile(0, 0);
    copyTile(1, 1);

    #pragma unroll 1
    for (int t = 0; t < NKT; t++) {
        int stage = t % 3;
        if (t + 1 < NKT) cp_wait1(); else cp_wait0();
        __syncthreads();
        if (t + 2 < NKT) copyTile(t + 2, (t + 2) % 3);

        const uint32_t* As = smu + stage * GA_WORDS;
        const uint32_t* Bs = smu + GB_BASE + stage * GB_WORDS;

        #pragma unroll
        for (int ks = 0; ks < 4; ks++) {
            uint32_t a[4][4], b[4][2];
            #pragma unroll
            for (int mt = 0; mt < 4; mt++) {
                int rb = warpM + mt * 16 + lq;
                int cb = ks * 8 + lr;
                a[mt][0] = As[rb * GA_ST + cb];
                a[mt][1] = As[(rb + 8) * GA_ST + cb];
                a[mt][2] = As[rb * GA_ST + cb + 4];
                a[mt][3] = As[(rb + 8) * GA_ST + cb + 4];
            }
            #pragma unroll
            for (int nt = 0; nt < 4; nt++) {
                int nb = warpN + nt * 8 + lq;
                b[nt][0] = Bs[(ks * 8 + lr) * GB_ST + nb];
                b[nt][1] = Bs[(ks * 8 + lr + 4) * GB_ST + nb];
            }
            #pragma unroll
            for (int mt = 0; mt < 4; mt++)
                #pragma unroll
                for (int nt = 0; nt < 4; nt++)
                    mma8(acc[mt][nt], a[mt], b[nt]);
        }
    }

    #pragma unroll
    for (int mt = 0; mt < 4; mt++)
        #pragma unroll
        for (int nt = 0; nt < 4; nt++) {
            int row = row0 + warpM + mt * 16 + lq;
            int col = col0 + warpN + nt * 8 + lr * 2;
            float2 v0 = { acc[mt][nt][0], acc[mt][nt][1] };
            float2 v1 = { acc[mt][nt][2], acc[mt][nt][3] };
            if (ROUND) {
                v0.x = f2tff(v0.x); v0.y = f2tff(v0.y);
                v1.x = f2tff(v1.x); v1.y = f2tff(v1.y);
            }
            if (RES) {
                float2 r0 = *(const float2*)&res[(size_t)row * Dq + col];
                float2 r1 = *(const float2*)&res[(size_t)(row + 8) * Dq + col];
                v0.x += r0.x; v0.y += r0.y; v1.x += r1.x; v1.y += r1.y;
            }
            *(float2*)&C[(size_t)row * Dq + col] = v0;
            *(float2*)&C[(size_t)(row + 8) * Dq + col] = v1;
        }
}

// ---------------------------------------------------------------------------
// Kernel 3: flash attention — 64-query CTAs, 128 threads, 3 CTAs/SM.
// NEW vs R9: ldmatrix.x4 for Q/K/P fragments (V stays scalar LDS; its layout
// orientation would need a transposed, conflict-prone store).
// ---------------------------------------------------------------------------
#define QS_OFF 0
#define KS_OFF 4352
#define VS_OFF 8704
#define PS_OFF 13312
#define QS(r, c) sm[QS_OFF + (r) * 68 + (c)]
#define KS(r, c) sm[KS_OFF + (r) * 68 + (c)]
#define VS(r, c) sm[VS_OFF + (r) * 72 + (c)]
#define PS(r, c) sm[PS_OFF + (r) * 68 + (c)]
#define FLASH_SMEM_WORDS 17664

__global__ __launch_bounds__(128, 3) void flash_tc(const float* __restrict__ rel_emb)
{
    extern __shared__ uint32_t sm[];
    __shared__ float bias_tab[32];

    const int tid = threadIdx.x;
    const int wid = tid >> 5, lane = tid & 31;
    const int lq = lane >> 2, lr = lane & 3;
    const int warpRow = wid * 16;

    const int q0 = blockIdx.x << 6;
    const int bh = blockIdx.y;
    const int b = bh >> 4, h = bh & 15;
    const size_t base = ((size_t)b * Sq) * Dq + (size_t)h * HDq;

    const uint32_t smb = (uint32_t)__cvta_generic_to_shared(sm);

    // ldmatrix per-lane addresses.
    // A-pattern (Q, P): mat0 rows 0-7 col+0 | mat1 rows 8-15 col+0
    //                   mat2 rows 0-7 col+4 | mat3 rows 8-15 col+4
    const int arow = warpRow + ((lane >> 3) & 1) * 8 + (lane & 7);
    const int acol = (lane >> 4) << 2;
    const uint32_t qaddr0 = smb + (QS_OFF + arow * 68 + acol) * 4;
    const uint32_t paddr0 = smb + (PS_OFF + arow * 68 + acol) * 4;
    // B-pattern (K): mat0 nt rows 0-7 col+0 | mat1 nt rows 0-7 col+4
    //                mat2 (nt+1) rows col+0 | mat3 (nt+1) rows col+4
    const int krow = ((lane >> 4) << 3) + (lane & 7);
    const int kcol = ((lane >> 3) & 1) << 2;
    const uint32_t kaddr0 = smb + (KS_OFF + krow * 68 + kcol) * 4;

    if (tid < 32) bias_tab[tid] = rel_emb[tid * Hq + h];

    // load Q tile (64 x 64, raw tf32 bits)
    #pragma unroll
    for (int u = 0; u < 8; u++) {
        int lin = tid + u * 128;
        int r = lin >> 4, c4 = (lin & 15) << 2;
        *(uint4*)&QS(r, c4) =
            *(const uint4*)&g_q[base + (size_t)(q0 + r) * Dq + c4];
    }
    __syncthreads();   // bias_tab + Q visible

    const float NEG_INF = __int_as_float(0xff800000u);
    float mA = NEG_INF, mB = NEG_INF, lA = 0.f, lB = 0.f;
    float o[8][4] = {};
    const int rowA = q0 + warpRow + lq;
    const float b31 = bias_tab[31];
    const float b0  = bias_tab[0];

    for (int k0 = 0; k0 < Sq; k0 += 64) {
        __syncthreads();
        #pragma unroll
        for (int u = 0; u < 8; u++) {
            int lin = tid + u * 128;
            int r = lin >> 4, c4 = (lin & 15) << 2;
            *(uint4*)&KS(r, c4) =
                *(const uint4*)&g_k[base + (size_t)(k0 + r) * Dq + c4];
            *(uint4*)&VS(r, c4) =
                *(const uint4*)&g_v[base + (size_t)(k0 + r) * Dq + c4];
        }
        __syncthreads();

        // S = Q K^T  (Q A-frags + K B-frags via ldmatrix)
        float s[8][4] = {};
        uint32_t aq[8][4];
        #pragma unroll
        for (int ks = 0; ks < 8; ks++)
            ldsm4(aq[ks][0], aq[ks][1], aq[ks][2], aq[ks][3], qaddr0 + ks * 32);
        #pragma unroll
        for (int ntp = 0; ntp < 4; ntp++) {
            #pragma unroll
            for (int ks = 0; ks < 8; ks++) {
                uint32_t kb[4];
                ldsm4(kb[0], kb[1], kb[2], kb[3],
                      kaddr0 + ntp * (16 * 68 * 4) + ks * 32);
                mma8(s[2 * ntp],     aq[ks], kb);      // b0,b1 = kb[0],kb[1]
                mma8(s[2 * ntp + 1], aq[ks], kb + 2);  // b0,b1 = kb[2],kb[3]
            }
        }

        // + relative position bias (fast path when bucket constant over tile)
        if (rowA - (k0 + 63) >= 128) {
            #pragma unroll
            for (int nt = 0; nt < 8; nt++) {
                s[nt][0] += b31; s[nt][1] += b31;
                s[nt][2] += b31; s[nt][3] += b31;
            }
        } else if (k0 > rowA + 8) {
            #pragma unroll
            for (int nt = 0; nt < 8; nt++) {
                s[nt][0] += b0; s[nt][1] += b0;
                s[nt][2] += b0; s[nt][3] += b0;
            }
        } else {
            #pragma unroll
            for (int nt = 0; nt < 8; nt++) {
                int kc = k0 + nt * 8 + lr * 2;
                s[nt][0] += bias_tab[rp_bucket(rowA - kc)];
                s[nt][1] += bias_tab[rp_bucket(rowA - kc - 1)];
                s[nt][2] += bias_tab[rp_bucket(rowA + 8 - kc)];
                s[nt][3] += bias_tab[rp_bucket(rowA + 8 - kc - 1)];
            }
        }

        // online softmax
        float mxA = NEG_INF, mxB = NEG_INF;
        #pragma unroll
        for (int nt = 0; nt < 8; nt++) {
            mxA = fmaxf(mxA, fmaxf(s[nt][0], s[nt][1]));
            mxB = fmaxf(mxB, fmaxf(s[nt][2], s[nt][3]));
        }
        mxA = fmaxf(mxA, __shfl_xor_sync(0xffffffffu, mxA, 1));
        mxA = fmaxf(mxA, __shfl_xor_sync(0xffffffffu, mxA, 2));
        mxB = fmaxf(mxB, __shfl_xor_sync(0xffffffffu, mxB, 1));
        mxB = fmaxf(mxB, __shfl_xor_sync(0xffffffffu, mxB, 2));
        float nmA = fmaxf(mA, mxA), nmB = fmaxf(mB, mxB);
        float alA = __expf(mA - nmA), alB = __expf(mB - nmB);
        float sumA = 0.f, sumB = 0.f;
        #pragma unroll
        for (int nt = 0; nt < 8; nt++) {
            s[nt][0] = __expf(s[nt][0] - nmA); sumA += s[nt][0];
            s[nt][1] = __expf(s[nt][1] - nmA); sumA += s[nt][1];
            s[nt][2] = __expf(s[nt][2] - nmB); sumB += s[nt][2];
            s[nt][3] = __expf(s[nt][3] - nmB); sumB += s[nt][3];
        }
        sumA += __shfl_xor_sync(0xffffffffu, sumA, 1);
        sumA += __shfl_xor_sync(0xffffffffu, sumA, 2);
        sumB += __shfl_xor_sync(0xffffffffu, sumB, 1);
        sumB += __shfl_xor_sync(0xffffffffu, sumB, 2);
        lA = lA * alA + sumA; mA = nmA;
        lB = lB * alB + sumB; mB = nmB;
        #pragma unroll
        for (int nt = 0; nt < 8; nt++) {
            o[nt][0] *= alA; o[nt][1] *= alA;
            o[nt][2] *= alB; o[nt][3] *= alB;
        }

        // stage P (tf32) in warp-private smem
        #pragma unroll
        for (int nt = 0; nt < 8; nt++) {
            int c = nt * 8 + lr * 2;
            PS(warpRow + lq, c)         = f2tf(s[nt][0]);
            PS(warpRow + lq, c + 1)     = f2tf(s[nt][1]);
            PS(warpRow + 8 + lq, c)     = f2tf(s[nt][2]);
            PS(warpRow + 8 + lq, c + 1) = f2tf(s[nt][3]);
        }
        __syncwarp();

        // O += P V  (P A-frags via ldmatrix, V scalar)
        #pragma unroll
        for (int ks = 0; ks < 8; ks++) {
            uint32_t ap[4];
            ldsm4(ap[0], ap[1], ap[2], ap[3], paddr0 + ks * 32);
            #pragma unroll
            for (int nt = 0; nt < 8; nt++) {
                uint32_t bb[2];
                bb[0] = VS(ks * 8 + lr, nt * 8 + lq);
                bb[1] = VS(ks * 8 + lr + 4, nt * 8 + lq);
                mma8(o[nt], ap, bb);
            }
        }
    }

    float invA = 1.0f / lA, invB = 1.0f / lB;
    #pragma unroll
    for (int nt = 0; nt < 8; nt++) {
        int col = nt * 8 + lr * 2;
        float2 vA = { f2tff(o[nt][0] * invA), f2tff(o[nt][1] * invA) };
        float2 vB = { f2tff(o[nt][2] * invB), f2tff(o[nt][3] * invB) };
        *(float2*)&g_ctx[base + (size_t)rowA * Dq + col] = vA;
        *(float2*)&g_ctx[base + (size_t)(rowA + 8) * Dq + col] = vB;
    }
}

// ---------------------------------------------------------------------------
// Launch
// ---------------------------------------------------------------------------
extern "C" void kernel_launch(void* const* d_in, const int* in_sizes, int n_in,
                              void* d_out, int out_size)
{
    const float* input = (const float*)d_in[0];
    const float* wq    = (const float*)d_in[2];
    const float* wk    = (const float*)d_in[3];
    const float* wv    = (const float*)d_in[4];
    const float* wo    = (const float*)d_in[5];
    const float* rel   = (const float*)d_in[6];
    const float* lnw   = (const float*)d_in[7];
    float* out         = (float*)d_out;

    static const int FLASH_SMEM = FLASH_SMEM_WORDS * 4;   // 70656
    cudaFuncSetAttribute(flash_tc,
                         cudaFuncAttributeMaxDynamicSharedMemorySize, FLASH_SMEM);
    cudaFuncSetAttribute(gemm_tc2<false, true>,
                         cudaFuncAttributeMaxDynamicSharedMemorySize, GEMM_SMEM_BYTES);
    cudaFuncSetAttribute(gemm_tc2<true, false>,
                         cudaFuncAttributeMaxDynamicSharedMemorySize, GEMM_SMEM_BYTES);

    float *g_xn_p, *g_q_p, *g_k_p, *g_v_p, *g_ctx_p, *g_wt_p;
    cudaGetSymbolAddress((void**)&g_xn_p, g_xn);
    cudaGetSymbolAddress((void**)&g_q_p,  g_q);
    cudaGetSymbolAddress((void**)&g_k_p,  g_k);
    cudaGetSymbolAddress((void**)&g_v_p,  g_v);
    cudaGetSymbolAddress((void**)&g_ctx_p, g_ctx);
    cudaGetSymbolAddress((void**)&g_wt_p, g_wt);

    dim3 gw(Dq * Dq / 1024, 4);
    cvtw_kernel<<<gw, 256>>>(wq, wk, wv, wo);

    norm_kernel<<<Mq, 256>>>(input, lnw, g_xn_p);

    const float* wq_t = g_wt_p;
    const float* wk_t = g_wt_p + (size_t)Dq * Dq;
    const float* wv_t = g_wt_p + 2 * (size_t)Dq * Dq;
    const float* wo_t = g_wt_p + 3 * (size_t)Dq * Dq;

    dim3 gg(Dq / 128, Mq / 128);
    gemm_tc2<false, true><<<gg, 256, GEMM_SMEM_BYTES>>>(g_xn_p, wq_t, g_q_p, nullptr);
    gemm_tc2<false, true><<<gg, 256, GEMM_SMEM_BYTES>>>(g_xn_p, wk_t, g_k_p, nullptr);
    gemm_tc2<false, true><<<gg, 256, GEMM_SMEM_BYTES>>>(g_xn_p, wv_t, g_v_p, nullptr);

    dim3 gf(Sq / 64, Bq * Hq);
    flash_tc<<<gf, 128, FLASH_SMEM>>>(rel);

    gemm_tc2<true, false><<<gg, 256, GEMM_SMEM_BYTES>>>(g_ctx_p, wo_t, out, input);
}

// round 11
// speedup vs baseline: 2.3548x; 1.8860x over previous
#include <cuda_runtime.h>
#include <cuda_fp16.h>
#include <cstdint>

#define Bq   4
#define Sq   2048
#define Dq   1024
#define Hq   16
#define HDq  64
#define Mq   (Bq*Sq)

__device__ __half g_xn[(size_t)Mq*Dq];
__device__ __half g_q[(size_t)Mq*Dq];
__device__ __half g_k[(size_t)Mq*Dq];
__device__ __half g_v[(size_t)Mq*Dq];
__device__ __half g_ctx[(size_t)Mq*Dq];
__device__ __half g_wt[4][(size_t)Dq*Dq];   // fp16-rounded weights

// ---------------------------------------------------------------------------
// helpers
// ---------------------------------------------------------------------------
__device__ __forceinline__ void mma16(float* c, const uint32_t* a, const uint32_t* b) {
    asm volatile(
        "mma.sync.aligned.m16n8k16.row.col.f32.f16.f16.f32 "
        "{%0,%1,%2,%3},{%4,%5,%6,%7},{%8,%9},{%0,%1,%2,%3};"
        : "+f"(c[0]), "+f"(c[1]), "+f"(c[2]), "+f"(c[3])
        : "r"(a[0]), "r"(a[1]), "r"(a[2]), "r"(a[3]), "r"(b[0]), "r"(b[1]));
}

__device__ __forceinline__ void ldsm4(uint32_t& r0, uint32_t& r1,
                                      uint32_t& r2, uint32_t& r3, uint32_t addr) {
    asm volatile("ldmatrix.sync.aligned.m8n8.x4.shared.b16 {%0,%1,%2,%3}, [%4];"
                 : "=r"(r0), "=r"(r1), "=r"(r2), "=r"(r3) : "r"(addr));
}
__device__ __forceinline__ void ldsm4t(uint32_t& r0, uint32_t& r1,
                                       uint32_t& r2, uint32_t& r3, uint32_t addr) {
    asm volatile("ldmatrix.sync.aligned.m8n8.x4.trans.shared.b16 {%0,%1,%2,%3}, [%4];"
                 : "=r"(r0), "=r"(r1), "=r"(r2), "=r"(r3) : "r"(addr));
}

__device__ __forceinline__ void cp16(uint32_t dst, const void* src) {
    asm volatile("cp.async.cg.shared.global [%0], [%1], 16;"
                 :: "r"(dst), "l"(src));
}
__device__ __forceinline__ void cp_commit() { asm volatile("cp.async.commit_group;"); }
__device__ __forceinline__ void cp_wait1()  { asm volatile("cp.async.wait_group 1;"); }
__device__ __forceinline__ void cp_wait0()  { asm volatile("cp.async.wait_group 0;"); }

__device__ __forceinline__ int rp_bucket(int rp) {
    if (rp < 0) rp = 0;
    if (rp < 16) return rp;
    int bk = 16 + (int)(__logf((float)rp * 0.0625f) * 7.6944086f);
    return bk > 31 ? 31 : bk;
}

__device__ __forceinline__ __half2 pack2(float a, float b) {
    __half2 h;
    h.x = __float2half_rn(a);
    h.y = __float2half_rn(b);
    return h;
}

// ---------------------------------------------------------------------------
// Kernel 0: round weights to fp16
// ---------------------------------------------------------------------------
__global__ __launch_bounds__(256) void cvtw_kernel(
    const float* __restrict__ w0, const float* __restrict__ w1,
    const float* __restrict__ w2, const float* __restrict__ w3)
{
    const float* w = (blockIdx.y == 0) ? w0 : (blockIdx.y == 1) ? w1
                   : (blockIdx.y == 2) ? w2 : w3;
    __half* o = g_wt[blockIdx.y];
    size_t i = ((size_t)blockIdx.x * 256 + threadIdx.x) * 4;
    float4 v = *(const float4*)&w[i];
    __half2* o2 = (__half2*)(o + i);
    o2[0] = pack2(v.x, v.y);
    o2[1] = pack2(v.z, v.w);
}

// ---------------------------------------------------------------------------
// Kernel 1: RMS norm, fp16 output
// ---------------------------------------------------------------------------
__global__ __launch_bounds__(256) void norm_kernel(
    const float* __restrict__ x, const float* __restrict__ lnw,
    __half* __restrict__ xn)
{
    int row = blockIdx.x;
    const float4* xr = (const float4*)(x + (size_t)row * Dq);
    float4 v = xr[threadIdx.x];
    float s = v.x * v.x + v.y * v.y + v.z * v.z + v.w * v.w;
    __shared__ float red[8];
    #pragma unroll
    for (int o = 16; o > 0; o >>= 1) s += __shfl_xor_sync(0xffffffffu, s, o);
    if ((threadIdx.x & 31) == 0) red[threadIdx.x >> 5] = s;
    __syncthreads();
    float t = 0.f;
    #pragma unroll
    for (int i = 0; i < 8; i++) t += red[i];
    float rs = rsqrtf(t * (1.0f / (float)Dq) + 1e-6f);
    float4 lw = ((const float4*)lnw)[threadIdx.x];
    __half2* o2 = (__half2*)(xn + (size_t)row * Dq + threadIdx.x * 4);
    o2[0] = pack2(v.x * rs * lw.x, v.y * rs * lw.y);
    o2[1] = pack2(v.z * rs * lw.z, v.w * rs * lw.w);
}

// ---------------------------------------------------------------------------
// Kernel 2: fp16 GEMM (m16n8k16, fp32 accum), 3-stage cp.async.
// BM=BN=128, BK=32, 256 threads, 2 CTAs/SM, warps 2(M)x4(N).
// A tile: 128 x 32 halves, row stride 40 halves (80 B).
// B tile: 32 x 128 halves, row stride 136 halves (272 B).
// smem: 3*(10240 + 8704) = 56832 B.
// ---------------------------------------------------------------------------
#define A_STAGE_B 10240
#define B_STAGE_B 8704
#define GBB       (3 * A_STAGE_B)          // 30720
#define GEMM_SMEM_BYTES (3 * (A_STAGE_B + B_STAGE_B))
#define NKT (Dq / 32)

template<bool RES>
__global__ __launch_bounds__(256, 2) void gemm_hc(
    const __half* __restrict__ A, const __half* __restrict__ W,
    void* __restrict__ Cv, const float* __restrict__ res)
{
    extern __shared__ char smc[];
    const uint32_t smb = (uint32_t)__cvta_generic_to_shared(smc);

    const int col0 = blockIdx.x << 7;
    const int row0 = blockIdx.y << 7;

    const int tid = threadIdx.x;
    const int wid = tid >> 5, lane = tid & 31;
    const int lq = lane >> 2, lr = lane & 3;
    const int warpM = (wid & 1) * 64;
    const int warpN = (wid >> 1) * 32;

    // copy indices: A 512 chunks (row = lin>>2, chunk col = (lin&3)*8 halves)
    //               B 512 chunks (row = lin>>4, chunk col = (lin&15)*8 halves)
    auto copyTile = [&](int t, int st) {
        int k0 = t * 32;
        #pragma unroll
        for (int u = 0; u < 2; u++) {
            int lin = tid + u * 256;
            int r = lin >> 2, c8 = (lin & 3) * 8;
            cp16(smb + st * A_STAGE_B + r * 80 + c8 * 2,
                 A + (size_t)(row0 + r) * Dq + k0 + c8);
        }
        #pragma unroll
        for (int u = 0; u < 2; u++) {
            int lin = tid + u * 256;
            int r = lin >> 4, c8 = (lin & 15) * 8;
            cp16(smb + GBB + st * B_STAGE_B + r * 272 + c8 * 2,
                 W + (size_t)(k0 + r) * Dq + col0 + c8);
        }
        cp_commit();
    };

    // ldmatrix lane addresses (byte offsets within a stage)
    // A (non-trans x4): row = warpM+mt*16 + (lane&7) + ((lane>>3)&1)*8,
    //                   colh = (lane>>4)*8 + ks*16
    const int a_row = (lane & 7) + ((lane >> 3) & 1) * 8;
    const int a_colh = (lane >> 4) * 8;
    // B (.trans x4): row(k) = ks*16 + ((lane>>3)&1)*8 + (lane&7),
    //                colh(n) = warpN + p*16 + ((lane>>4)&1)*8
    const int b_rowk = ((lane >> 3) & 1) * 8 + (lane & 7);
    const int b_colh = ((lane >> 4) & 1) * 8;

    float acc[4][4][4] = {};

    copyTile(0, 0);
    copyTile(1, 1);

    #pragma unroll 1
    for (int t = 0; t < NKT; t++) {
        int stage = t % 3;
        if (t + 1 < NKT) cp_wait1(); else cp_wait0();
        __syncthreads();
        if (t + 2 < NKT) copyTile(t + 2, (t + 2) % 3);

        const uint32_t aBase = smb + stage * A_STAGE_B;
        const uint32_t bBase = smb + GBB + stage * B_STAGE_B;

        #pragma unroll
        for (int ks = 0; ks < 2; ks++) {
            uint32_t a[4][4];
            #pragma unroll
            for (int mt = 0; mt < 4; mt++)
                ldsm4(a[mt][0], a[mt][1], a[mt][2], a[mt][3],
                      aBase + (warpM + mt * 16 + a_row) * 80
                            + (a_colh + ks * 16) * 2);
            #pragma unroll
            for (int p = 0; p < 2; p++) {
                uint32_t kb[4];
                ldsm4t(kb[0], kb[1], kb[2], kb[3],
                       bBase + (ks * 16 + b_rowk) * 272
                             + (warpN + p * 16 + b_colh) * 2);
                #pragma unroll
                for (int mt = 0; mt < 4; mt++) {
                    mma16(acc[mt][2 * p],     a[mt], kb);
                    mma16(acc[mt][2 * p + 1], a[mt], kb + 2);
                }
            }
        }
    }

    #pragma unroll
    for (int mt = 0; mt < 4; mt++)
        #pragma unroll
        for (int nt = 0; nt < 4; nt++) {
            int row = row0 + warpM + mt * 16 + lq;
            int col = col0 + warpN + nt * 8 + lr * 2;
            if (RES) {
                float* C = (float*)Cv;
                float2 r0 = *(const float2*)&res[(size_t)row * Dq + col];
                float2 r1 = *(const float2*)&res[(size_t)(row + 8) * Dq + col];
                float2 v0 = { acc[mt][nt][0] + r0.x, acc[mt][nt][1] + r0.y };
                float2 v1 = { acc[mt][nt][2] + r1.x, acc[mt][nt][3] + r1.y };
                *(float2*)&C[(size_t)row * Dq + col] = v0;
                *(float2*)&C[(size_t)(row + 8) * Dq + col] = v1;
            } else {
                __half* C = (__half*)Cv;
                *(__half2*)&C[(size_t)row * Dq + col] =
                    pack2(acc[mt][nt][0], acc[mt][nt][1]);
                *(__half2*)&C[(size_t)(row + 8) * Dq + col] =
                    pack2(acc[mt][nt][2], acc[mt][nt][3]);
            }
        }
}

// ---------------------------------------------------------------------------
// Kernel 3: flash attention fp16 — 64-query CTAs, 128 threads, 3 CTAs/SM.
// All tiles fp16, row stride 72 halves (144 B). All fragments via ldmatrix.
// smem: Q 9216 + K 9216 + V 9216 + P 9216 = 36864 B.
// ---------------------------------------------------------------------------
#define FQ_OFF 0
#define FK_OFF 9216
#define FV_OFF 18432
#define FP_OFF 27648
#define FLASH_SMEM_BYTES 36864

__global__ __launch_bounds__(128, 3) void flash_hc(const float* __restrict__ rel_emb)
{
    extern __shared__ char smc[];
    __shared__ float bias_tab[32];

    const int tid = threadIdx.x;
    const int wid = tid >> 5, lane = tid & 31;
    const int lq = lane >> 2, lr = lane & 3;
    const int warpRow = wid * 16;

    const int q0 = blockIdx.x << 6;
    const int bh = blockIdx.y;
    const int b = bh >> 4, h = bh & 15;
    const size_t base = ((size_t)b * Sq) * Dq + (size_t)h * HDq;

    const uint32_t smb = (uint32_t)__cvta_generic_to_shared(smc);

    // ldmatrix lane address components
    const int a_row  = (lane & 7) + ((lane >> 3) & 1) * 8;   // A pattern (Q, P)
    const int a_colh = (lane >> 4) * 8;
    const int kb_row = ((lane >> 4) & 1) * 8 + (lane & 7);   // K non-trans B
    const int kb_colh = ((lane >> 3) & 1) * 8;
    const int vb_row = ((lane >> 3) & 1) * 8 + (lane & 7);   // V trans B
    const int vb_colh = ((lane >> 4) & 1) * 8;

    const uint32_t qa0 = smb + FQ_OFF + (warpRow + a_row) * 144 + a_colh * 2;
    const uint32_t pa0 = smb + FP_OFF + (warpRow + a_row) * 144 + a_colh * 2;
    const uint32_t ka0 = smb + FK_OFF + kb_row * 144 + kb_colh * 2;
    const uint32_t va0 = smb + FV_OFF + vb_row * 144 + vb_colh * 2;

    if (tid < 32) bias_tab[tid] = rel_emb[tid * Hq + h];

    // load Q tile (64 rows x 64 halves; 512 16B-chunks, 4 per thread)
    #pragma unroll
    for (int u = 0; u < 4; u++) {
        int lin = tid + u * 128;
        int r = lin >> 3, c8 = (lin & 7) * 8;
        *(uint4*)(smc + FQ_OFF + r * 144 + c8 * 2) =
            *(const uint4*)&g_q[base + (size_t)(q0 + r) * Dq + c8];
    }
    __syncthreads();

    // hoist Q fragments? keep re-read simple: 4 ldsm per tile is cheap. Hoist:
    uint32_t aq[4][4];
    #pragma unroll
    for (int ks = 0; ks < 4; ks++)
        ldsm4(aq[ks][0], aq[ks][1], aq[ks][2], aq[ks][3], qa0 + ks * 32);

    const float NEG_INF = __int_as_float(0xff800000u);
    float mA = NEG_INF, mB = NEG_INF, lA = 0.f, lB = 0.f;
    float o[8][4] = {};
    const int rowA = q0 + warpRow + lq;
    const float b31 = bias_tab[31];
    const float b0  = bias_tab[0];

    for (int k0 = 0; k0 < Sq; k0 += 64) {
        __syncthreads();
        #pragma unroll
        for (int u = 0; u < 4; u++) {
            int lin = tid + u * 128;
            int r = lin >> 3, c8 = (lin & 7) * 8;
            *(uint4*)(smc + FK_OFF + r * 144 + c8 * 2) =
                *(const uint4*)&g_k[base + (size_t)(k0 + r) * Dq + c8];
            *(uint4*)(smc + FV_OFF + r * 144 + c8 * 2) =
                *(const uint4*)&g_v[base + (size_t)(k0 + r) * Dq + c8];
        }
        __syncthreads();

        // S = Q K^T
        float s[8][4] = {};
        #pragma unroll
        for (int p = 0; p < 4; p++) {
            #pragma unroll
            for (int ks = 0; ks < 4; ks++) {
                uint32_t kb[4];
                ldsm4(kb[0], kb[1], kb[2], kb[3],
                      ka0 + p * (16 * 144) + ks * 32);
                mma16(s[2 * p],     aq[ks], kb);
                mma16(s[2 * p + 1], aq[ks], kb + 2);
            }
        }

        // + relative position bias (constant-bucket fast paths)
        if (rowA - (k0 + 63) >= 128) {
            #pragma unroll
            for (int nt = 0; nt < 8; nt++) {
                s[nt][0] += b31; s[nt][1] += b31;
                s[nt][2] += b31; s[nt][3] += b31;
            }
        } else if (k0 > rowA + 8) {
            #pragma unroll
            for (int nt = 0; nt < 8; nt++) {
                s[nt][0] += b0; s[nt][1] += b0;
                s[nt][2] += b0; s[nt][3] += b0;
            }
        } else {
            #pragma unroll
            for (int nt = 0; nt < 8; nt++) {
                int kc = k0 + nt * 8 + lr * 2;
                s[nt][0] += bias_tab[rp_bucket(rowA - kc)];
                s[nt][1] += bias_tab[rp_bucket(rowA - kc - 1)];
                s[nt][2] += bias_tab[rp_bucket(rowA + 8 - kc)];
                s[nt][3] += bias_tab[rp_bucket(rowA + 8 - kc - 1)];
            }
        }

        // online softmax
        float mxA = NEG_INF, mxB = NEG_INF;
        #pragma unroll
        for (int nt = 0; nt < 8; nt++) {
            mxA = fmaxf(mxA, fmaxf(s[nt][0], s[nt][1]));
            mxB = fmaxf(mxB, fmaxf(s[nt][2], s[nt][3]));
        }
        mxA = fmaxf(mxA, __shfl_xor_sync(0xffffffffu, mxA, 1));
        mxA = fmaxf(mxA, __shfl_xor_sync(0xffffffffu, mxA, 2));
        mxB = fmaxf(mxB, __shfl_xor_sync(0xffffffffu, mxB, 1));
        mxB = fmaxf(mxB, __shfl_xor_sync(0xffffffffu, mxB, 2));
        float nmA = fmaxf(mA, mxA), nmB = fmaxf(mB, mxB);
        float alA = __expf(mA - nmA), alB = __expf(mB - nmB);
        float sumA = 0.f, sumB = 0.f;
        #pragma unroll
        for (int nt = 0; nt < 8; nt++) {
            s[nt][0] = __expf(s[nt][0] - nmA); sumA += s[nt][0];
            s[nt][1] = __expf(s[nt][1] - nmA); sumA += s[nt][1];
            s[nt][2] = __expf(s[nt][2] - nmB); sumB += s[nt][2];
            s[nt][3] = __expf(s[nt][3] - nmB); sumB += s[nt][3];
        }
        sumA += __shfl_xor_sync(0xffffffffu, sumA, 1);
        sumA += __shfl_xor_sync(0xffffffffu, sumA, 2);
        sumB += __shfl_xor_sync(0xffffffffu, sumB, 1);
        sumB += __shfl_xor_sync(0xffffffffu, sumB, 2);
        lA = lA * alA + sumA; mA = nmA;
        lB = lB * alB + sumB; mB = nmB;
        #pragma unroll
        for (int nt = 0; nt < 8; nt++) {
            o[nt][0] *= alA; o[nt][1] *= alA;
            o[nt][2] *= alB; o[nt][3] *= alB;
        }

        // stage P (fp16) in warp-private smem: half2 per (nt,row-half)
        #pragma unroll
        for (int nt = 0; nt < 8; nt++) {
            int cb = (nt * 8 + lr * 2) * 2;   // byte col
            *(__half2*)(smc + FP_OFF + (warpRow + lq) * 144 + cb) =
                pack2(s[nt][0], s[nt][1]);
            *(__half2*)(smc + FP_OFF + (warpRow + 8 + lq) * 144 + cb) =
                pack2(s[nt][2], s[nt][3]);
        }
        __syncwarp();

        // O += P V
        #pragma unroll
        for (int ks = 0; ks < 4; ks++) {
            uint32_t ap[4];
            ldsm4(ap[0], ap[1], ap[2], ap[3], pa0 + ks * 32);
            #pragma unroll
            for (int p = 0; p < 4; p++) {
                uint32_t vb[4];
                ldsm4t(vb[0], vb[1], vb[2], vb[3],
                       va0 + ks * (16 * 144) + p * 32);
                mma16(o[2 * p],     ap, vb);
                mma16(o[2 * p + 1], ap, vb + 2);
            }
        }
    }

    float invA = 1.0f / lA, invB = 1.0f / lB;
    #pragma unroll
    for (int nt = 0; nt < 8; nt++) {
        int col = nt * 8 + lr * 2;
        *(__half2*)&g_ctx[base + (size_t)rowA * Dq + col] =
            pack2(o[nt][0] * invA, o[nt][1] * invA);
        *(__half2*)&g_ctx[base + (size_t)(rowA + 8) * Dq + col] =
            pack2(o[nt][2] * invB, o[nt][3] * invB);
    }
}

// ---------------------------------------------------------------------------
// Launch
// ---------------------------------------------------------------------------
extern "C" void kernel_launch(void* const* d_in, const int* in_sizes, int n_in,
                              void* d_out, int out_size)
{
    const float* input = (const float*)d_in[0];
    const float* wq    = (const float*)d_in[2];
    const float* wk    = (const float*)d_in[3];
    const float* wv    = (const float*)d_in[4];
    const float* wo    = (const float*)d_in[5];
    const float* rel   = (const float*)d_in[6];
    const float* lnw   = (const float*)d_in[7];
    float* out         = (float*)d_out;

    cudaFuncSetAttribute(flash_hc,
                         cudaFuncAttributeMaxDynamicSharedMemorySize, FLASH_SMEM_BYTES);
    cudaFuncSetAttribute(gemm_hc<false>,
                         cudaFuncAttributeMaxDynamicSharedMemorySize, GEMM_SMEM_BYTES);
    cudaFuncSetAttribute(gemm_hc<true>,
                         cudaFuncAttributeMaxDynamicSharedMemorySize, GEMM_SMEM_BYTES);

    __half *g_xn_p, *g_q_p, *g_k_p, *g_v_p, *g_ctx_p, *g_wt_p;
    cudaGetSymbolAddress((void**)&g_xn_p, g_xn);
    cudaGetSymbolAddress((void**)&g_q_p,  g_q);
    cudaGetSymbolAddress((void**)&g_k_p,  g_k);
    cudaGetSymbolAddress((void**)&g_v_p,  g_v);
    cudaGetSymbolAddress((void**)&g_ctx_p, g_ctx);
    cudaGetSymbolAddress((void**)&g_wt_p, g_wt);

    dim3 gw(Dq * Dq / 1024, 4);
    cvtw_kernel<<<gw, 256>>>(wq, wk, wv, wo);

    norm_kernel<<<Mq, 256>>>(input, lnw, g_xn_p);

    const __half* wq_t = g_wt_p;
    const __half* wk_t = g_wt_p + (size_t)Dq * Dq;
    const __half* wv_t = g_wt_p + 2 * (size_t)Dq * Dq;
    const __half* wo_t = g_wt_p + 3 * (size_t)Dq * Dq;

    dim3 gg(Dq / 128, Mq / 128);
    gemm_hc<false><<<gg, 256, GEMM_SMEM_BYTES>>>(g_xn_p, wq_t, g_q_p, nullptr);
    gemm_hc<false><<<gg, 256, GEMM_SMEM_BYTES>>>(g_xn_p, wk_t, g_k_p, nullptr);
    gemm_hc<false><<<gg, 256, GEMM_SMEM_BYTES>>>(g_xn_p, wv_t, g_v_p, nullptr);

    dim3 gf(Sq / 64, Bq * Hq);
    flash_hc<<<gf, 128, FLASH_SMEM_BYTES>>>(rel);

    gemm_hc<true><<<gg, 256, GEMM_SMEM_BYTES>>>(g_ctx_p, wo_t, out, input);
}

// round 12
// speedup vs baseline: 2.4355x; 1.0343x over previous
#include <cuda_runtime.h>
#include <cuda_fp16.h>
#include <cstdint>

#define Bq   4
#define Sq   2048
#define Dq   1024
#define Hq   16
#define HDq  64
#define Mq   (Bq*Sq)

__device__ __half g_xn[(size_t)Mq*Dq];
__device__ __half g_q[(size_t)Mq*Dq];
__device__ __half g_k[(size_t)Mq*Dq];
__device__ __half g_v[(size_t)Mq*Dq];
__device__ __half g_ctx[(size_t)Mq*Dq];
__device__ __half g_wt[4][(size_t)Dq*Dq];   // fp16-rounded weights

// ---------------------------------------------------------------------------
// helpers
// ---------------------------------------------------------------------------
__device__ __forceinline__ void mma16(float* c, const uint32_t* a, const uint32_t* b) {
    asm volatile(
        "mma.sync.aligned.m16n8k16.row.col.f32.f16.f16.f32 "
        "{%0,%1,%2,%3},{%4,%5,%6,%7},{%8,%9},{%0,%1,%2,%3};"
        : "+f"(c[0]), "+f"(c[1]), "+f"(c[2]), "+f"(c[3])
        : "r"(a[0]), "r"(a[1]), "r"(a[2]), "r"(a[3]), "r"(b[0]), "r"(b[1]));
}

__device__ __forceinline__ void ldsm4(uint32_t& r0, uint32_t& r1,
                                      uint32_t& r2, uint32_t& r3, uint32_t addr) {
    asm volatile("ldmatrix.sync.aligned.m8n8.x4.shared.b16 {%0,%1,%2,%3}, [%4];"
                 : "=r"(r0), "=r"(r1), "=r"(r2), "=r"(r3) : "r"(addr));
}
__device__ __forceinline__ void ldsm4t(uint32_t& r0, uint32_t& r1,
                                       uint32_t& r2, uint32_t& r3, uint32_t addr) {
    asm volatile("ldmatrix.sync.aligned.m8n8.x4.trans.shared.b16 {%0,%1,%2,%3}, [%4];"
                 : "=r"(r0), "=r"(r1), "=r"(r2), "=r"(r3) : "r"(addr));
}

__device__ __forceinline__ void cp16(uint32_t dst, const void* src) {
    asm volatile("cp.async.cg.shared.global [%0], [%1], 16;"
                 :: "r"(dst), "l"(src));
}
__device__ __forceinline__ void cp_commit() { asm volatile("cp.async.commit_group;"); }
__device__ __forceinline__ void cp_wait2()  { asm volatile("cp.async.wait_group 2;"); }
__device__ __forceinline__ void cp_wait1()  { asm volatile("cp.async.wait_group 1;"); }
__device__ __forceinline__ void cp_wait0()  { asm volatile("cp.async.wait_group 0;"); }

__device__ __forceinline__ int rp_bucket(int rp) {
    if (rp < 0) rp = 0;
    if (rp < 16) return rp;
    int bk = 16 + (int)(__logf((float)rp * 0.0625f) * 7.6944086f);
    return bk > 31 ? 31 : bk;
}

__device__ __forceinline__ __half2 pack2(float a, float b) {
    __half2 h;
    h.x = __float2half_rn(a);
    h.y = __float2half_rn(b);
    return h;
}

// ---------------------------------------------------------------------------
// Kernel 0: round weights to fp16
// ---------------------------------------------------------------------------
__global__ __launch_bounds__(256) void cvtw_kernel(
    const float* __restrict__ w0, const float* __restrict__ w1,
    const float* __restrict__ w2, const float* __restrict__ w3)
{
    const float* w = (blockIdx.y == 0) ? w0 : (blockIdx.y == 1) ? w1
                   : (blockIdx.y == 2) ? w2 : w3;
    __half* o = g_wt[blockIdx.y];
    size_t i = ((size_t)blockIdx.x * 256 + threadIdx.x) * 4;
    float4 v = *(const float4*)&w[i];
    __half2* o2 = (__half2*)(o + i);
    o2[0] = pack2(v.x, v.y);
    o2[1] = pack2(v.z, v.w);
}

// ---------------------------------------------------------------------------
// Kernel 1: RMS norm, fp16 output
// ---------------------------------------------------------------------------
__global__ __launch_bounds__(256) void norm_kernel(
    const float* __restrict__ x, const float* __restrict__ lnw,
    __half* __restrict__ xn)
{
    int row = blockIdx.x;
    const float4* xr = (const float4*)(x + (size_t)row * Dq);
    float4 v = xr[threadIdx.x];
    float s = v.x * v.x + v.y * v.y + v.z * v.z + v.w * v.w;
    __shared__ float red[8];
    #pragma unroll
    for (int o = 16; o > 0; o >>= 1) s += __shfl_xor_sync(0xffffffffu, s, o);
    if ((threadIdx.x & 31) == 0) red[threadIdx.x >> 5] = s;
    __syncthreads();
    float t = 0.f;
    #pragma unroll
    for (int i = 0; i < 8; i++) t += red[i];
    float rs = rsqrtf(t * (1.0f / (float)Dq) + 1e-6f);
    float4 lw = ((const float4*)lnw)[threadIdx.x];
    __half2* o2 = (__half2*)(xn + (size_t)row * Dq + threadIdx.x * 4);
    o2[0] = pack2(v.x * rs * lw.x, v.y * rs * lw.y);
    o2[1] = pack2(v.z * rs * lw.z, v.w * rs * lw.w);
}

// ---------------------------------------------------------------------------
// Kernel 2: fp16 GEMM (m16n8k16, fp32 accum), 4-stage cp.async pipeline.
// BM=BN=128, BK=32, 256 threads, 2 CTAs/SM.
// A tile: 128 x 32 halves, stride 80 B. B tile: 32 x 128, stride 272 B.
// smem: 4*(10240 + 8704) = 75776 B.
// ---------------------------------------------------------------------------
#define A_STAGE_B 10240
#define B_STAGE_B 8704
#define GBB       (4 * A_STAGE_B)          // 40960
#define GEMM_SMEM_BYTES (4 * (A_STAGE_B + B_STAGE_B))
#define NKT (Dq / 32)

template<bool RES>
__global__ __launch_bounds__(256, 2) void gemm_hc(
    const __half* __restrict__ A, const __half* __restrict__ W,
    void* __restrict__ Cv, const float* __restrict__ res)
{
    extern __shared__ char smc[];
    const uint32_t smb = (uint32_t)__cvta_generic_to_shared(smc);

    const int col0 = blockIdx.x << 7;
    const int row0 = blockIdx.y << 7;

    const int tid = threadIdx.x;
    const int wid = tid >> 5, lane = tid & 31;
    const int lq = lane >> 2, lr = lane & 3;
    const int warpM = (wid & 1) * 64;
    const int warpN = (wid >> 1) * 32;

    auto copyTile = [&](int t, int st) {
        int k0 = t * 32;
        #pragma unroll
        for (int u = 0; u < 2; u++) {
            int lin = tid + u * 256;
            int r = lin >> 2, c8 = (lin & 3) * 8;
            cp16(smb + st * A_STAGE_B + r * 80 + c8 * 2,
                 A + (size_t)(row0 + r) * Dq + k0 + c8);
        }
        #pragma unroll
        for (int u = 0; u < 2; u++) {
            int lin = tid + u * 256;
            int r = lin >> 4, c8 = (lin & 15) * 8;
            cp16(smb + GBB + st * B_STAGE_B + r * 272 + c8 * 2,
                 W + (size_t)(k0 + r) * Dq + col0 + c8);
        }
        cp_commit();
    };

    const int a_row = (lane & 7) + ((lane >> 3) & 1) * 8;
    const int a_colh = (lane >> 4) * 8;
    const int b_rowk = ((lane >> 3) & 1) * 8 + (lane & 7);
    const int b_colh = ((lane >> 4) & 1) * 8;

    float acc[4][4][4] = {};

    copyTile(0, 0);
    copyTile(1, 1);
    copyTile(2, 2);

    #pragma unroll 1
    for (int t = 0; t < NKT; t++) {
        int stage = t & 3;
        if (t + 2 < NKT) cp_wait2();
        else if (t + 1 < NKT) cp_wait1();
        else cp_wait0();
        __syncthreads();
        if (t + 3 < NKT) copyTile(t + 3, (t + 3) & 3);

        const uint32_t aBase = smb + stage * A_STAGE_B;
        const uint32_t bBase = smb + GBB + stage * B_STAGE_B;

        #pragma unroll
        for (int ks = 0; ks < 2; ks++) {
            uint32_t a[4][4];
            #pragma unroll
            for (int mt = 0; mt < 4; mt++)
                ldsm4(a[mt][0], a[mt][1], a[mt][2], a[mt][3],
                      aBase + (warpM + mt * 16 + a_row) * 80
                            + (a_colh + ks * 16) * 2);
            #pragma unroll
            for (int p = 0; p < 2; p++) {
                uint32_t kb[4];
                ldsm4t(kb[0], kb[1], kb[2], kb[3],
                       bBase + (ks * 16 + b_rowk) * 272
                             + (warpN + p * 16 + b_colh) * 2);
                #pragma unroll
                for (int mt = 0; mt < 4; mt++) {
                    mma16(acc[mt][2 * p],     a[mt], kb);
                    mma16(acc[mt][2 * p + 1], a[mt], kb + 2);
                }
            }
        }
    }

    #pragma unroll
    for (int mt = 0; mt < 4; mt++)
        #pragma unroll
        for (int nt = 0; nt < 4; nt++) {
            int row = row0 + warpM + mt * 16 + lq;
            int col = col0 + warpN + nt * 8 + lr * 2;
            if (RES) {
                float* C = (float*)Cv;
                float2 r0 = *(const float2*)&res[(size_t)row * Dq + col];
                float2 r1 = *(const float2*)&res[(size_t)(row + 8) * Dq + col];
                float2 v0 = { acc[mt][nt][0] + r0.x, acc[mt][nt][1] + r0.y };
                float2 v1 = { acc[mt][nt][2] + r1.x, acc[mt][nt][3] + r1.y };
                *(float2*)&C[(size_t)row * Dq + col] = v0;
                *(float2*)&C[(size_t)(row + 8) * Dq + col] = v1;
            } else {
                __half* C = (__half*)Cv;
                *(__half2*)&C[(size_t)row * Dq + col] =
                    pack2(acc[mt][nt][0], acc[mt][nt][1]);
                *(__half2*)&C[(size_t)(row + 8) * Dq + col] =
                    pack2(acc[mt][nt][2], acc[mt][nt][3]);
            }
        }
}

// ---------------------------------------------------------------------------
// Kernel 3: flash attention fp16 — 64-query CTAs, 128 threads, 3 CTAs/SM,
// cp.async 2-stage double-buffered K/V.
// smem: Q 9216 + K 2x9216 + V 2x9216 + P 9216 = 55296 B.
// ---------------------------------------------------------------------------
#define FQ_OFF 0
#define FK_OFF 9216
#define FV_OFF 27648
#define FP_OFF 46080
#define FLASH_SMEM_BYTES 55296
#define NFT (Sq / 64)

__global__ __launch_bounds__(128, 3) void flash_hc(const float* __restrict__ rel_emb)
{
    extern __shared__ char smc[];
    __shared__ float bias_tab[32];

    const int tid = threadIdx.x;
    const int wid = tid >> 5, lane = tid & 31;
    const int lq = lane >> 2, lr = lane & 3;
    const int warpRow = wid * 16;

    const int q0 = blockIdx.x << 6;
    const int bh = blockIdx.y;
    const int b = bh >> 4, h = bh & 15;
    const size_t base = ((size_t)b * Sq) * Dq + (size_t)h * HDq;

    const uint32_t smb = (uint32_t)__cvta_generic_to_shared(smc);

    const int a_row  = (lane & 7) + ((lane >> 3) & 1) * 8;   // A pattern (Q, P)
    const int a_colh = (lane >> 4) * 8;
    const int kb_row = ((lane >> 4) & 1) * 8 + (lane & 7);   // K non-trans B
    const int kb_colh = ((lane >> 3) & 1) * 8;
    const int vb_row = ((lane >> 3) & 1) * 8 + (lane & 7);   // V trans B
    const int vb_colh = ((lane >> 4) & 1) * 8;

    const uint32_t qa0 = smb + FQ_OFF + (warpRow + a_row) * 144 + a_colh * 2;
    const uint32_t pa0 = smb + FP_OFF + (warpRow + a_row) * 144 + a_colh * 2;

    if (tid < 32) bias_tab[tid] = rel_emb[tid * Hq + h];

    // K/V tile copy via cp.async (one commit group per tile)
    auto copyKV = [&](int t, int st) {
        int k0 = t * 64;
        #pragma unroll
        for (int u = 0; u < 4; u++) {
            int lin = tid + u * 128;
            int r = lin >> 3, c8 = (lin & 7) * 8;
            cp16(smb + FK_OFF + st * 9216 + r * 144 + c8 * 2,
                 &g_k[base + (size_t)(k0 + r) * Dq + c8]);
            cp16(smb + FV_OFF + st * 9216 + r * 144 + c8 * 2,
                 &g_v[base + (size_t)(k0 + r) * Dq + c8]);
        }
        cp_commit();
    };

    copyKV(0, 0);
    copyKV(1, 1);

    // load Q tile (plain loads, overlaps with cp.async)
    #pragma unroll
    for (int u = 0; u < 4; u++) {
        int lin = tid + u * 128;
        int r = lin >> 3, c8 = (lin & 7) * 8;
        *(uint4*)(smc + FQ_OFF + r * 144 + c8 * 2) =
            *(const uint4*)&g_q[base + (size_t)(q0 + r) * Dq + c8];
    }
    __syncthreads();

    uint32_t aq[4][4];
    #pragma unroll
    for (int ks = 0; ks < 4; ks++)
        ldsm4(aq[ks][0], aq[ks][1], aq[ks][2], aq[ks][3], qa0 + ks * 32);

    const float NEG_INF = __int_as_float(0xff800000u);
    float mA = NEG_INF, mB = NEG_INF, lA = 0.f, lB = 0.f;
    float o[8][4] = {};
    const int rowA = q0 + warpRow + lq;
    const float b31 = bias_tab[31];
    const float b0  = bias_tab[0];

    #pragma unroll 1
    for (int t = 0; t < NFT; t++) {
        const int st = t & 1;
        const int k0 = t * 64;
        if (t + 1 < NFT) cp_wait1(); else cp_wait0();
        __syncthreads();

        const uint32_t ka0 = smb + FK_OFF + st * 9216 + kb_row * 144 + kb_colh * 2;
        const uint32_t va0 = smb + FV_OFF + st * 9216 + vb_row * 144 + vb_colh * 2;

        // S = Q K^T
        float s[8][4] = {};
        #pragma unroll
        for (int p = 0; p < 4; p++) {
            #pragma unroll
            for (int ks = 0; ks < 4; ks++) {
                uint32_t kb[4];
                ldsm4(kb[0], kb[1], kb[2], kb[3],
                      ka0 + p * (16 * 144) + ks * 32);
                mma16(s[2 * p],     aq[ks], kb);
                mma16(s[2 * p + 1], aq[ks], kb + 2);
            }
        }

        // + relative position bias (constant-bucket fast paths)
        if (rowA - (k0 + 63) >= 128) {
            #pragma unroll
            for (int nt = 0; nt < 8; nt++) {
                s[nt][0] += b31; s[nt][1] += b31;
                s[nt][2] += b31; s[nt][3] += b31;
            }
        } else if (k0 > rowA + 8) {
            #pragma unroll
            for (int nt = 0; nt < 8; nt++) {
                s[nt][0] += b0; s[nt][1] += b0;
                s[nt][2] += b0; s[nt][3] += b0;
            }
        } else {
            #pragma unroll
            for (int nt = 0; nt < 8; nt++) {
                int kc = k0 + nt * 8 + lr * 2;
                s[nt][0] += bias_tab[rp_bucket(rowA - kc)];
                s[nt][1] += bias_tab[rp_bucket(rowA - kc - 1)];
                s[nt][2] += bias_tab[rp_bucket(rowA + 8 - kc)];
                s[nt][3] += bias_tab[rp_bucket(rowA + 8 - kc - 1)];
            }
        }

        // online softmax
        float mxA = NEG_INF, mxB = NEG_INF;
        #pragma unroll
        for (int nt = 0; nt < 8; nt++) {
            mxA = fmaxf(mxA, fmaxf(s[nt][0], s[nt][1]));
            mxB = fmaxf(mxB, fmaxf(s[nt][2], s[nt][3]));
        }
        mxA = fmaxf(mxA, __shfl_xor_sync(0xffffffffu, mxA, 1));
        mxA = fmaxf(mxA, __shfl_xor_sync(0xffffffffu, mxA, 2));
        mxB = fmaxf(mxB, __shfl_xor_sync(0xffffffffu, mxB, 1));
        mxB = fmaxf(mxB, __shfl_xor_sync(0xffffffffu, mxB, 2));
        float nmA = fmaxf(mA, mxA), nmB = fmaxf(mB, mxB);
        float alA = __expf(mA - nmA), alB = __expf(mB - nmB);
        float sumA = 0.f, sumB = 0.f;
        #pragma unroll
        for (int nt = 0; nt < 8; nt++) {
            s[nt][0] = __expf(s[nt][0] - nmA); sumA += s[nt][0];
            s[nt][1] = __expf(s[nt][1] - nmA); sumA += s[nt][1];
            s[nt][2] = __expf(s[nt][2] - nmB); sumB += s[nt][2];
            s[nt][3] = __expf(s[nt][3] - nmB); sumB += s[nt][3];
        }
        sumA += __shfl_xor_sync(0xffffffffu, sumA, 1);
        sumA += __shfl_xor_sync(0xffffffffu, sumA, 2);
        sumB += __shfl_xor_sync(0xffffffffu, sumB, 1);
        sumB += __shfl_xor_sync(0xffffffffu, sumB, 2);
        lA = lA * alA + sumA; mA = nmA;
        lB = lB * alB + sumB; mB = nmB;
        #pragma unroll
        for (int nt = 0; nt < 8; nt++) {
            o[nt][0] *= alA; o[nt][1] *= alA;
            o[nt][2] *= alB; o[nt][3] *= alB;
        }

        // stage P (fp16) in warp-private smem
        #pragma unroll
        for (int nt = 0; nt < 8; nt++) {
            int cb = (nt * 8 + lr * 2) * 2;
            *(__half2*)(smc + FP_OFF + (warpRow + lq) * 144 + cb) =
                pack2(s[nt][0], s[nt][1]);
            *(__half2*)(smc + FP_OFF + (warpRow + 8 + lq) * 144 + cb) =
                pack2(s[nt][2], s[nt][3]);
        }
        __syncwarp();

        // O += P V
        #pragma unroll
        for (int ks = 0; ks < 4; ks++) {
            uint32_t ap[4];
            ldsm4(ap[0], ap[1], ap[2], ap[3], pa0 + ks * 32);
            #pragma unroll
            for (int p = 0; p < 4; p++) {
                uint32_t vb[4];
                ldsm4t(vb[0], vb[1], vb[2], vb[3],
                       va0 + ks * (16 * 144) + p * 32);
                mma16(o[2 * p],     ap, vb);
                mma16(o[2 * p + 1], ap, vb + 2);
            }
        }

        __syncthreads();   // stage st fully consumed before refill
        if (t + 2 < NFT) copyKV(t + 2, st);
    }

    float invA = 1.0f / lA, invB = 1.0f / lB;
    #pragma unroll
    for (int nt = 0; nt < 8; nt++) {
        int col = nt * 8 + lr * 2;
        *(__half2*)&g_ctx[base + (size_t)rowA * Dq + col] =
            pack2(o[nt][0] * invA, o[nt][1] * invA);
        *(__half2*)&g_ctx[base + (size_t)(rowA + 8) * Dq + col] =
            pack2(o[nt][2] * invB, o[nt][3] * invB);
    }
}

// ---------------------------------------------------------------------------
// Launch
// ---------------------------------------------------------------------------
extern "C" void kernel_launch(void* const* d_in, const int* in_sizes, int n_in,
                              void* d_out, int out_size)
{
    const float* input = (const float*)d_in[0];
    const float* wq    = (const float*)d_in[2];
    const float* wk    = (const float*)d_in[3];
    const float* wv    = (const float*)d_in[4];
    const float* wo    = (const float*)d_in[5];
    const float* rel   = (const float*)d_in[6];
    const float* lnw   = (const float*)d_in[7];
    float* out         = (float*)d_out;

    cudaFuncSetAttribute(flash_hc,
                         cudaFuncAttributeMaxDynamicSharedMemorySize, FLASH_SMEM_BYTES);
    cudaFuncSetAttribute(gemm_hc<false>,
                         cudaFuncAttributeMaxDynamicSharedMemorySize, GEMM_SMEM_BYTES);
    cudaFuncSetAttribute(gemm_hc<true>,
                         cudaFuncAttributeMaxDynamicSharedMemorySize, GEMM_SMEM_BYTES);

    __half *g_xn_p, *g_q_p, *g_k_p, *g_v_p, *g_ctx_p, *g_wt_p;
    cudaGetSymbolAddress((void**)&g_xn_p, g_xn);
    cudaGetSymbolAddress((void**)&g_q_p,  g_q);
    cudaGetSymbolAddress((void**)&g_k_p,  g_k);
    cudaGetSymbolAddress((void**)&g_v_p,  g_v);
    cudaGetSymbolAddress((void**)&g_ctx_p, g_ctx);
    cudaGetSymbolAddress((void**)&g_wt_p, g_wt);

    dim3 gw(Dq * Dq / 1024, 4);
    cvtw_kernel<<<gw, 256>>>(wq, wk, wv, wo);

    norm_kernel<<<Mq, 256>>>(input, lnw, g_xn_p);

    const __half* wq_t = g_wt_p;
    const __half* wk_t = g_wt_p + (size_t)Dq * Dq;
    const __half* wv_t = g_wt_p + 2 * (size_t)Dq * Dq;
    const __half* wo_t = g_wt_p + 3 * (size_t)Dq * Dq;

    dim3 gg(Dq / 128, Mq / 128);
    gemm_hc<false><<<gg, 256, GEMM_SMEM_BYTES>>>(g_xn_p, wq_t, g_q_p, nullptr);
    gemm_hc<false><<<gg, 256, GEMM_SMEM_BYTES>>>(g_xn_p, wk_t, g_k_p, nullptr);
    gemm_hc<false><<<gg, 256, GEMM_SMEM_BYTES>>>(g_xn_p, wv_t, g_v_p, nullptr);

    dim3 gf(Sq / 64, Bq * Hq);
    flash_hc<<<gf, 128, FLASH_SMEM_BYTES>>>(rel);

    gemm_hc<true><<<gg, 256, GEMM_SMEM_BYTES>>>(g_ctx_p, wo_t, out, input);
}

// round 13
// speedup vs baseline: 2.5182x; 1.0339x over previous
#include <cuda_runtime.h>
#include <cuda_fp16.h>
#include <cstdint>

#define Bq   4
#define Sq   2048
#define Dq   1024
#define Hq   16
#define HDq  64
#define Mq   (Bq*Sq)

__device__ __half g_xn[(size_t)Mq*Dq];
__device__ __half g_q[(size_t)Mq*Dq];
__device__ __half g_k[(size_t)Mq*Dq];
__device__ __half g_v[(size_t)Mq*Dq];
__device__ __half g_ctx[(size_t)Mq*Dq];
__device__ __half g_wt[4][(size_t)Dq*Dq];   // fp16-rounded weights

// ---------------------------------------------------------------------------
// helpers
// ---------------------------------------------------------------------------
__device__ __forceinline__ void mma16(float* c, const uint32_t* a, const uint32_t* b) {
    asm volatile(
        "mma.sync.aligned.m16n8k16.row.col.f32.f16.f16.f32 "
        "{%0,%1,%2,%3},{%4,%5,%6,%7},{%8,%9},{%0,%1,%2,%3};"
        : "+f"(c[0]), "+f"(c[1]), "+f"(c[2]), "+f"(c[3])
        : "r"(a[0]), "r"(a[1]), "r"(a[2]), "r"(a[3]), "r"(b[0]), "r"(b[1]));
}

__device__ __forceinline__ void ldsm4(uint32_t& r0, uint32_t& r1,
                                      uint32_t& r2, uint32_t& r3, uint32_t addr) {
    asm volatile("ldmatrix.sync.aligned.m8n8.x4.shared.b16 {%0,%1,%2,%3}, [%4];"
                 : "=r"(r0), "=r"(r1), "=r"(r2), "=r"(r3) : "r"(addr));
}
__device__ __forceinline__ void ldsm4t(uint32_t& r0, uint32_t& r1,
                                       uint32_t& r2, uint32_t& r3, uint32_t addr) {
    asm volatile("ldmatrix.sync.aligned.m8n8.x4.trans.shared.b16 {%0,%1,%2,%3}, [%4];"
                 : "=r"(r0), "=r"(r1), "=r"(r2), "=r"(r3) : "r"(addr));
}

__device__ __forceinline__ void cp16(uint32_t dst, const void* src) {
    asm volatile("cp.async.cg.shared.global [%0], [%1], 16;"
                 :: "r"(dst), "l"(src));
}
__device__ __forceinline__ void cp_commit() { asm volatile("cp.async.commit_group;"); }
__device__ __forceinline__ void cp_wait1()  { asm volatile("cp.async.wait_group 1;"); }
__device__ __forceinline__ void cp_wait0()  { asm volatile("cp.async.wait_group 0;"); }

__device__ __forceinline__ int rp_bucket(int rp) {
    if (rp < 0) rp = 0;
    if (rp < 16) return rp;
    int bk = 16 + (int)(__logf((float)rp * 0.0625f) * 7.6944086f);
    return bk > 31 ? 31 : bk;
}

__device__ __forceinline__ __half2 pack2(float a, float b) {
    __half2 h;
    h.x = __float2half_rn(a);
    h.y = __float2half_rn(b);
    return h;
}

// ---------------------------------------------------------------------------
// Kernel 0: round weights to fp16
// ---------------------------------------------------------------------------
__global__ __launch_bounds__(256) void cvtw_kernel(
    const float* __restrict__ w0, const float* __restrict__ w1,
    const float* __restrict__ w2, const float* __restrict__ w3)
{
    const float* w = (blockIdx.y == 0) ? w0 : (blockIdx.y == 1) ? w1
                   : (blockIdx.y == 2) ? w2 : w3;
    __half* o = g_wt[blockIdx.y];
    size_t i = ((size_t)blockIdx.x * 256 + threadIdx.x) * 4;
    float4 v = *(const float4*)&w[i];
    __half2* o2 = (__half2*)(o + i);
    o2[0] = pack2(v.x, v.y);
    o2[1] = pack2(v.z, v.w);
}

// ---------------------------------------------------------------------------
// Kernel 1: RMS norm, fp16 output
// ---------------------------------------------------------------------------
__global__ __launch_bounds__(256) void norm_kernel(
    const float* __restrict__ x, const float* __restrict__ lnw,
    __half* __restrict__ xn)
{
    int row = blockIdx.x;
    const float4* xr = (const float4*)(x + (size_t)row * Dq);
    float4 v = xr[threadIdx.x];
    float s = v.x * v.x + v.y * v.y + v.z * v.z + v.w * v.w;
    __shared__ float red[8];
    #pragma unroll
    for (int o = 16; o > 0; o >>= 1) s += __shfl_xor_sync(0xffffffffu, s, o);
    if ((threadIdx.x & 31) == 0) red[threadIdx.x >> 5] = s;
    __syncthreads();
    float t = 0.f;
    #pragma unroll
    for (int i = 0; i < 8; i++) t += red[i];
    float rs = rsqrtf(t * (1.0f / (float)Dq) + 1e-6f);
    float4 lw = ((const float4*)lnw)[threadIdx.x];
    __half2* o2 = (__half2*)(xn + (size_t)row * Dq + threadIdx.x * 4);
    o2[0] = pack2(v.x * rs * lw.x, v.y * rs * lw.y);
    o2[1] = pack2(v.z * rs * lw.z, v.w * rs * lw.w);
}

// ---------------------------------------------------------------------------
// Kernel 2: fp16 GEMM (m16n8k16, fp32 accum), 3-stage cp.async (R11-exact).
// BM=BN=128, BK=32, 256 threads, 2 CTAs/SM.
// smem: 3*(10240 + 8704) = 56832 B.
// ---------------------------------------------------------------------------
#define A_STAGE_B 10240
#define B_STAGE_B 8704
#define GBB       (3 * A_STAGE_B)          // 30720
#define GEMM_SMEM_BYTES (3 * (A_STAGE_B + B_STAGE_B))
#define NKT (Dq / 32)

template<bool RES>
__global__ __launch_bounds__(256, 2) void gemm_hc(
    const __half* __restrict__ A, const __half* __restrict__ W,
    void* __restrict__ Cv, const float* __restrict__ res)
{
    extern __shared__ char smc[];
    const uint32_t smb = (uint32_t)__cvta_generic_to_shared(smc);

    const int col0 = blockIdx.x << 7;
    const int row0 = blockIdx.y << 7;

    const int tid = threadIdx.x;
    const int wid = tid >> 5, lane = tid & 31;
    const int lq = lane >> 2, lr = lane & 3;
    const int warpM = (wid & 1) * 64;
    const int warpN = (wid >> 1) * 32;

    auto copyTile = [&](int t, int st) {
        int k0 = t * 32;
        #pragma unroll
        for (int u = 0; u < 2; u++) {
            int lin = tid + u * 256;
            int r = lin >> 2, c8 = (lin & 3) * 8;
            cp16(smb + st * A_STAGE_B + r * 80 + c8 * 2,
                 A + (size_t)(row0 + r) * Dq + k0 + c8);
        }
        #pragma unroll
        for (int u = 0; u < 2; u++) {
            int lin = tid + u * 256;
            int r = lin >> 4, c8 = (lin & 15) * 8;
            cp16(smb + GBB + st * B_STAGE_B + r * 272 + c8 * 2,
                 W + (size_t)(k0 + r) * Dq + col0 + c8);
        }
        cp_commit();
    };

    const int a_row = (lane & 7) + ((lane >> 3) & 1) * 8;
    const int a_colh = (lane >> 4) * 8;
    const int b_rowk = ((lane >> 3) & 1) * 8 + (lane & 7);
    const int b_colh = ((lane >> 4) & 1) * 8;

    float acc[4][4][4] = {};

    copyTile(0, 0);
    copyTile(1, 1);

    #pragma unroll 1
    for (int t = 0; t < NKT; t++) {
        int stage = t % 3;
        if (t + 1 < NKT) cp_wait1(); else cp_wait0();
        __syncthreads();
        if (t + 2 < NKT) copyTile(t + 2, (t + 2) % 3);

        const uint32_t aBase = smb + stage * A_STAGE_B;
        const uint32_t bBase = smb + GBB + stage * B_STAGE_B;

        #pragma unroll
        for (int ks = 0; ks < 2; ks++) {
            uint32_t a[4][4];
            #pragma unroll
            for (int mt = 0; mt < 4; mt++)
                ldsm4(a[mt][0], a[mt][1], a[mt][2], a[mt][3],
                      aBase + (warpM + mt * 16 + a_row) * 80
                            + (a_colh + ks * 16) * 2);
            #pragma unroll
            for (int p = 0; p < 2; p++) {
                uint32_t kb[4];
                ldsm4t(kb[0], kb[1], kb[2], kb[3],
                       bBase + (ks * 16 + b_rowk) * 272
                             + (warpN + p * 16 + b_colh) * 2);
                #pragma unroll
                for (int mt = 0; mt < 4; mt++) {
                    mma16(acc[mt][2 * p],     a[mt], kb);
                    mma16(acc[mt][2 * p + 1], a[mt], kb + 2);
                }
            }
        }
    }

    #pragma unroll
    for (int mt = 0; mt < 4; mt++)
        #pragma unroll
        for (int nt = 0; nt < 4; nt++) {
            int row = row0 + warpM + mt * 16 + lq;
            int col = col0 + warpN + nt * 8 + lr * 2;
            if (RES) {
                float* C = (float*)Cv;
                float2 r0 = *(const float2*)&res[(size_t)row * Dq + col];
                float2 r1 = *(const float2*)&res[(size_t)(row + 8) * Dq + col];
                float2 v0 = { acc[mt][nt][0] + r0.x, acc[mt][nt][1] + r0.y };
                float2 v1 = { acc[mt][nt][2] + r1.x, acc[mt][nt][3] + r1.y };
                *(float2*)&C[(size_t)row * Dq + col] = v0;
                *(float2*)&C[(size_t)(row + 8) * Dq + col] = v1;
            } else {
                __half* C = (__half*)Cv;
                *(__half2*)&C[(size_t)row * Dq + col] =
                    pack2(acc[mt][nt][0], acc[mt][nt][1]);
                *(__half2*)&C[(size_t)(row + 8) * Dq + col] =
                    pack2(acc[mt][nt][2], acc[mt][nt][3]);
            }
        }
}

// ---------------------------------------------------------------------------
// Kernel 3: flash attention fp16 — 64-query CTAs, 128 threads, 3 CTAs/SM,
// 3-stage cp.async K/V pipeline with ONE __syncthreads per tile.
// smem: Q 9216 + K 3x9216 + V 3x9216 + P 9216 = 73728 B (x3 CTAs = 221184).
// ---------------------------------------------------------------------------
#define FQ_OFF 0
#define FK_OFF 9216
#define FV_OFF (9216 + 3 * 9216)            // 36864
#define FP_OFF (9216 + 6 * 9216)            // 64512
#define FLASH_SMEM_BYTES 73728
#define NFT (Sq / 64)

__global__ __launch_bounds__(128, 3) void flash_hc(const float* __restrict__ rel_emb)
{
    extern __shared__ char smc[];
    __shared__ float bias_tab[32];

    const int tid = threadIdx.x;
    const int wid = tid >> 5, lane = tid & 31;
    const int lq = lane >> 2, lr = lane & 3;
    const int warpRow = wid * 16;

    const int q0 = blockIdx.x << 6;
    const int bh = blockIdx.y;
    const int b = bh >> 4, h = bh & 15;
    const size_t base = ((size_t)b * Sq) * Dq + (size_t)h * HDq;

    const uint32_t smb = (uint32_t)__cvta_generic_to_shared(smc);

    const int a_row  = (lane & 7) + ((lane >> 3) & 1) * 8;   // A pattern (Q, P)
    const int a_colh = (lane >> 4) * 8;
    const int kb_row = ((lane >> 4) & 1) * 8 + (lane & 7);   // K non-trans B
    const int kb_colh = ((lane >> 3) & 1) * 8;
    const int vb_row = ((lane >> 3) & 1) * 8 + (lane & 7);   // V trans B
    const int vb_colh = ((lane >> 4) & 1) * 8;

    const uint32_t qa0 = smb + FQ_OFF + (warpRow + a_row) * 144 + a_colh * 2;
    const uint32_t pa0 = smb + FP_OFF + (warpRow + a_row) * 144 + a_colh * 2;

    if (tid < 32) bias_tab[tid] = rel_emb[tid * Hq + h];

    auto copyKV = [&](int t, int st) {
        int k0 = t * 64;
        #pragma unroll
        for (int u = 0; u < 4; u++) {
            int lin = tid + u * 128;
            int r = lin >> 3, c8 = (lin & 7) * 8;
            cp16(smb + FK_OFF + st * 9216 + r * 144 + c8 * 2,
                 &g_k[base + (size_t)(k0 + r) * Dq + c8]);
            cp16(smb + FV_OFF + st * 9216 + r * 144 + c8 * 2,
                 &g_v[base + (size_t)(k0 + r) * Dq + c8]);
        }
        cp_commit();
    };

    copyKV(0, 0);
    copyKV(1, 1);

    // load Q tile (plain loads, overlaps with cp.async)
    #pragma unroll
    for (int u = 0; u < 4; u++) {
        int lin = tid + u * 128;
        int r = lin >> 3, c8 = (lin & 7) * 8;
        *(uint4*)(smc + FQ_OFF + r * 144 + c8 * 2) =
            *(const uint4*)&g_q[base + (size_t)(q0 + r) * Dq + c8];
    }
    __syncthreads();

    uint32_t aq[4][4];
    #pragma unroll
    for (int ks = 0; ks < 4; ks++)
        ldsm4(aq[ks][0], aq[ks][1], aq[ks][2], aq[ks][3], qa0 + ks * 32);

    const float NEG_INF = __int_as_float(0xff800000u);
    float mA = NEG_INF, mB = NEG_INF, lA = 0.f, lB = 0.f;
    float o[8][4] = {};
    const int rowA = q0 + warpRow + lq;
    const float b31 = bias_tab[31];
    const float b0  = bias_tab[0];

    #pragma unroll 1
    for (int t = 0; t < NFT; t++) {
        const int st = t % 3;
        const int k0 = t * 64;
        if (t + 1 < NFT) cp_wait1(); else cp_wait0();
        __syncthreads();
        // stage (t+2)%3 was consumed at iteration t-1; barrier above makes
        // that consumption globally visible -> safe to refill now.
        if (t + 2 < NFT) copyKV(t + 2, (t + 2) % 3);

        const uint32_t ka0 = smb + FK_OFF + st * 9216 + kb_row * 144 + kb_colh * 2;
        const uint32_t va0 = smb + FV_OFF + st * 9216 + vb_row * 144 + vb_colh * 2;

        // S = Q K^T
        float s[8][4] = {};
        #pragma unroll
        for (int p = 0; p < 4; p++) {
            #pragma unroll
            for (int ks = 0; ks < 4; ks++) {
                uint32_t kb[4];
                ldsm4(kb[0], kb[1], kb[2], kb[3],
                      ka0 + p * (16 * 144) + ks * 32);
                mma16(s[2 * p],     aq[ks], kb);
                mma16(s[2 * p + 1], aq[ks], kb + 2);
            }
        }

        // + relative position bias (constant-bucket fast paths)
        if (rowA - (k0 + 63) >= 128) {
            #pragma unroll
            for (int nt = 0; nt < 8; nt++) {
                s[nt][0] += b31; s[nt][1] += b31;
                s[nt][2] += b31; s[nt][3] += b31;
            }
        } else if (k0 > rowA + 8) {
            #pragma unroll
            for (int nt = 0; nt < 8; nt++) {
                s[nt][0] += b0; s[nt][1] += b0;
                s[nt][2] += b0; s[nt][3] += b0;
            }
        } else {
            #pragma unroll
            for (int nt = 0; nt < 8; nt++) {
                int kc = k0 + nt * 8 + lr * 2;
                s[nt][0] += bias_tab[rp_bucket(rowA - kc)];
                s[nt][1] += bias_tab[rp_bucket(rowA - kc - 1)];
                s[nt][2] += bias_tab[rp_bucket(rowA + 8 - kc)];
                s[nt][3] += bias_tab[rp_bucket(rowA + 8 - kc - 1)];
            }
        }

        // online softmax
        float mxA = NEG_INF, mxB = NEG_INF;
        #pragma unroll
        for (int nt = 0; nt < 8; nt++) {
            mxA = fmaxf(mxA, fmaxf(s[nt][0], s[nt][1]));
            mxB = fmaxf(mxB, fmaxf(s[nt][2], s[nt][3]));
        }
        mxA = fmaxf(mxA, __shfl_xor_sync(0xffffffffu, mxA, 1));
        mxA = fmaxf(mxA, __shfl_xor_sync(0xffffffffu, mxA, 2));
        mxB = fmaxf(mxB, __shfl_xor_sync(0xffffffffu, mxB, 1));
        mxB = fmaxf(mxB, __shfl_xor_sync(0xffffffffu, mxB, 2));
        float nmA = fmaxf(mA, mxA), nmB = fmaxf(mB, mxB);
        float alA = __expf(mA - nmA), alB = __expf(mB - nmB);
        float sumA = 0.f, sumB = 0.f;
        #pragma unroll
        for (int nt = 0; nt < 8; nt++) {
            s[nt][0] = __expf(s[nt][0] - nmA); sumA += s[nt][0];
            s[nt][1] = __expf(s[nt][1] - nmA); sumA += s[nt][1];
            s[nt][2] = __expf(s[nt][2] - nmB); sumB += s[nt][2];
            s[nt][3] = __expf(s[nt][3] - nmB); sumB += s[nt][3];
        }
        sumA += __shfl_xor_sync(0xffffffffu, sumA, 1);
        sumA += __shfl_xor_sync(0xffffffffu, sumA, 2);
        sumB += __shfl_xor_sync(0xffffffffu, sumB, 1);
        sumB += __shfl_xor_sync(0xffffffffu, sumB, 2);
        lA = lA * alA + sumA; mA = nmA;
        lB = lB * alB + sumB; mB = nmB;
        #pragma unroll
        for (int nt = 0; nt < 8; nt++) {
            o[nt][0] *= alA; o[nt][1] *= alA;
            o[nt][2] *= alB; o[nt][3] *= alB;
        }

        // stage P (fp16) in warp-private smem
        #pragma unroll
        for (int nt = 0; nt < 8; nt++) {
            int cb = (nt * 8 + lr * 2) * 2;
            *(__half2*)(smc + FP_OFF + (warpRow + lq) * 144 + cb) =
                pack2(s[nt][0], s[nt][1]);
            *(__half2*)(smc + FP_OFF + (warpRow + 8 + lq) * 144 + cb) =
                pack2(s[nt][2], s[nt][3]);
        }
        __syncwarp();

        // O += P V
        #pragma unroll
        for (int ks = 0; ks < 4; ks++) {
            uint32_t ap[4];
            ldsm4(ap[0], ap[1], ap[2], ap[3], pa0 + ks * 32);
            #pragma unroll
            for (int p = 0; p < 4; p++) {
                uint32_t vb[4];
                ldsm4t(vb[0], vb[1], vb[2], vb[3],
                       va0 + ks * (16 * 144) + p * 32);
                mma16(o[2 * p],     ap, vb);
                mma16(o[2 * p + 1], ap, vb + 2);
            }
        }
    }

    float invA = 1.0f / lA, invB = 1.0f / lB;
    #pragma unroll
    for (int nt = 0; nt < 8; nt++) {
        int col = nt * 8 + lr * 2;
        *(__half2*)&g_ctx[base + (size_t)rowA * Dq + col] =
            pack2(o[nt][0] * invA, o[nt][1] * invA);
        *(__half2*)&g_ctx[base + (size_t)(rowA + 8) * Dq + col] =
            pack2(o[nt][2] * invB, o[nt][3] * invB);
    }
}

// ---------------------------------------------------------------------------
// Launch
// ---------------------------------------------------------------------------
extern "C" void kernel_launch(void* const* d_in, const int* in_sizes, int n_in,
                              void* d_out, int out_size)
{
    const float* input = (const float*)d_in[0];
    const float* wq    = (const float*)d_in[2];
    const float* wk    = (const float*)d_in[3];
    const float* wv    = (const float*)d_in[4];
    const float* wo    = (const float*)d_in[5];
    const float* rel   = (const float*)d_in[6];
    const float* lnw   = (const float*)d_in[7];
    float* out         = (float*)d_out;

    cudaFuncSetAttribute(flash_hc,
                         cudaFuncAttributeMaxDynamicSharedMemorySize, FLASH_SMEM_BYTES);
    cudaFuncSetAttribute(gemm_hc<false>,
                         cudaFuncAttributeMaxDynamicSharedMemorySize, GEMM_SMEM_BYTES);
    cudaFuncSetAttribute(gemm_hc<true>,
                         cudaFuncAttributeMaxDynamicSharedMemorySize, GEMM_SMEM_BYTES);

    __half *g_xn_p, *g_q_p, *g_k_p, *g_v_p, *g_ctx_p, *g_wt_p;
    cudaGetSymbolAddress((void**)&g_xn_p, g_xn);
    cudaGetSymbolAddress((void**)&g_q_p,  g_q);
    cudaGetSymbolAddress((void**)&g_k_p,  g_k);
    cudaGetSymbolAddress((void**)&g_v_p,  g_v);
    cudaGetSymbolAddress((void**)&g_ctx_p, g_ctx);
    cudaGetSymbolAddress((void**)&g_wt_p, g_wt);

    dim3 gw(Dq * Dq / 1024, 4);
    cvtw_kernel<<<gw, 256>>>(wq, wk, wv, wo);

    norm_kernel<<<Mq, 256>>>(input, lnw, g_xn_p);

    const __half* wq_t = g_wt_p;
    const __half* wk_t = g_wt_p + (size_t)Dq * Dq;
    const __half* wv_t = g_wt_p + 2 * (size_t)Dq * Dq;
    const __half* wo_t = g_wt_p + 3 * (size_t)Dq * Dq;

    dim3 gg(Dq / 128, Mq / 128);
    gemm_hc<false><<<gg, 256, GEMM_SMEM_BYTES>>>(g_xn_p, wq_t, g_q_p, nullptr);
    gemm_hc<false><<<gg, 256, GEMM_SMEM_BYTES>>>(g_xn_p, wk_t, g_k_p, nullptr);
    gemm_hc<false><<<gg, 256, GEMM_SMEM_BYTES>>>(g_xn_p, wv_t, g_v_p, nullptr);

    dim3 gf(Sq / 64, Bq * Hq);
    flash_hc<<<gf, 128, FLASH_SMEM_BYTES>>>(rel);

    gemm_hc<true><<<gg, 256, GEMM_SMEM_BYTES>>>(g_ctx_p, wo_t, out, input);
}

// round 14
// speedup vs baseline: 2.5795x; 1.0243x over previous
#include <cuda_runtime.h>
#include <cuda_fp16.h>
#include <cstdint>
#include <cstring>

#define Bq   4
#define Sq   2048
#define Dq   1024
#define Hq   16
#define HDq  64
#define Mq   (Bq*Sq)

__device__ __half g_xn[(size_t)Mq*Dq];
__device__ __half g_q[(size_t)Mq*Dq];
__device__ __half g_k[(size_t)Mq*Dq];
__device__ __half g_v[(size_t)Mq*Dq];
__device__ __half g_ctx[(size_t)Mq*Dq];
__device__ __half g_wt[4][(size_t)Dq*Dq];   // fp16-rounded weights

// ---------------------------------------------------------------------------
// helpers
// ---------------------------------------------------------------------------
__device__ __forceinline__ void mma16(float* c, const uint32_t* a, const uint32_t* b) {
    asm volatile(
        "mma.sync.aligned.m16n8k16.row.col.f32.f16.f16.f32 "
        "{%0,%1,%2,%3},{%4,%5,%6,%7},{%8,%9},{%0,%1,%2,%3};"
        : "+f"(c[0]), "+f"(c[1]), "+f"(c[2]), "+f"(c[3])
        : "r"(a[0]), "r"(a[1]), "r"(a[2]), "r"(a[3]), "r"(b[0]), "r"(b[1]));
}

__device__ __forceinline__ void ldsm4(uint32_t& r0, uint32_t& r1,
                                      uint32_t& r2, uint32_t& r3, uint32_t addr) {
    asm volatile("ldmatrix.sync.aligned.m8n8.x4.shared.b16 {%0,%1,%2,%3}, [%4];"
                 : "=r"(r0), "=r"(r1), "=r"(r2), "=r"(r3) : "r"(addr));
}
__device__ __forceinline__ void ldsm4t(uint32_t& r0, uint32_t& r1,
                                       uint32_t& r2, uint32_t& r3, uint32_t addr) {
    asm volatile("ldmatrix.sync.aligned.m8n8.x4.trans.shared.b16 {%0,%1,%2,%3}, [%4];"
                 : "=r"(r0), "=r"(r1), "=r"(r2), "=r"(r3) : "r"(addr));
}

__device__ __forceinline__ void cp16(uint32_t dst, const void* src) {
    asm volatile("cp.async.cg.shared.global [%0], [%1], 16;"
                 :: "r"(dst), "l"(src));
}
__device__ __forceinline__ void cp_commit() { asm volatile("cp.async.commit_group;"); }
__device__ __forceinline__ void cp_wait1()  { asm volatile("cp.async.wait_group 1;"); }
__device__ __forceinline__ void cp_wait0()  { asm volatile("cp.async.wait_group 0;"); }

__device__ __forceinline__ int rp_bucket(int rp) {
    if (rp < 0) rp = 0;
    if (rp < 16) return rp;
    int bk = 16 + (int)(__logf((float)rp * 0.0625f) * 7.6944086f);
    return bk > 31 ? 31 : bk;
}

__device__ __forceinline__ __half2 pack2(float a, float b) {
    __half2 h;
    h.x = __float2half_rn(a);
    h.y = __float2half_rn(b);
    return h;
}
__device__ __forceinline__ uint32_t packu(float a, float b) {
    __half2 h = pack2(a, b);
    uint32_t u;
    memcpy(&u, &h, 4);
    return u;
}

// ---------------------------------------------------------------------------
// Kernel 0: round weights to fp16
// ---------------------------------------------------------------------------
__global__ __launch_bounds__(256) void cvtw_kernel(
    const float* __restrict__ w0, const float* __restrict__ w1,
    const float* __restrict__ w2, const float* __restrict__ w3)
{
    const float* w = (blockIdx.y == 0) ? w0 : (blockIdx.y == 1) ? w1
                   : (blockIdx.y == 2) ? w2 : w3;
    __half* o = g_wt[blockIdx.y];
    size_t i = ((size_t)blockIdx.x * 256 + threadIdx.x) * 4;
    float4 v = *(const float4*)&w[i];
    __half2* o2 = (__half2*)(o + i);
    o2[0] = pack2(v.x, v.y);
    o2[1] = pack2(v.z, v.w);
}

// ---------------------------------------------------------------------------
// Kernel 1: RMS norm, fp16 output
// ---------------------------------------------------------------------------
__global__ __launch_bounds__(256) void norm_kernel(
    const float* __restrict__ x, const float* __restrict__ lnw,
    __half* __restrict__ xn)
{
    int row = blockIdx.x;
    const float4* xr = (const float4*)(x + (size_t)row * Dq);
    float4 v = xr[threadIdx.x];
    float s = v.x * v.x + v.y * v.y + v.z * v.z + v.w * v.w;
    __shared__ float red[8];
    #pragma unroll
    for (int o = 16; o > 0; o >>= 1) s += __shfl_xor_sync(0xffffffffu, s, o);
    if ((threadIdx.x & 31) == 0) red[threadIdx.x >> 5] = s;
    __syncthreads();
    float t = 0.f;
    #pragma unroll
    for (int i = 0; i < 8; i++) t += red[i];
    float rs = rsqrtf(t * (1.0f / (float)Dq) + 1e-6f);
    float4 lw = ((const float4*)lnw)[threadIdx.x];
    __half2* o2 = (__half2*)(xn + (size_t)row * Dq + threadIdx.x * 4);
    o2[0] = pack2(v.x * rs * lw.x, v.y * rs * lw.y);
    o2[1] = pack2(v.z * rs * lw.z, v.w * rs * lw.w);
}

// ---------------------------------------------------------------------------
// Kernel 2: fp16 GEMM (m16n8k16, fp32 accum), 3-stage cp.async, BK=64.
// BM=BN=128, 256 threads, 2 CTAs/SM. A tile 128x64 (stride 144 B),
// B tile 64x128 (stride 272 B). smem: 3*(18432+17408) = 107520 B.
// ---------------------------------------------------------------------------
#define A_STAGE_B 18432
#define B_STAGE_B 17408
#define GBB       (3 * A_STAGE_B)          // 55296
#define GEMM_SMEM_BYTES (3 * (A_STAGE_B + B_STAGE_B))   // 107520
#define NKT (Dq / 64)                      // 16

template<bool RES>
__global__ __launch_bounds__(256, 2) void gemm_hc(
    const __half* __restrict__ A, const __half* __restrict__ W,
    void* __restrict__ Cv, const float* __restrict__ res)
{
    extern __shared__ char smc[];
    const uint32_t smb = (uint32_t)__cvta_generic_to_shared(smc);

    const int col0 = blockIdx.x << 7;
    const int row0 = blockIdx.y << 7;

    const int tid = threadIdx.x;
    const int wid = tid >> 5, lane = tid & 31;
    const int lq = lane >> 2, lr = lane & 3;
    const int warpM = (wid & 1) * 64;
    const int warpN = (wid >> 1) * 32;

    auto copyTile = [&](int t, int st) {
        int k0 = t * 64;
        #pragma unroll
        for (int u = 0; u < 4; u++) {
            int lin = tid + u * 256;           // 0..1023
            int r = lin >> 3, c8 = (lin & 7) * 8;   // A: 128 x 64
            cp16(smb + st * A_STAGE_B + r * 144 + c8 * 2,
                 A + (size_t)(row0 + r) * Dq + k0 + c8);
        }
        #pragma unroll
        for (int u = 0; u < 4; u++) {
            int lin = tid + u * 256;
            int r = lin >> 4, c8 = (lin & 15) * 8;  // B: 64 x 128
            cp16(smb + GBB + st * B_STAGE_B + r * 272 + c8 * 2,
                 W + (size_t)(k0 + r) * Dq + col0 + c8);
        }
        cp_commit();
    };

    const int a_row = (lane & 7) + ((lane >> 3) & 1) * 8;
    const int a_colh = (lane >> 4) * 8;
    const int b_rowk = ((lane >> 3) & 1) * 8 + (lane & 7);
    const int b_colh = ((lane >> 4) & 1) * 8;

    float acc[4][4][4] = {};

    copyTile(0, 0);
    copyTile(1, 1);

    #pragma unroll 1
    for (int t = 0; t < NKT; t++) {
        int stage = t % 3;
        if (t + 1 < NKT) cp_wait1(); else cp_wait0();
        __syncthreads();
        if (t + 2 < NKT) copyTile(t + 2, (t + 2) % 3);

        const uint32_t aBase = smb + stage * A_STAGE_B;
        const uint32_t bBase = smb + GBB + stage * B_STAGE_B;

        #pragma unroll
        for (int ks = 0; ks < 4; ks++) {
            uint32_t a[4][4];
            #pragma unroll
            for (int mt = 0; mt < 4; mt++)
                ldsm4(a[mt][0], a[mt][1], a[mt][2], a[mt][3],
                      aBase + (warpM + mt * 16 + a_row) * 144
                            + (a_colh + ks * 16) * 2);
            #pragma unroll
            for (int p = 0; p < 2; p++) {
                uint32_t kb[4];
                ldsm4t(kb[0], kb[1], kb[2], kb[3],
                       bBase + (ks * 16 + b_rowk) * 272
                             + (warpN + p * 16 + b_colh) * 2);
                #pragma unroll
                for (int mt = 0; mt < 4; mt++) {
                    mma16(acc[mt][2 * p],     a[mt], kb);
                    mma16(acc[mt][2 * p + 1], a[mt], kb + 2);
                }
            }
        }
    }

    #pragma unroll
    for (int mt = 0; mt < 4; mt++)
        #pragma unroll
        for (int nt = 0; nt < 4; nt++) {
            int row = row0 + warpM + mt * 16 + lq;
            int col = col0 + warpN + nt * 8 + lr * 2;
            if (RES) {
                float* C = (float*)Cv;
                float2 r0 = *(const float2*)&res[(size_t)row * Dq + col];
                float2 r1 = *(const float2*)&res[(size_t)(row + 8) * Dq + col];
                float2 v0 = { acc[mt][nt][0] + r0.x, acc[mt][nt][1] + r0.y };
                float2 v1 = { acc[mt][nt][2] + r1.x, acc[mt][nt][3] + r1.y };
                *(float2*)&C[(size_t)row * Dq + col] = v0;
                *(float2*)&C[(size_t)(row + 8) * Dq + col] = v1;
            } else {
                __half* C = (__half*)Cv;
                *(__half2*)&C[(size_t)row * Dq + col] =
                    pack2(acc[mt][nt][0], acc[mt][nt][1]);
                *(__half2*)&C[(size_t)(row + 8) * Dq + col] =
                    pack2(acc[mt][nt][2], acc[mt][nt][3]);
            }
        }
}

// ---------------------------------------------------------------------------
// Kernel 3: flash attention fp16 — 64-query CTAs, 128 threads, 3 CTAs/SM,
// 3-stage cp.async K/V, register P-fragment reuse (no P smem roundtrip).
// smem: Q 9216 + K 3x9216 + V 3x9216 = 64512 B (x3 CTAs = 193536).
// ---------------------------------------------------------------------------
#define FQ_OFF 0
#define FK_OFF 9216
#define FV_OFF (9216 + 3 * 9216)            // 36864
#define FLASH_SMEM_BYTES 64512
#define NFT (Sq / 64)

__global__ __launch_bounds__(128, 3) void flash_hc(const float* __restrict__ rel_emb)
{
    extern __shared__ char smc[];
    __shared__ float bias_tab[32];

    const int tid = threadIdx.x;
    const int wid = tid >> 5, lane = tid & 31;
    const int lq = lane >> 2, lr = lane & 3;
    const int warpRow = wid * 16;

    const int q0 = blockIdx.x << 6;
    const int bh = blockIdx.y;
    const int b = bh >> 4, h = bh & 15;
    const size_t base = ((size_t)b * Sq) * Dq + (size_t)h * HDq;

    const uint32_t smb = (uint32_t)__cvta_generic_to_shared(smc);

    const int a_row  = (lane & 7) + ((lane >> 3) & 1) * 8;   // A pattern (Q)
    const int a_colh = (lane >> 4) * 8;
    const int kb_row = ((lane >> 4) & 1) * 8 + (lane & 7);   // K non-trans B
    const int kb_colh = ((lane >> 3) & 1) * 8;
    const int vb_row = ((lane >> 3) & 1) * 8 + (lane & 7);   // V trans B
    const int vb_colh = ((lane >> 4) & 1) * 8;

    const uint32_t qa0 = smb + FQ_OFF + (warpRow + a_row) * 144 + a_colh * 2;

    if (tid < 32) bias_tab[tid] = rel_emb[tid * Hq + h];

    auto copyKV = [&](int t, int st) {
        int k0 = t * 64;
        #pragma unroll
        for (int u = 0; u < 4; u++) {
            int lin = tid + u * 128;
            int r = lin >> 3, c8 = (lin & 7) * 8;
            cp16(smb + FK_OFF + st * 9216 + r * 144 + c8 * 2,
                 &g_k[base + (size_t)(k0 + r) * Dq + c8]);
            cp16(smb + FV_OFF + st * 9216 + r * 144 + c8 * 2,
                 &g_v[base + (size_t)(k0 + r) * Dq + c8]);
        }
        cp_commit();
    };

    copyKV(0, 0);
    copyKV(1, 1);

    // load Q tile (plain loads, overlaps with cp.async)
    #pragma unroll
    for (int u = 0; u < 4; u++) {
        int lin = tid + u * 128;
        int r = lin >> 3, c8 = (lin & 7) * 8;
        *(uint4*)(smc + FQ_OFF + r * 144 + c8 * 2) =
            *(const uint4*)&g_q[base + (size_t)(q0 + r) * Dq + c8];
    }
    __syncthreads();

    uint32_t aq[4][4];
    #pragma unroll
    for (int ks = 0; ks < 4; ks++)
        ldsm4(aq[ks][0], aq[ks][1], aq[ks][2], aq[ks][3], qa0 + ks * 32);

    const float NEG_INF = __int_as_float(0xff800000u);
    float mA = NEG_INF, mB = NEG_INF, lA = 0.f, lB = 0.f;
    float o[8][4] = {};
    const int rowA = q0 + warpRow + lq;
    const float b31 = bias_tab[31];
    const float b0  = bias_tab[0];

    #pragma unroll 1
    for (int t = 0; t < NFT; t++) {
        const int st = t % 3;
        const int k0 = t * 64;
        if (t + 1 < NFT) cp_wait1(); else cp_wait0();
        __syncthreads();
        if (t + 2 < NFT) copyKV(t + 2, (t + 2) % 3);

        const uint32_t ka0 = smb + FK_OFF + st * 9216 + kb_row * 144 + kb_colh * 2;
        const uint32_t va0 = smb + FV_OFF + st * 9216 + vb_row * 144 + vb_colh * 2;

        // S = Q K^T
        float s[8][4] = {};
        #pragma unroll
        for (int p = 0; p < 4; p++) {
            #pragma unroll
            for (int ks = 0; ks < 4; ks++) {
                uint32_t kb[4];
                ldsm4(kb[0], kb[1], kb[2], kb[3],
                      ka0 + p * (16 * 144) + ks * 32);
                mma16(s[2 * p],     aq[ks], kb);
                mma16(s[2 * p + 1], aq[ks], kb + 2);
            }
        }

        // + relative position bias (constant-bucket fast paths)
        if (rowA - (k0 + 63) >= 128) {
            #pragma unroll
            for (int nt = 0; nt < 8; nt++) {
                s[nt][0] += b31; s[nt][1] += b31;
                s[nt][2] += b31; s[nt][3] += b31;
            }
        } else if (k0 > rowA + 8) {
            #pragma unroll
            for (int nt = 0; nt < 8; nt++) {
                s[nt][0] += b0; s[nt][1] += b0;
                s[nt][2] += b0; s[nt][3] += b0;
            }
        } else {
            #pragma unroll
            for (int nt = 0; nt < 8; nt++) {
                int kc = k0 + nt * 8 + lr * 2;
                s[nt][0] += bias_tab[rp_bucket(rowA - kc)];
                s[nt][1] += bias_tab[rp_bucket(rowA - kc - 1)];
                s[nt][2] += bias_tab[rp_bucket(rowA + 8 - kc)];
                s[nt][3] += bias_tab[rp_bucket(rowA + 8 - kc - 1)];
            }
        }

        // online softmax
        float mxA = NEG_INF, mxB = NEG_INF;
        #pragma unroll
        for (int nt = 0; nt < 8; nt++) {
            mxA = fmaxf(mxA, fmaxf(s[nt][0], s[nt][1]));
            mxB = fmaxf(mxB, fmaxf(s[nt][2], s[nt][3]));
        }
        mxA = fmaxf(mxA, __shfl_xor_sync(0xffffffffu, mxA, 1));
        mxA = fmaxf(mxA, __shfl_xor_sync(0xffffffffu, mxA, 2));
        mxB = fmaxf(mxB, __shfl_xor_sync(0xffffffffu, mxB, 1));
        mxB = fmaxf(mxB, __shfl_xor_sync(0xffffffffu, mxB, 2));
        float nmA = fmaxf(mA, mxA), nmB = fmaxf(mB, mxB);
        float alA = __expf(mA - nmA), alB = __expf(mB - nmB);
        float sumA = 0.f, sumB = 0.f;
        #pragma unroll
        for (int nt = 0; nt < 8; nt++) {
            s[nt][0] = __expf(s[nt][0] - nmA); sumA += s[nt][0];
            s[nt][1] = __expf(s[nt][1] - nmA); sumA += s[nt][1];
            s[nt][2] = __expf(s[nt][2] - nmB); sumB += s[nt][2];
            s[nt][3] = __expf(s[nt][3] - nmB); sumB += s[nt][3];
        }
        sumA += __shfl_xor_sync(0xffffffffu, sumA, 1);
        sumA += __shfl_xor_sync(0xffffffffu, sumA, 2);
        sumB += __shfl_xor_sync(0xffffffffu, sumB, 1);
        sumB += __shfl_xor_sync(0xffffffffu, sumB, 2);
        lA = lA * alA + sumA; mA = nmA;
        lB = lB * alB + sumB; mB = nmB;
        #pragma unroll
        for (int nt = 0; nt < 8; nt++) {
            o[nt][0] *= alA; o[nt][1] *= alA;
            o[nt][2] *= alB; o[nt][3] *= alB;
        }

        // O += P V — P A-fragments built directly from S registers:
        // k-block [16j,16j+16): a0 = P[lq][16j+2lr..+1]   = s[2j]   c0,c1
        //                       a1 = P[lq+8][...]          = s[2j]   c2,c3
        //                       a2 = P[lq][16j+8+2lr..+1]  = s[2j+1] c0,c1
        //                       a3 = P[lq+8][...]          = s[2j+1] c2,c3
        #pragma unroll
        for (int j = 0; j < 4; j++) {
            uint32_t ap[4];
            ap[0] = packu(s[2 * j][0],     s[2 * j][1]);
            ap[1] = packu(s[2 * j][2],     s[2 * j][3]);
            ap[2] = packu(s[2 * j + 1][0], s[2 * j + 1][1]);
            ap[3] = packu(s[2 * j + 1][2], s[2 * j + 1][3]);
            #pragma unroll
            for (int p = 0; p < 4; p++) {
                uint32_t vb[4];
                ldsm4t(vb[0], vb[1], vb[2], vb[3],
                       va0 + j * (16 * 144) + p * 32);
                mma16(o[2 * p],     ap, vb);
                mma16(o[2 * p + 1], ap, vb + 2);
            }
        }
    }

    float invA = 1.0f / lA, invB = 1.0f / lB;
    #pragma unroll
    for (int nt = 0; nt < 8; nt++) {
        int col = nt * 8 + lr * 2;
        *(__half2*)&g_ctx[base + (size_t)rowA * Dq + col] =
            pack2(o[nt][0] * invA, o[nt][1] * invA);
        *(__half2*)&g_ctx[base + (size_t)(rowA + 8) * Dq + col] =
            pack2(o[nt][2] * invB, o[nt][3] * invB);
    }
}

// ---------------------------------------------------------------------------
// Launch
// ---------------------------------------------------------------------------
extern "C" void kernel_launch(void* const* d_in, const int* in_sizes, int n_in,
                              void* d_out, int out_size)
{
    const float* input = (const float*)d_in[0];
    const float* wq    = (const float*)d_in[2];
    const float* wk    = (const float*)d_in[3];
    const float* wv    = (const float*)d_in[4];
    const float* wo    = (const float*)d_in[5];
    const float* rel   = (const float*)d_in[6];
    const float* lnw   = (const float*)d_in[7];
    float* out         = (float*)d_out;

    cudaFuncSetAttribute(flash_hc,
                         cudaFuncAttributeMaxDynamicSharedMemorySize, FLASH_SMEM_BYTES);
    cudaFuncSetAttribute(gemm_hc<false>,
                         cudaFuncAttributeMaxDynamicSharedMemorySize, GEMM_SMEM_BYTES);
    cudaFuncSetAttribute(gemm_hc<true>,
                         cudaFuncAttributeMaxDynamicSharedMemorySize, GEMM_SMEM_BYTES);

    __half *g_xn_p, *g_q_p, *g_k_p, *g_v_p, *g_ctx_p, *g_wt_p;
    cudaGetSymbolAddress((void**)&g_xn_p, g_xn);
    cudaGetSymbolAddress((void**)&g_q_p,  g_q);
    cudaGetSymbolAddress((void**)&g_k_p,  g_k);
    cudaGetSymbolAddress((void**)&g_v_p,  g_v);
    cudaGetSymbolAddress((void**)&g_ctx_p, g_ctx);
    cudaGetSymbolAddress((void**)&g_wt_p, g_wt);

    dim3 gw(Dq * Dq / 1024, 4);
    cvtw_kernel<<<gw, 256>>>(wq, wk, wv, wo);

    norm_kernel<<<Mq, 256>>>(input, lnw, g_xn_p);

    const __half* wq_t = g_wt_p;
    const __half* wk_t = g_wt_p + (size_t)Dq * Dq;
    const __half* wv_t = g_wt_p + 2 * (size_t)Dq * Dq;
    const __half* wo_t = g_wt_p + 3 * (size_t)Dq * Dq;

    dim3 gg(Dq / 128, Mq / 128);
    gemm_hc<false><<<gg, 256, GEMM_SMEM_BYTES>>>(g_xn_p, wq_t, g_q_p, nullptr);
    gemm_hc<false><<<gg, 256, GEMM_SMEM_BYTES>>>(g_xn_p, wk_t, g_k_p, nullptr);
    gemm_hc<false><<<gg, 256, GEMM_SMEM_BYTES>>>(g_xn_p, wv_t, g_v_p, nullptr);

    dim3 gf(Sq / 64, Bq * Hq);
    flash_hc<<<gf, 128, FLASH_SMEM_BYTES>>>(rel);

    gemm_hc<true><<<gg, 256, GEMM_SMEM_BYTES>>>(g_ctx_p, wo_t, out, input);
}

// round 16
// speedup vs baseline: 2.6248x; 1.0176x over previous
#include <cuda_runtime.h>
#include <cuda_fp16.h>
#include <cstdint>
#include <cstring>

#define Bq   4
#define Sq   2048
#define Dq   1024
#define Hq   16
#define HDq  64
#define Mq   (Bq*Sq)

__device__ __half g_xn[(size_t)Mq*Dq];
__device__ __half g_q[(size_t)Mq*Dq];
__device__ __half g_k[(size_t)Mq*Dq];
__device__ __half g_v[(size_t)Mq*Dq];
__device__ __half g_ctx[(size_t)Mq*Dq];
__device__ __half g_wt[4][(size_t)Dq*Dq];   // fp16-rounded weights

// ---------------------------------------------------------------------------
// helpers
// ---------------------------------------------------------------------------
__device__ __forceinline__ void mma16(float* c, const uint32_t* a, const uint32_t* b) {
    asm volatile(
        "mma.sync.aligned.m16n8k16.row.col.f32.f16.f16.f32 "
        "{%0,%1,%2,%3},{%4,%5,%6,%7},{%8,%9},{%0,%1,%2,%3};"
        : "+f"(c[0]), "+f"(c[1]), "+f"(c[2]), "+f"(c[3])
        : "r"(a[0]), "r"(a[1]), "r"(a[2]), "r"(a[3]), "r"(b[0]), "r"(b[1]));
}

__device__ __forceinline__ void ldsm4(uint32_t& r0, uint32_t& r1,
                                      uint32_t& r2, uint32_t& r3, uint32_t addr) {
    asm volatile("ldmatrix.sync.aligned.m8n8.x4.shared.b16 {%0,%1,%2,%3}, [%4];"
                 : "=r"(r0), "=r"(r1), "=r"(r2), "=r"(r3) : "r"(addr));
}
__device__ __forceinline__ void ldsm4t(uint32_t& r0, uint32_t& r1,
                                       uint32_t& r2, uint32_t& r3, uint32_t addr) {
    asm volatile("ldmatrix.sync.aligned.m8n8.x4.trans.shared.b16 {%0,%1,%2,%3}, [%4];"
                 : "=r"(r0), "=r"(r1), "=r"(r2), "=r"(r3) : "r"(addr));
}

__device__ __forceinline__ void cp16(uint32_t dst, const void* src) {
    asm volatile("cp.async.cg.shared.global [%0], [%1], 16;"
                 :: "r"(dst), "l"(src));
}
__device__ __forceinline__ void cp_commit() { asm volatile("cp.async.commit_group;"); }
__device__ __forceinline__ void cp_wait1()  { asm volatile("cp.async.wait_group 1;"); }
__device__ __forceinline__ void cp_wait0()  { asm volatile("cp.async.wait_group 0;"); }

__device__ __forceinline__ int rp_bucket(int rp) {
    if (rp < 0) rp = 0;
    if (rp < 16) return rp;
    int bk = 16 + (int)(__logf((float)rp * 0.0625f) * 7.6944086f);
    return bk > 31 ? 31 : bk;
}

__device__ __forceinline__ __half2 pack2(float a, float b) {
    __half2 h;
    h.x = __float2half_rn(a);
    h.y = __float2half_rn(b);
    return h;
}
__device__ __forceinline__ uint32_t packu(float a, float b) {
    __half2 h = pack2(a, b);
    uint32_t u;
    memcpy(&u, &h, 4);
    return u;
}

// ---------------------------------------------------------------------------
// Kernel 0: round weights to fp16
// ---------------------------------------------------------------------------
__global__ __launch_bounds__(256) void cvtw_kernel(
    const float* __restrict__ w0, const float* __restrict__ w1,
    const float* __restrict__ w2, const float* __restrict__ w3)
{
    const float* w = (blockIdx.y == 0) ? w0 : (blockIdx.y == 1) ? w1
                   : (blockIdx.y == 2) ? w2 : w3;
    __half* o = g_wt[blockIdx.y];
    size_t i = ((size_t)blockIdx.x * 256 + threadIdx.x) * 4;
    float4 v = *(const float4*)&w[i];
    __half2* o2 = (__half2*)(o + i);
    o2[0] = pack2(v.x, v.y);
    o2[1] = pack2(v.z, v.w);
}

// ---------------------------------------------------------------------------
// Kernel 1: RMS norm, fp16 output
// ---------------------------------------------------------------------------
__global__ __launch_bounds__(256) void norm_kernel(
    const float* __restrict__ x, const float* __restrict__ lnw,
    __half* __restrict__ xn)
{
    int row = blockIdx.x;
    const float4* xr = (const float4*)(x + (size_t)row * Dq);
    float4 v = xr[threadIdx.x];
    float s = v.x * v.x + v.y * v.y + v.z * v.z + v.w * v.w;
    __shared__ float red[8];
    #pragma unroll
    for (int o = 16; o > 0; o >>= 1) s += __shfl_xor_sync(0xffffffffu, s, o);
    if ((threadIdx.x & 31) == 0) red[threadIdx.x >> 5] = s;
    __syncthreads();
    float t = 0.f;
    #pragma unroll
    for (int i = 0; i < 8; i++) t += red[i];
    float rs = rsqrtf(t * (1.0f / (float)Dq) + 1e-6f);
    float4 lw = ((const float4*)lnw)[threadIdx.x];
    __half2* o2 = (__half2*)(xn + (size_t)row * Dq + threadIdx.x * 4);
    o2[0] = pack2(v.x * rs * lw.x, v.y * rs * lw.y);
    o2[1] = pack2(v.z * rs * lw.z, v.w * rs * lw.w);
}

// ---------------------------------------------------------------------------
// Kernel 2: fp16 GEMM (m16n8k16, fp32 accum), 3-stage cp.async, BK=32.
// (R13-measured-best: 59.0us/launch.)
// smem: 3*(10240 + 8704) = 56832 B.
// ---------------------------------------------------------------------------
#define A_STAGE_B 10240
#define B_STAGE_B 8704
#define GBB       (3 * A_STAGE_B)
#define GEMM_SMEM_BYTES (3 * (A_STAGE_B + B_STAGE_B))
#define NKT (Dq / 32)

template<bool RES>
__global__ __launch_bounds__(256, 2) void gemm_hc(
    const __half* __restrict__ A, const __half* __restrict__ W,
    void* __restrict__ Cv, const float* __restrict__ res)
{
    extern __shared__ char smc[];
    const uint32_t smb = (uint32_t)__cvta_generic_to_shared(smc);

    const int col0 = blockIdx.x << 7;
    const int row0 = blockIdx.y << 7;

    const int tid = threadIdx.x;
    const int wid = tid >> 5, lane = tid & 31;
    const int lq = lane >> 2, lr = lane & 3;
    const int warpM = (wid & 1) * 64;
    const int warpN = (wid >> 1) * 32;

    auto copyTile = [&](int t, int st) {
        int k0 = t * 32;
        #pragma unroll
        for (int u = 0; u < 2; u++) {
            int lin = tid + u * 256;
            int r = lin >> 2, c8 = (lin & 3) * 8;
            cp16(smb + st * A_STAGE_B + r * 80 + c8 * 2,
                 A + (size_t)(row0 + r) * Dq + k0 + c8);
        }
        #pragma unroll
        for (int u = 0; u < 2; u++) {
            int lin = tid + u * 256;
            int r = lin >> 4, c8 = (lin & 15) * 8;
            cp16(smb + GBB + st * B_STAGE_B + r * 272 + c8 * 2,
                 W + (size_t)(k0 + r) * Dq + col0 + c8);
        }
        cp_commit();
    };

    const int a_row = (lane & 7) + ((lane >> 3) & 1) * 8;
    const int a_colh = (lane >> 4) * 8;
    const int b_rowk = ((lane >> 3) & 1) * 8 + (lane & 7);
    const int b_colh = ((lane >> 4) & 1) * 8;

    float acc[4][4][4] = {};

    copyTile(0, 0);
    copyTile(1, 1);

    #pragma unroll 1
    for (int t = 0; t < NKT; t++) {
        int stage = t % 3;
        if (t + 1 < NKT) cp_wait1(); else cp_wait0();
        __syncthreads();
        if (t + 2 < NKT) copyTile(t + 2, (t + 2) % 3);

        const uint32_t aBase = smb + stage * A_STAGE_B;
        const uint32_t bBase = smb + GBB + stage * B_STAGE_B;

        #pragma unroll
        for (int ks = 0; ks < 2; ks++) {
            uint32_t a[4][4];
            #pragma unroll
            for (int mt = 0; mt < 4; mt++)
                ldsm4(a[mt][0], a[mt][1], a[mt][2], a[mt][3],
                      aBase + (warpM + mt * 16 + a_row) * 80
                            + (a_colh + ks * 16) * 2);
            #pragma unroll
            for (int p = 0; p < 2; p++) {
                uint32_t kb[4];
                ldsm4t(kb[0], kb[1], kb[2], kb[3],
                       bBase + (ks * 16 + b_rowk) * 272
                             + (warpN + p * 16 + b_colh) * 2);
                #pragma unroll
                for (int mt = 0; mt < 4; mt++) {
                    mma16(acc[mt][2 * p],     a[mt], kb);
                    mma16(acc[mt][2 * p + 1], a[mt], kb + 2);
                }
            }
        }
    }

    #pragma unroll
    for (int mt = 0; mt < 4; mt++)
        #pragma unroll
        for (int nt = 0; nt < 4; nt++) {
            int row = row0 + warpM + mt * 16 + lq;
            int col = col0 + warpN + nt * 8 + lr * 2;
            if (RES) {
                float* C = (float*)Cv;
                float2 r0 = *(const float2*)&res[(size_t)row * Dq + col];
                float2 r1 = *(const float2*)&res[(size_t)(row + 8) * Dq + col];
                float2 v0 = { acc[mt][nt][0] + r0.x, acc[mt][nt][1] + r0.y };
                float2 v1 = { acc[mt][nt][2] + r1.x, acc[mt][nt][3] + r1.y };
                *(float2*)&C[(size_t)row * Dq + col] = v0;
                *(float2*)&C[(size_t)(row + 8) * Dq + col] = v1;
            } else {
                __half* C = (__half*)Cv;
                *(__half2*)&C[(size_t)row * Dq + col] =
                    pack2(acc[mt][nt][0], acc[mt][nt][1]);
                *(__half2*)&C[(size_t)(row + 8) * Dq + col] =
                    pack2(acc[mt][nt][2], acc[mt][nt][3]);
            }
        }
}

// ---------------------------------------------------------------------------
// Kernel 3: flash attention fp16 — 128-query CTAs, 256 threads (8 warps,
// each owning 16 rows: warp math identical to R14), 2 CTAs/SM,
// 3-stage cp.async K/V, register P-fragment reuse.
// K/V traffic HALVED vs 64-query CTAs; 16 active warps/SM (was 12).
// smem: Q 128*144=18432 + K 3x9216 + V 3x9216 = 73728 B (x2 = 147456).
// ---------------------------------------------------------------------------
#define FQ_OFF 0
#define FK_OFF 18432
#define FV_OFF (18432 + 3 * 9216)           // 46080
#define FLASH_SMEM_BYTES 73728
#define NFT (Sq / 64)

__global__ __launch_bounds__(256, 2) void flash_hc(const float* __restrict__ rel_emb)
{
    extern __shared__ char smc[];
    __shared__ float bias_tab[32];

    const int tid = threadIdx.x;
    const int wid = tid >> 5, lane = tid & 31;
    const int lq = lane >> 2, lr = lane & 3;
    const int warpRow = wid * 16;          // 0..112

    const int q0 = blockIdx.x << 7;        // 128 queries per CTA
    const int bh = blockIdx.y;
    const int b = bh >> 4, h = bh & 15;
    const size_t base = ((size_t)b * Sq) * Dq + (size_t)h * HDq;

    const uint32_t smb = (uint32_t)__cvta_generic_to_shared(smc);

    const int a_row  = (lane & 7) + ((lane >> 3) & 1) * 8;   // A pattern (Q)
    const int a_colh = (lane >> 4) * 8;
    const int kb_row = ((lane >> 4) & 1) * 8 + (lane & 7);   // K non-trans B
    const int kb_colh = ((lane >> 3) & 1) * 8;
    const int vb_row = ((lane >> 3) & 1) * 8 + (lane & 7);   // V trans B
    const int vb_colh = ((lane >> 4) & 1) * 8;

    const uint32_t qa0 = smb + FQ_OFF + (warpRow + a_row) * 144 + a_colh * 2;

    if (tid < 32) bias_tab[tid] = rel_emb[tid * Hq + h];

    // K/V tile copy: 64 rows x 64 halves = 512 16B-chunks, 256 thr -> u<2
    auto copyKV = [&](int t, int st) {
        int k0 = t * 64;
        #pragma unroll
        for (int u = 0; u < 2; u++) {
            int lin = tid + u * 256;
            int r = lin >> 3, c8 = (lin & 7) * 8;
            cp16(smb + FK_OFF + st * 9216 + r * 144 + c8 * 2,
                 &g_k[base + (size_t)(k0 + r) * Dq + c8]);
            cp16(smb + FV_OFF + st * 9216 + r * 144 + c8 * 2,
                 &g_v[base + (size_t)(k0 + r) * Dq + c8]);
        }
        cp_commit();
    };

    copyKV(0, 0);
    copyKV(1, 1);

    // Q tile: 128 rows x 64 halves = 1024 16B-chunks, 256 thr -> u<4
    #pragma unroll
    for (int u = 0; u < 4; u++) {
        int lin = tid + u * 256;
        int r = lin >> 3, c8 = (lin & 7) * 8;
        *(uint4*)(smc + FQ_OFF + r * 144 + c8 * 2) =
            *(const uint4*)&g_q[base + (size_t)(q0 + r) * Dq + c8];
    }
    __syncthreads();

    uint32_t aq[4][4];
    #pragma unroll
    for (int ks = 0; ks < 4; ks++)
        ldsm4(aq[ks][0], aq[ks][1], aq[ks][2], aq[ks][3], qa0 + ks * 32);

    const float NEG_INF = __int_as_float(0xff800000u);
    float mA = NEG_INF, mB = NEG_INF, lA = 0.f, lB = 0.f;
    float o[8][4] = {};
    const int rowA = q0 + warpRow + lq;
    const float b31 = bias_tab[31];
    const float b0  = bias_tab[0];

    #pragma unroll 1
    for (int t = 0; t < NFT; t++) {
        const int st = t % 3;
        const int k0 = t * 64;
        if (t + 1 < NFT) cp_wait1(); else cp_wait0();
        __syncthreads();
        // stage (t+2)%3 consumed at iter t-1; barrier above publishes that
        if (t + 2 < NFT) copyKV(t + 2, (t + 2) % 3);

        const uint32_t ka0 = smb + FK_OFF + st * 9216 + kb_row * 144 + kb_colh * 2;
        const uint32_t va0 = smb + FV_OFF + st * 9216 + vb_row * 144 + vb_colh * 2;

        // S = Q K^T
        float s[8][4] = {};
        #pragma unroll
        for (int p = 0; p < 4; p++) {
            #pragma unroll
            for (int ks = 0; ks < 4; ks++) {
                uint32_t kb[4];
                ldsm4(kb[0], kb[1], kb[2], kb[3],
                      ka0 + p * (16 * 144) + ks * 32);
                mma16(s[2 * p],     aq[ks], kb);
                mma16(s[2 * p + 1], aq[ks], kb + 2);
            }
        }

        // + relative position bias (constant-bucket fast paths)
        if (rowA - (k0 + 63) >= 128) {
            #pragma unroll
            for (int nt = 0; nt < 8; nt++) {
                s[nt][0] += b31; s[nt][1] += b31;
                s[nt][2] += b31; s[nt][3] += b31;
            }
        } else if (k0 > rowA + 8) {
            #pragma unroll
            for (int nt = 0; nt < 8; nt++) {
                s[nt][0] += b0; s[nt][1] += b0;
                s[nt][2] += b0; s[nt][3] += b0;
            }
        } else {
            #pragma unroll
            for (int nt = 0; nt < 8; nt++) {
                int kc = k0 + nt * 8 + lr * 2;
                s[nt][0] += bias_tab[rp_bucket(rowA - kc)];
                s[nt][1] += bias_tab[rp_bucket(rowA - kc - 1)];
                s[nt][2] += bias_tab[rp_bucket(rowA + 8 - kc)];
                s[nt][3] += bias_tab[rp_bucket(rowA + 8 - kc - 1)];
            }
        }

        // online softmax
        float mxA = NEG_INF, mxB = NEG_INF;
        #pragma unroll
        for (int nt = 0; nt < 8; nt++) {
            mxA = fmaxf(mxA, fmaxf(s[nt][0], s[nt][1]));
            mxB = fmaxf(mxB, fmaxf(s[nt][2], s[nt][3]));
        }
        mxA = fmaxf(mxA, __shfl_xor_sync(0xffffffffu, mxA, 1));
        mxA = fmaxf(mxA, __shfl_xor_sync(0xffffffffu, mxA, 2));
        mxB = fmaxf(mxB, __shfl_xor_sync(0xffffffffu, mxB, 1));
        mxB = fmaxf(mxB, __shfl_xor_sync(0xffffffffu, mxB, 2));
        float nmA = fmaxf(mA, mxA), nmB = fmaxf(mB, mxB);
        float alA = __expf(mA - nmA), alB = __expf(mB - nmB);
        float sumA = 0.f, sumB = 0.f;
        #pragma unroll
        for (int nt = 0; nt < 8; nt++) {
            s[nt][0] = __expf(s[nt][0] - nmA); sumA += s[nt][0];
            s[nt][1] = __expf(s[nt][1] - nmA); sumA += s[nt][1];
            s[nt][2] = __expf(s[nt][2] - nmB); sumB += s[nt][2];
            s[nt][3] = __expf(s[nt][3] - nmB); sumB += s[nt][3];
        }
        sumA += __shfl_xor_sync(0xffffffffu, sumA, 1);
        sumA += __shfl_xor_sync(0xffffffffu, sumA, 2);
        sumB += __shfl_xor_sync(0xffffffffu, sumB, 1);
        sumB += __shfl_xor_sync(0xffffffffu, sumB, 2);
        lA = lA * alA + sumA; mA = nmA;
        lB = lB * alB + sumB; mB = nmB;
        #pragma unroll
        for (int nt = 0; nt < 8; nt++) {
            o[nt][0] *= alA; o[nt][1] *= alA;
            o[nt][2] *= alB; o[nt][3] *= alB;
        }

        // O += P V — P A-fragments built directly from S registers
        #pragma unroll
        for (int j = 0; j < 4; j++) {
            uint32_t ap[4];
            ap[0] = packu(s[2 * j][0],     s[2 * j][1]);
            ap[1] = packu(s[2 * j][2],     s[2 * j][3]);
            ap[2] = packu(s[2 * j + 1][0], s[2 * j + 1][1]);
            ap[3] = packu(s[2 * j + 1][2], s[2 * j + 1][3]);
            #pragma unroll
            for (int p = 0; p < 4; p++) {
                uint32_t vb[4];
                ldsm4t(vb[0], vb[1], vb[2], vb[3],
                       va0 + j * (16 * 144) + p * 32);
                mma16(o[2 * p],     ap, vb);
                mma16(o[2 * p + 1], ap, vb + 2);
            }
        }
    }

    float invA = 1.0f / lA, invB = 1.0f / lB;
    #pragma unroll
    for (int nt = 0; nt < 8; nt++) {
        int col = nt * 8 + lr * 2;
        *(__half2*)&g_ctx[base + (size_t)rowA * Dq + col] =
            pack2(o[nt][0] * invA, o[nt][1] * invA);
        *(__half2*)&g_ctx[base + (size_t)(rowA + 8) * Dq + col] =
            pack2(o[nt][2] * invB, o[nt][3] * invB);
    }
}

// ---------------------------------------------------------------------------
// Launch
// ---------------------------------------------------------------------------
extern "C" void kernel_launch(void* const* d_in, const int* in_sizes, int n_in,
                              void* d_out, int out_size)
{
    const float* input = (const float*)d_in[0];
    const float* wq    = (const float*)d_in[2];
    const float* wk    = (const float*)d_in[3];
    const float* wv    = (const float*)d_in[4];
    const float* wo    = (const float*)d_in[5];
    const float* rel   = (const float*)d_in[6];
    const float* lnw   = (const float*)d_in[7];
    float* out         = (float*)d_out;

    cudaFuncSetAttribute(flash_hc,
                         cudaFuncAttributeMaxDynamicSharedMemorySize, FLASH_SMEM_BYTES);
    cudaFuncSetAttribute(gemm_hc<false>,
                         cudaFuncAttributeMaxDynamicSharedMemorySize, GEMM_SMEM_BYTES);
    cudaFuncSetAttribute(gemm_hc<true>,
                         cudaFuncAttributeMaxDynamicSharedMemorySize, GEMM_SMEM_BYTES);

    __half *g_xn_p, *g_q_p, *g_k_p, *g_v_p, *g_ctx_p, *g_wt_p;
    cudaGetSymbolAddress((void**)&g_xn_p, g_xn);
    cudaGetSymbolAddress((void**)&g_q_p,  g_q);
    cudaGetSymbolAddress((void**)&g_k_p,  g_k);
    cudaGetSymbolAddress((void**)&g_v_p,  g_v);
    cudaGetSymbolAddress((void**)&g_ctx_p, g_ctx);
    cudaGetSymbolAddress((void**)&g_wt_p, g_wt);

    dim3 gw(Dq * Dq / 1024, 4);
    cvtw_kernel<<<gw, 256>>>(wq, wk, wv, wo);

    norm_kernel<<<Mq, 256>>>(input, lnw, g_xn_p);

    const __half* wq_t = g_wt_p;
    const __half* wk_t = g_wt_p + (size_t)Dq * Dq;
    const __half* wv_t = g_wt_p + 2 * (size_t)Dq * Dq;
    const __half* wo_t = g_wt_p + 3 * (size_t)Dq * Dq;

    dim3 gg(Dq / 128, Mq / 128);
    gemm_hc<false><<<gg, 256, GEMM_SMEM_BYTES>>>(g_xn_p, wq_t, g_q_p, nullptr);
    gemm_hc<false><<<gg, 256, GEMM_SMEM_BYTES>>>(g_xn_p, wk_t, g_k_p, nullptr);
    gemm_hc<false><<<gg, 256, GEMM_SMEM_BYTES>>>(g_xn_p, wv_t, g_v_p, nullptr);

    dim3 gf(Sq / 128, Bq * Hq);
    flash_hc<<<gf, 256, FLASH_SMEM_BYTES>>>(rel);

    gemm_hc<true><<<gg, 256, GEMM_SMEM_BYTES>>>(g_ctx_p, wo_t, out, input);
}

// round 17
// speedup vs baseline: 2.7241x; 1.0378x over previous
#include <cuda_runtime.h>
#include <cuda_fp16.h>
#include <cstdint>
#include <cstring>

#define Bq   4
#define Sq   2048
#define Dq   1024
#define Hq   16
#define HDq  64
#define Mq   (Bq*Sq)

__device__ __half g_xn[(size_t)Mq*Dq];
__device__ __half g_q[(size_t)Mq*Dq];
__device__ __half g_k[(size_t)Mq*Dq];
__device__ __half g_v[(size_t)Mq*Dq];
__device__ __half g_ctx[(size_t)Mq*Dq];
__device__ __half g_wt[4][(size_t)Dq*Dq];   // fp16-rounded weights

// ---------------------------------------------------------------------------
// helpers
// ---------------------------------------------------------------------------
__device__ __forceinline__ void mma16(float* c, const uint32_t* a, const uint32_t* b) {
    asm volatile(
        "mma.sync.aligned.m16n8k16.row.col.f32.f16.f16.f32 "
        "{%0,%1,%2,%3},{%4,%5,%6,%7},{%8,%9},{%0,%1,%2,%3};"
        : "+f"(c[0]), "+f"(c[1]), "+f"(c[2]), "+f"(c[3])
        : "r"(a[0]), "r"(a[1]), "r"(a[2]), "r"(a[3]), "r"(b[0]), "r"(b[1]));
}

__device__ __forceinline__ void ldsm4(uint32_t& r0, uint32_t& r1,
                                      uint32_t& r2, uint32_t& r3, uint32_t addr) {
    asm volatile("ldmatrix.sync.aligned.m8n8.x4.shared.b16 {%0,%1,%2,%3}, [%4];"
                 : "=r"(r0), "=r"(r1), "=r"(r2), "=r"(r3) : "r"(addr));
}
__device__ __forceinline__ void ldsm4t(uint32_t& r0, uint32_t& r1,
                                       uint32_t& r2, uint32_t& r3, uint32_t addr) {
    asm volatile("ldmatrix.sync.aligned.m8n8.x4.trans.shared.b16 {%0,%1,%2,%3}, [%4];"
                 : "=r"(r0), "=r"(r1), "=r"(r2), "=r"(r3) : "r"(addr));
}

__device__ __forceinline__ void cp16(uint32_t dst, const void* src) {
    asm volatile("cp.async.cg.shared.global [%0], [%1], 16;"
                 :: "r"(dst), "l"(src));
}
__device__ __forceinline__ void cp_commit() { asm volatile("cp.async.commit_group;"); }
__device__ __forceinline__ void cp_wait1()  { asm volatile("cp.async.wait_group 1;"); }
__device__ __forceinline__ void cp_wait0()  { asm volatile("cp.async.wait_group 0;"); }

__device__ __forceinline__ int rp_bucket(int rp) {
    if (rp < 0) rp = 0;
    if (rp < 16) return rp;
    int bk = 16 + (int)(__logf((float)rp * 0.0625f) * 7.6944086f);
    return bk > 31 ? 31 : bk;
}

__device__ __forceinline__ __half2 pack2(float a, float b) {
    __half2 h;
    h.x = __float2half_rn(a);
    h.y = __float2half_rn(b);
    return h;
}
__device__ __forceinline__ uint32_t packu(float a, float b) {
    __half2 h = pack2(a, b);
    uint32_t u;
    memcpy(&u, &h, 4);
    return u;
}

// ---------------------------------------------------------------------------
// Kernel 0: round weights to fp16
// ---------------------------------------------------------------------------
__global__ __launch_bounds__(256) void cvtw_kernel(
    const float* __restrict__ w0, const float* __restrict__ w1,
    const float* __restrict__ w2, const float* __restrict__ w3)
{
    const float* w = (blockIdx.y == 0) ? w0 : (blockIdx.y == 1) ? w1
                   : (blockIdx.y == 2) ? w2 : w3;
    __half* o = g_wt[blockIdx.y];
    size_t i = ((size_t)blockIdx.x * 256 + threadIdx.x) * 4;
    float4 v = *(const float4*)&w[i];
    __half2* o2 = (__half2*)(o + i);
    o2[0] = pack2(v.x, v.y);
    o2[1] = pack2(v.z, v.w);
}

// ---------------------------------------------------------------------------
// Kernel 1: RMS norm, fp16 output
// ---------------------------------------------------------------------------
__global__ __launch_bounds__(256) void norm_kernel(
    const float* __restrict__ x, const float* __restrict__ lnw,
    __half* __restrict__ xn)
{
    int row = blockIdx.x;
    const float4* xr = (const float4*)(x + (size_t)row * Dq);
    float4 v = xr[threadIdx.x];
    float s = v.x * v.x + v.y * v.y + v.z * v.z + v.w * v.w;
    __shared__ float red[8];
    #pragma unroll
    for (int o = 16; o > 0; o >>= 1) s += __shfl_xor_sync(0xffffffffu, s, o);
    if ((threadIdx.x & 31) == 0) red[threadIdx.x >> 5] = s;
    __syncthreads();
    float t = 0.f;
    #pragma unroll
    for (int i = 0; i < 8; i++) t += red[i];
    float rs = rsqrtf(t * (1.0f / (float)Dq) + 1e-6f);
    float4 lw = ((const float4*)lnw)[threadIdx.x];
    __half2* o2 = (__half2*)(xn + (size_t)row * Dq + threadIdx.x * 4);
    o2[0] = pack2(v.x * rs * lw.x, v.y * rs * lw.y);
    o2[1] = pack2(v.z * rs * lw.z, v.w * rs * lw.w);
}

// ---------------------------------------------------------------------------
// Kernel 2: fp16 GEMM (m16n8k16, fp32 accum), 3-stage cp.async, BK=32.
// NEW: BM=64, BN=128, 128 threads, 4 CTAs/SM (barrier staggering).
// A tile 64x32 (row stride 80 B), B tile 32x128 (row stride 272 B).
// smem: 3*(5120 + 8704) = 41472 B -> x4 CTAs = 165888 B.
// ---------------------------------------------------------------------------
#define A_STAGE_B 5120
#define B_STAGE_B 8704
#define GBB       (3 * A_STAGE_B)          // 15360
#define GEMM_SMEM_BYTES (3 * (A_STAGE_B + B_STAGE_B))   // 41472
#define NKT (Dq / 32)

template<bool RES>
__global__ __launch_bounds__(128, 4) void gemm_hc(
    const __half* __restrict__ A, const __half* __restrict__ W,
    void* __restrict__ Cv, const float* __restrict__ res)
{
    extern __shared__ char smc[];
    const uint32_t smb = (uint32_t)__cvta_generic_to_shared(smc);

    const int col0 = blockIdx.x << 7;
    const int row0 = blockIdx.y << 6;      // 64-row tiles

    const int tid = threadIdx.x;
    const int wid = tid >> 5, lane = tid & 31;
    const int lq = lane >> 2, lr = lane & 3;
    const int warpN = wid * 32;            // 4 warps across N

    auto copyTile = [&](int t, int st) {
        int k0 = t * 32;
        #pragma unroll
        for (int u = 0; u < 2; u++) {
            int lin = tid + u * 128;           // 0..255
            int r = lin >> 2, c8 = (lin & 3) * 8;   // A: 64 x 32
            cp16(smb + st * A_STAGE_B + r * 80 + c8 * 2,
                 A + (size_t)(row0 + r) * Dq + k0 + c8);
        }
        #pragma unroll
        for (int u = 0; u < 4; u++) {
            int lin = tid + u * 128;           // 0..511
            int r = lin >> 4, c8 = (lin & 15) * 8;  // B: 32 x 128
            cp16(smb + GBB + st * B_STAGE_B + r * 272 + c8 * 2,
                 W + (size_t)(k0 + r) * Dq + col0 + c8);
        }
        cp_commit();
    };

    const int a_row = (lane & 7) + ((lane >> 3) & 1) * 8;
    const int a_colh = (lane >> 4) * 8;
    const int b_rowk = ((lane >> 3) & 1) * 8 + (lane & 7);
    const int b_colh = ((lane >> 4) & 1) * 8;

    float acc[4][4][4] = {};

    copyTile(0, 0);
    copyTile(1, 1);

    #pragma unroll 1
    for (int t = 0; t < NKT; t++) {
        int stage = t % 3;
        if (t + 1 < NKT) cp_wait1(); else cp_wait0();
        __syncthreads();
        if (t + 2 < NKT) copyTile(t + 2, (t + 2) % 3);

        const uint32_t aBase = smb + stage * A_STAGE_B;
        const uint32_t bBase = smb + GBB + stage * B_STAGE_B;

        #pragma unroll
        for (int ks = 0; ks < 2; ks++) {
            uint32_t a[4][4];
            #pragma unroll
            for (int mt = 0; mt < 4; mt++)
                ldsm4(a[mt][0], a[mt][1], a[mt][2], a[mt][3],
                      aBase + (mt * 16 + a_row) * 80
                            + (a_colh + ks * 16) * 2);
            #pragma unroll
            for (int p = 0; p < 2; p++) {
                uint32_t kb[4];
                ldsm4t(kb[0], kb[1], kb[2], kb[3],
                       bBase + (ks * 16 + b_rowk) * 272
                             + (warpN + p * 16 + b_colh) * 2);
                #pragma unroll
                for (int mt = 0; mt < 4; mt++) {
                    mma16(acc[mt][2 * p],     a[mt], kb);
                    mma16(acc[mt][2 * p + 1], a[mt], kb + 2);
                }
            }
        }
    }

    #pragma unroll
    for (int mt = 0; mt < 4; mt++)
        #pragma unroll
        for (int nt = 0; nt < 4; nt++) {
            int row = row0 + mt * 16 + lq;
            int col = col0 + warpN + nt * 8 + lr * 2;
            if (RES) {
                float* C = (float*)Cv;
                float2 r0 = *(const float2*)&res[(size_t)row * Dq + col];
                float2 r1 = *(const float2*)&res[(size_t)(row + 8) * Dq + col];
                float2 v0 = { acc[mt][nt][0] + r0.x, acc[mt][nt][1] + r0.y };
                float2 v1 = { acc[mt][nt][2] + r1.x, acc[mt][nt][3] + r1.y };
                *(float2*)&C[(size_t)row * Dq + col] = v0;
                *(float2*)&C[(size_t)(row + 8) * Dq + col] = v1;
            } else {
                __half* C = (__half*)Cv;
                *(__half2*)&C[(size_t)row * Dq + col] =
                    pack2(acc[mt][nt][0], acc[mt][nt][1]);
                *(__half2*)&C[(size_t)(row + 8) * Dq + col] =
                    pack2(acc[mt][nt][2], acc[mt][nt][3]);
            }
        }
}

// ---------------------------------------------------------------------------
// Kernel 3: flash attention fp16 — 128-query CTAs, 256 threads, 2 CTAs/SM,
// 3-stage cp.async K/V, register P-fragment reuse. (R16 unchanged.)
// ---------------------------------------------------------------------------
#define FQ_OFF 0
#define FK_OFF 18432
#define FV_OFF (18432 + 3 * 9216)           // 46080
#define FLASH_SMEM_BYTES 73728
#define NFT (Sq / 64)

__global__ __launch_bounds__(256, 2) void flash_hc(const float* __restrict__ rel_emb)
{
    extern __shared__ char smc[];
    __shared__ float bias_tab[32];

    const int tid = threadIdx.x;
    const int wid = tid >> 5, lane = tid & 31;
    const int lq = lane >> 2, lr = lane & 3;
    const int warpRow = wid * 16;

    const int q0 = blockIdx.x << 7;
    const int bh = blockIdx.y;
    const int b = bh >> 4, h = bh & 15;
    const size_t base = ((size_t)b * Sq) * Dq + (size_t)h * HDq;

    const uint32_t smb = (uint32_t)__cvta_generic_to_shared(smc);

    const int a_row  = (lane & 7) + ((lane >> 3) & 1) * 8;
    const int a_colh = (lane >> 4) * 8;
    const int kb_row = ((lane >> 4) & 1) * 8 + (lane & 7);
    const int kb_colh = ((lane >> 3) & 1) * 8;
    const int vb_row = ((lane >> 3) & 1) * 8 + (lane & 7);
    const int vb_colh = ((lane >> 4) & 1) * 8;

    const uint32_t qa0 = smb + FQ_OFF + (warpRow + a_row) * 144 + a_colh * 2;

    if (tid < 32) bias_tab[tid] = rel_emb[tid * Hq + h];

    auto copyKV = [&](int t, int st) {
        int k0 = t * 64;
        #pragma unroll
        for (int u = 0; u < 2; u++) {
            int lin = tid + u * 256;
            int r = lin >> 3, c8 = (lin & 7) * 8;
            cp16(smb + FK_OFF + st * 9216 + r * 144 + c8 * 2,
                 &g_k[base + (size_t)(k0 + r) * Dq + c8]);
            cp16(smb + FV_OFF + st * 9216 + r * 144 + c8 * 2,
                 &g_v[base + (size_t)(k0 + r) * Dq + c8]);
        }
        cp_commit();
    };

    copyKV(0, 0);
    copyKV(1, 1);

    #pragma unroll
    for (int u = 0; u < 4; u++) {
        int lin = tid + u * 256;
        int r = lin >> 3, c8 = (lin & 7) * 8;
        *(uint4*)(smc + FQ_OFF + r * 144 + c8 * 2) =
            *(const uint4*)&g_q[base + (size_t)(q0 + r) * Dq + c8];
    }
    __syncthreads();

    uint32_t aq[4][4];
    #pragma unroll
    for (int ks = 0; ks < 4; ks++)
        ldsm4(aq[ks][0], aq[ks][1], aq[ks][2], aq[ks][3], qa0 + ks * 32);

    const float NEG_INF = __int_as_float(0xff800000u);
    float mA = NEG_INF, mB = NEG_INF, lA = 0.f, lB = 0.f;
    float o[8][4] = {};
    const int rowA = q0 + warpRow + lq;
    const float b31 = bias_tab[31];
    const float b0  = bias_tab[0];

    #pragma unroll 1
    for (int t = 0; t < NFT; t++) {
        const int st = t % 3;
        const int k0 = t * 64;
        if (t + 1 < NFT) cp_wait1(); else cp_wait0();
        __syncthreads();
        if (t + 2 < NFT) copyKV(t + 2, (t + 2) % 3);

        const uint32_t ka0 = smb + FK_OFF + st * 9216 + kb_row * 144 + kb_colh * 2;
        const uint32_t va0 = smb + FV_OFF + st * 9216 + vb_row * 144 + vb_colh * 2;

        float s[8][4] = {};
        #pragma unroll
        for (int p = 0; p < 4; p++) {
            #pragma unroll
            for (int ks = 0; ks < 4; ks++) {
                uint32_t kb[4];
                ldsm4(kb[0], kb[1], kb[2], kb[3],
                      ka0 + p * (16 * 144) + ks * 32);
                mma16(s[2 * p],     aq[ks], kb);
                mma16(s[2 * p + 1], aq[ks], kb + 2);
            }
        }

        if (rowA - (k0 + 63) >= 128) {
            #pragma unroll
            for (int nt = 0; nt < 8; nt++) {
                s[nt][0] += b31; s[nt][1] += b31;
                s[nt][2] += b31; s[nt][3] += b31;
            }
        } else if (k0 > rowA + 8) {
            #pragma unroll
            for (int nt = 0; nt < 8; nt++) {
                s[nt][0] += b0; s[nt][1] += b0;
                s[nt][2] += b0; s[nt][3] += b0;
            }
        } else {
            #pragma unroll
            for (int nt = 0; nt < 8; nt++) {
                int kc = k0 + nt * 8 + lr * 2;
                s[nt][0] += bias_tab[rp_bucket(rowA - kc)];
                s[nt][1] += bias_tab[rp_bucket(rowA - kc - 1)];
                s[nt][2] += bias_tab[rp_bucket(rowA + 8 - kc)];
                s[nt][3] += bias_tab[rp_bucket(rowA + 8 - kc - 1)];
            }
        }

        float mxA = NEG_INF, mxB = NEG_INF;
        #pragma unroll
        for (int nt = 0; nt < 8; nt++) {
            mxA = fmaxf(mxA, fmaxf(s[nt][0], s[nt][1]));
            mxB = fmaxf(mxB, fmaxf(s[nt][2], s[nt][3]));
        }
        mxA = fmaxf(mxA, __shfl_xor_sync(0xffffffffu, mxA, 1));
        mxA = fmaxf(mxA, __shfl_xor_sync(0xffffffffu, mxA, 2));
        mxB = fmaxf(mxB, __shfl_xor_sync(0xffffffffu, mxB, 1));
        mxB = fmaxf(mxB, __shfl_xor_sync(0xffffffffu, mxB, 2));
        float nmA = fmaxf(mA, mxA), nmB = fmaxf(mB, mxB);
        float alA = __expf(mA - nmA), alB = __expf(mB - nmB);
        float sumA = 0.f, sumB = 0.f;
        #pragma unroll
        for (int nt = 0; nt < 8; nt++) {
            s[nt][0] = __expf(s[nt][0] - nmA); sumA += s[nt][0];
            s[nt][1] = __expf(s[nt][1] - nmA); sumA += s[nt][1];
            s[nt][2] = __expf(s[nt][2] - nmB); sumB += s[nt][2];
            s[nt][3] = __expf(s[nt][3] - nmB); sumB += s[nt][3];
        }
        sumA += __shfl_xor_sync(0xffffffffu, sumA, 1);
        sumA += __shfl_xor_sync(0xffffffffu, sumA, 2);
        sumB += __shfl_xor_sync(0xffffffffu, sumB, 1);
        sumB += __shfl_xor_sync(0xffffffffu, sumB, 2);
        lA = lA * alA + sumA; mA = nmA;
        lB = lB * alB + sumB; mB = nmB;
        #pragma unroll
        for (int nt = 0; nt < 8; nt++) {
            o[nt][0] *= alA; o[nt][1] *= alA;
            o[nt][2] *= alB; o[nt][3] *= alB;
        }

        #pragma unroll
        for (int j = 0; j < 4; j++) {
            uint32_t ap[4];
            ap[0] = packu(s[2 * j][0],     s[2 * j][1]);
            ap[1] = packu(s[2 * j][2],     s[2 * j][3]);
            ap[2] = packu(s[2 * j + 1][0], s[2 * j + 1][1]);
            ap[3] = packu(s[2 * j + 1][2], s[2 * j + 1][3]);
            #pragma unroll
            for (int p = 0; p < 4; p++) {
                uint32_t vb[4];
                ldsm4t(vb[0], vb[1], vb[2], vb[3],
                       va0 + j * (16 * 144) + p * 32);
                mma16(o[2 * p],     ap, vb);
                mma16(o[2 * p + 1], ap, vb + 2);
            }
        }
    }

    float invA = 1.0f / lA, invB = 1.0f / lB;
    #pragma unroll
    for (int nt = 0; nt < 8; nt++) {
        int col = nt * 8 + lr * 2;
        *(__half2*)&g_ctx[base + (size_t)rowA * Dq + col] =
            pack2(o[nt][0] * invA, o[nt][1] * invA);
        *(__half2*)&g_ctx[base + (size_t)(rowA + 8) * Dq + col] =
            pack2(o[nt][2] * invB, o[nt][3] * invB);
    }
}

// ---------------------------------------------------------------------------
// Launch
// ---------------------------------------------------------------------------
extern "C" void kernel_launch(void* const* d_in, const int* in_sizes, int n_in,
                              void* d_out, int out_size)
{
    const float* input = (const float*)d_in[0];
    const float* wq    = (const float*)d_in[2];
    const float* wk    = (const float*)d_in[3];
    const float* wv    = (const float*)d_in[4];
    const float* wo    = (const float*)d_in[5];
    const float* rel   = (const float*)d_in[6];
    const float* lnw   = (const float*)d_in[7];
    float* out         = (float*)d_out;

    cudaFuncSetAttribute(flash_hc,
                         cudaFuncAttributeMaxDynamicSharedMemorySize, FLASH_SMEM_BYTES);
    cudaFuncSetAttribute(gemm_hc<false>,
                         cudaFuncAttributeMaxDynamicSharedMemorySize, GEMM_SMEM_BYTES);
    cudaFuncSetAttribute(gemm_hc<true>,
                         cudaFuncAttributeMaxDynamicSharedMemorySize, GEMM_SMEM_BYTES);

    __half *g_xn_p, *g_q_p, *g_k_p, *g_v_p, *g_ctx_p, *g_wt_p;
    cudaGetSymbolAddress((void**)&g_xn_p, g_xn);
    cudaGetSymbolAddress((void**)&g_q_p,  g_q);
    cudaGetSymbolAddress((void**)&g_k_p,  g_k);
    cudaGetSymbolAddress((void**)&g_v_p,  g_v);
    cudaGetSymbolAddress((void**)&g_ctx_p, g_ctx);
    cudaGetSymbolAddress((void**)&g_wt_p, g_wt);

    dim3 gw(Dq * Dq / 1024, 4);
    cvtw_kernel<<<gw, 256>>>(wq, wk, wv, wo);

    norm_kernel<<<Mq, 256>>>(input, lnw, g_xn_p);

    const __half* wq_t = g_wt_p;
    const __half* wk_t = g_wt_p + (size_t)Dq * Dq;
    const __half* wv_t = g_wt_p + 2 * (size_t)Dq * Dq;
    const __half* wo_t = g_wt_p + 3 * (size_t)Dq * Dq;

    dim3 gg(Dq / 128, Mq / 64);
    gemm_hc<false><<<gg, 128, GEMM_SMEM_BYTES>>>(g_xn_p, wq_t, g_q_p, nullptr);
    gemm_hc<false><<<gg, 128, GEMM_SMEM_BYTES>>>(g_xn_p, wk_t, g_k_p, nullptr);
    gemm_hc<false><<<gg, 128, GEMM_SMEM_BYTES>>>(g_xn_p, wv_t, g_v_p, nullptr);

    dim3 gf(Sq / 128, Bq * Hq);
    flash_hc<<<gf, 256, FLASH_SMEM_BYTES>>>(rel);

    gemm_hc<true><<<gg, 128, GEMM_SMEM_BYTES>>>(g_ctx_p, wo_t, out, input);
}